// round 9
// baseline (speedup 1.0000x reference)
#include <cuda_runtime.h>
#include <cuda_bf16.h>
#include <cstdint>

#define NN 8192
#define FIN 1433
#define FINB 1472      // FIN padded to multiple of 64
#define NDEC 1536      // decoder N padded to multiple of 64
#define MAXE (1 << 20)

typedef unsigned long long u64t;
typedef __nv_bfloat16 bf16;

// ---------------- scratch (device globals) ----------------
__device__ bf16 g_w1thi[256 * FINB];
__device__ bf16 g_w1tlo[256 * FINB];
__device__ bf16 g_w2thi[128 * 256];
__device__ bf16 g_w2tlo[128 * 256];
__device__ bf16 g_w3thi[2 * NDEC * 64];
__device__ bf16 g_w3tlo[2 * NDEC * 64];
__device__ float g_h1p[NN * 256];
__device__ bf16 g_agg1hi[NN * 256];
__device__ bf16 g_agg1lo[NN * 256];
__device__ float g_h2p[NN * 128];
__device__ float g_h2[NN * 64];
__device__ bf16 g_h2hi[NN * 64];
__device__ bf16 g_h2lo[NN * 64];
__device__ bf16 g_agg3hi[2 * NN * 64];
__device__ bf16 g_agg3lo[2 * NN * 64];
__device__ float g_el[3 * NN * 2];
__device__ float g_er[3 * NN * 2];
__device__ float g_uv[2 * 64 * 2];     // layer-3 u/v: uv[h*64+k], uv[128+h*64+k]
__device__ float g_u1[4 * FINB];       // layer-1 u/v from feat: [uh0,uh1,vh0,vh1] x FINB
__device__ float g_u2[4 * 256];        // layer-2 u/v over agg1 dims
__device__ int g_deg[NN];
__device__ int g_cursor[NN];
__device__ int g_rowptr[NN + 1];
__device__ int g_csrsrc[MAXE];

__device__ __forceinline__ float lrelu(float x, float a) { return x > 0.f ? x : a * x; }

__device__ __forceinline__ uint32_t smem_u32(const void* p) {
    uint32_t a;
    asm("{ .reg .u64 t; cvta.to.shared.u64 t, %1; cvt.u32.u64 %0, t; }" : "=r"(a) : "l"(p));
    return a;
}
__device__ __forceinline__ void ldm_x4(uint32_t* r, uint32_t addr) {
    asm volatile("ldmatrix.sync.aligned.m8n8.x4.shared.b16 {%0,%1,%2,%3}, [%4];"
                 : "=r"(r[0]), "=r"(r[1]), "=r"(r[2]), "=r"(r[3]) : "r"(addr));
}
__device__ __forceinline__ void mma_bf16(float* c, const uint32_t* a, uint32_t b0, uint32_t b1) {
    asm volatile(
        "mma.sync.aligned.m16n8k16.row.col.f32.bf16.bf16.f32 "
        "{%0,%1,%2,%3}, {%4,%5,%6,%7}, {%8,%9}, {%0,%1,%2,%3};"
        : "+f"(c[0]), "+f"(c[1]), "+f"(c[2]), "+f"(c[3])
        : "r"(a[0]), "r"(a[1]), "r"(a[2]), "r"(a[3]), "r"(b0), "r"(b1));
}
__device__ __forceinline__ void split_bf16(float v, bf16* hi, bf16* lo) {
    bf16 h = __float2bfloat16(v);
    *hi = h;
    *lo = __float2bfloat16(v - __bfloat162float(h));
}
__device__ __forceinline__ void cp16(uint32_t dst, const void* src) {
    asm volatile("cp.async.cg.shared.global [%0], [%1], 16;" :: "r"(dst), "l"(src));
}

#define APITCH 72    // bf16 per smem row (144B) — conflict-free ldmatrix
#define TILEB 18432  // one 128xAPITCH bf16 tile in bytes

// ================= layer-1 GEMM: A = fp32 feat (in-kernel split), B = packed bf16 =================
// C[8192,256] grid (2,64); K loop over FINB in 64-chunks with FIN guard.
#define HG1_SMEM (8 * TILEB)

__global__ void __launch_bounds__(256)
hmma_gemm1(const float* __restrict__ A, const bf16* __restrict__ Bhi,
           const bf16* __restrict__ Blo, float* __restrict__ C) {
    extern __shared__ char smem[];
    const uint32_t sb = smem_u32(smem);
    const int tid = threadIdx.x, wid = tid >> 5, lane = tid & 31;
    const int rowBase = blockIdx.y * 128, colBase = blockIdx.x * 128;
    const int wm = (wid & 3) * 32, wn = (wid >> 2) * 64;
    const int lrow = lane & 15, lch = lane >> 4;
    const int nk = FINB / 64;  // 23

    const int arow = rowBase + (tid >> 1), ahalf = tid & 1;
    const float* Ap = A + (size_t)arow * FIN + ahalf * 32;
    const uint32_t arowoff = (uint32_t)((tid >> 1) * APITCH + ahalf * 32) * 2;

    float acc[2][8][4];
#pragma unroll
    for (int i = 0; i < 2; i++)
#pragma unroll
        for (int j = 0; j < 8; j++)
#pragma unroll
            for (int q = 0; q < 4; q++) acc[i][j][q] = 0.f;

    float tmp[32];
    auto loadA = [&](int kc) {
#pragma unroll 8
        for (int j = 0; j < 32; j++) {
            int gk = kc + ahalf * 32 + j;
            tmp[j] = (gk < FIN) ? __ldg(Ap + kc + j) : 0.f;
        }
    };
    auto writeA = [&](int buf) {
        char* base = smem + buf * (4 * TILEB);
#pragma unroll
        for (int j = 0; j < 32; j += 2) {
            bf16 h0 = __float2bfloat16(tmp[j]);
            bf16 l0 = __float2bfloat16(tmp[j] - __bfloat162float(h0));
            bf16 h1 = __float2bfloat16(tmp[j + 1]);
            bf16 l1 = __float2bfloat16(tmp[j + 1] - __bfloat162float(h1));
            uint32_t hp = (uint32_t)__bfloat16_as_ushort(h0) |
                          ((uint32_t)__bfloat16_as_ushort(h1) << 16);
            uint32_t lp = (uint32_t)__bfloat16_as_ushort(l0) |
                          ((uint32_t)__bfloat16_as_ushort(l1) << 16);
            *(uint32_t*)(base + arowoff + j * 2) = hp;
            *(uint32_t*)(base + TILEB + arowoff + j * 2) = lp;
        }
    };
    auto stageB = [&](int buf, int kc) {
        uint32_t base = sb + buf * (4 * TILEB);
        for (int idx = tid; idx < 1024; idx += 256) {
            int row = idx >> 3, ch = idx & 7;
            uint32_t off = (uint32_t)(row * APITCH + ch * 8) * 2;
            cp16(base + 2 * TILEB + off, Bhi + (size_t)(colBase + row) * FINB + kc + ch * 8);
            cp16(base + 3 * TILEB + off, Blo + (size_t)(colBase + row) * FINB + kc + ch * 8);
        }
        asm volatile("cp.async.commit_group;" ::: "memory");
    };

    loadA(0);
    writeA(0);
    stageB(0, 0);
    for (int t = 0; t < nk; ++t) {
        const bool more = (t + 1 < nk);
        if (more) loadA((t + 1) * 64);
        asm volatile("cp.async.wait_group 0;" ::: "memory");
        __syncthreads();
        if (more) stageB((t + 1) & 1, (t + 1) * 64);
        const uint32_t base = sb + (t & 1) * (4 * TILEB);
        const uint32_t bAhi = base, bAlo = base + TILEB;
        const uint32_t bBhi = base + 2 * TILEB, bBlo = base + 3 * TILEB;
#pragma unroll
        for (int ks = 0; ks < 4; ks++) {
            uint32_t afh[2][4], afl[2][4];
#pragma unroll
            for (int i = 0; i < 2; i++) {
                uint32_t ao = ((wm + i * 16 + lrow) * APITCH) * 2 + (ks * 2 + lch) * 16;
                ldm_x4(afh[i], bAhi + ao);
                ldm_x4(afl[i], bAlo + ao);
            }
            uint32_t bfh[8][2], bfl[8][2];
#pragma unroll
            for (int jj = 0; jj < 4; jj++) {
                uint32_t bo = ((wn + jj * 16 + lrow) * APITCH) * 2 + (ks * 2 + lch) * 16;
                uint32_t r[4];
                ldm_x4(r, bBhi + bo);
                bfh[2 * jj][0] = r[0]; bfh[2 * jj][1] = r[2];
                bfh[2 * jj + 1][0] = r[1]; bfh[2 * jj + 1][1] = r[3];
                ldm_x4(r, bBlo + bo);
                bfl[2 * jj][0] = r[0]; bfl[2 * jj][1] = r[2];
                bfl[2 * jj + 1][0] = r[1]; bfl[2 * jj + 1][1] = r[3];
            }
#pragma unroll
            for (int i = 0; i < 2; i++)
#pragma unroll
                for (int j = 0; j < 8; j++) {
                    mma_bf16(acc[i][j], afh[i], bfh[j][0], bfh[j][1]);
                    mma_bf16(acc[i][j], afh[i], bfl[j][0], bfl[j][1]);
                    mma_bf16(acc[i][j], afl[i], bfh[j][0], bfh[j][1]);
                }
        }
        if (more) writeA((t + 1) & 1);
    }

    const int rr = lane >> 2, cc = (lane & 3) * 2;
#pragma unroll
    for (int i = 0; i < 2; i++) {
        int gr = rowBase + wm + i * 16 + rr;
        float* out0 = C + (size_t)gr * 256 + colBase + wn + cc;
        float* out1 = out0 + 8 * 256;
#pragma unroll
        for (int j = 0; j < 8; j++) {
            *(float2*)(out0 + j * 8) = make_float2(acc[i][j][0], acc[i][j][1]);
            *(float2*)(out1 + j * 8) = make_float2(acc[i][j][2], acc[i][j][3]);
        }
    }
}

// ================= generic bf16-split HMMA GEMM (layer 2), cp.async double-buffered =====
#define HG_SMEM (8 * TILEB)

__global__ void __launch_bounds__(256)
hmma_gemm(const bf16* __restrict__ Ahi, const bf16* __restrict__ Alo,
          const bf16* __restrict__ Bhi, const bf16* __restrict__ Blo,
          float* __restrict__ C, int K, int lda, int ldb, int ldc) {
    extern __shared__ char smem[];
    const uint32_t sb = smem_u32(smem);
    const int tid = threadIdx.x, wid = tid >> 5, lane = tid & 31;
    const int rowBase = blockIdx.y * 128, colBase = blockIdx.x * 128;
    const int wm = (wid & 3) * 32, wn = (wid >> 2) * 64;
    const int lrow = lane & 15, lch = lane >> 4;
    const int nk = K >> 6;

    float acc[2][8][4];
#pragma unroll
    for (int i = 0; i < 2; i++)
#pragma unroll
        for (int j = 0; j < 8; j++)
#pragma unroll
            for (int q = 0; q < 4; q++) acc[i][j][q] = 0.f;

    auto stage = [&](int buf, int kc) {
        uint32_t base = sb + buf * (4 * TILEB);
        for (int idx = tid; idx < 1024; idx += 256) {
            int row = idx >> 3, ch = idx & 7;
            uint32_t off = (uint32_t)(row * APITCH + ch * 8) * 2;
            cp16(base + off, Ahi + (size_t)(rowBase + row) * lda + kc + ch * 8);
            cp16(base + TILEB + off, Alo + (size_t)(rowBase + row) * lda + kc + ch * 8);
            cp16(base + 2 * TILEB + off, Bhi + (size_t)(colBase + row) * ldb + kc + ch * 8);
            cp16(base + 3 * TILEB + off, Blo + (size_t)(colBase + row) * ldb + kc + ch * 8);
        }
        asm volatile("cp.async.commit_group;" ::: "memory");
    };

    stage(0, 0);
    for (int t = 0; t < nk; ++t) {
        asm volatile("cp.async.wait_group 0;" ::: "memory");
        __syncthreads();
        if (t + 1 < nk) stage((t + 1) & 1, (t + 1) * 64);
        const uint32_t base = sb + (t & 1) * (4 * TILEB);
        const uint32_t bAhi = base, bAlo = base + TILEB;
        const uint32_t bBhi = base + 2 * TILEB, bBlo = base + 3 * TILEB;
#pragma unroll
        for (int ks = 0; ks < 4; ks++) {
            uint32_t afh[2][4], afl[2][4];
#pragma unroll
            for (int i = 0; i < 2; i++) {
                uint32_t ao = ((wm + i * 16 + lrow) * APITCH) * 2 + (ks * 2 + lch) * 16;
                ldm_x4(afh[i], bAhi + ao);
                ldm_x4(afl[i], bAlo + ao);
            }
            uint32_t bfh[8][2], bfl[8][2];
#pragma unroll
            for (int jj = 0; jj < 4; jj++) {
                uint32_t bo = ((wn + jj * 16 + lrow) * APITCH) * 2 + (ks * 2 + lch) * 16;
                uint32_t r[4];
                ldm_x4(r, bBhi + bo);
                bfh[2 * jj][0] = r[0]; bfh[2 * jj][1] = r[2];
                bfh[2 * jj + 1][0] = r[1]; bfh[2 * jj + 1][1] = r[3];
                ldm_x4(r, bBlo + bo);
                bfl[2 * jj][0] = r[0]; bfl[2 * jj][1] = r[2];
                bfl[2 * jj + 1][0] = r[1]; bfl[2 * jj + 1][1] = r[3];
            }
#pragma unroll
            for (int i = 0; i < 2; i++)
#pragma unroll
                for (int j = 0; j < 8; j++) {
                    mma_bf16(acc[i][j], afh[i], bfh[j][0], bfh[j][1]);
                    mma_bf16(acc[i][j], afh[i], bfl[j][0], bfl[j][1]);
                    mma_bf16(acc[i][j], afl[i], bfh[j][0], bfh[j][1]);
                }
        }
        __syncthreads();
    }

    const int rr = lane >> 2, cc = (lane & 3) * 2;
#pragma unroll
    for (int i = 0; i < 2; i++) {
        int gr = rowBase + wm + i * 16 + rr;
        float* out0 = C + (size_t)gr * ldc + colBase + wn + cc;
        float* out1 = out0 + 8 * ldc;
#pragma unroll
        for (int j = 0; j < 8; j++) {
            *(float2*)(out0 + j * 8) = make_float2(acc[i][j][0], acc[i][j][1]);
            *(float2*)(out1 + j * 8) = make_float2(acc[i][j][2], acc[i][j][3]);
        }
    }
}

// ================= a_hat HMMA (128x128, K=64) =================
#define AHAT_SMEM (4 * TILEB)

__global__ void __launch_bounds__(256)
ahat_hmma(const bf16* __restrict__ hi, const bf16* __restrict__ lo, float* __restrict__ C) {
    extern __shared__ char smem[];
    bf16* sAhi = (bf16*)(smem);
    bf16* sAlo = (bf16*)(smem + TILEB);
    bf16* sBhi = (bf16*)(smem + 2 * TILEB);
    bf16* sBlo = (bf16*)(smem + 3 * TILEB);
    const int tid = threadIdx.x, wid = tid >> 5, lane = tid & 31;
    const int rowBase = blockIdx.y * 128, colBase = blockIdx.x * 128;

    for (int idx = tid; idx < 128 * 8; idx += 256) {
        int row = idx >> 3, ch = idx & 7;
        int off = row * APITCH + ch * 8;
        *(uint4*)(sAhi + off) = *((const uint4*)(hi + (size_t)(rowBase + row) * 64) + ch);
        *(uint4*)(sAlo + off) = *((const uint4*)(lo + (size_t)(rowBase + row) * 64) + ch);
        *(uint4*)(sBhi + off) = *((const uint4*)(hi + (size_t)(colBase + row) * 64) + ch);
        *(uint4*)(sBlo + off) = *((const uint4*)(lo + (size_t)(colBase + row) * 64) + ch);
    }
    __syncthreads();

    const int wm = (wid & 3) * 32, wn = (wid >> 2) * 64;
    float acc[2][8][4];
#pragma unroll
    for (int i = 0; i < 2; i++)
#pragma unroll
        for (int j = 0; j < 8; j++)
#pragma unroll
            for (int q = 0; q < 4; q++) acc[i][j][q] = 0.f;

    const int lrow = lane & 15, lch = lane >> 4;
    const uint32_t sbAhi = smem_u32(sAhi), sbAlo = smem_u32(sAlo);
    const uint32_t sbBhi = smem_u32(sBhi), sbBlo = smem_u32(sBlo);

#pragma unroll
    for (int pass = 0; pass < 3; pass++) {
        const uint32_t aBase = (pass == 2) ? sbAlo : sbAhi;
        const uint32_t bBase = (pass == 1) ? sbBlo : sbBhi;
#pragma unroll
        for (int ks = 0; ks < 4; ks++) {
            uint32_t af[2][4];
#pragma unroll
            for (int i = 0; i < 2; i++)
                ldm_x4(af[i], aBase + ((wm + i * 16 + lrow) * APITCH) * 2 + (ks * 2 + lch) * 16);
            uint32_t bf[8][2];
#pragma unroll
            for (int jj = 0; jj < 4; jj++) {
                uint32_t r[4];
                ldm_x4(r, bBase + ((wn + jj * 16 + lrow) * APITCH) * 2 + (ks * 2 + lch) * 16);
                bf[2 * jj][0] = r[0]; bf[2 * jj][1] = r[2];
                bf[2 * jj + 1][0] = r[1]; bf[2 * jj + 1][1] = r[3];
            }
#pragma unroll
            for (int i = 0; i < 2; i++)
#pragma unroll
                for (int j = 0; j < 8; j++)
                    mma_bf16(acc[i][j], af[i], bf[j][0], bf[j][1]);
        }
    }

    const int rr = lane >> 2, cc = (lane & 3) * 2;
#pragma unroll
    for (int i = 0; i < 2; i++) {
        int gr = rowBase + wm + i * 16 + rr;
        float* out0 = C + (size_t)gr * NN + colBase + wn + cc;
        float* out1 = out0 + 8 * NN;
#pragma unroll
        for (int j = 0; j < 8; j++) {
            *(float2*)(out0 + j * 8) = make_float2(acc[i][j][0], acc[i][j][1]);
            *(float2*)(out1 + j * 8) = make_float2(acc[i][j][2], acc[i][j][3]);
        }
    }
}

// ================= fused decoder HMMA (2 heads + bias + lrelu + mean) =================
#define DEC_SMEM (2 * TILEB + TILEB)

__global__ void __launch_bounds__(256)
dec_hmma(const bf16* __restrict__ Ahi, const bf16* __restrict__ Alo,
         const bf16* __restrict__ Bhi, const bf16* __restrict__ Blo,
         const float* __restrict__ b3, float* __restrict__ xhat) {
    extern __shared__ char smem[];
    bf16* sAhi = (bf16*)smem;
    bf16* sAlo = (bf16*)(smem + TILEB);
    bf16* sBhi = (bf16*)(smem + 2 * TILEB);
    bf16* sBlo = (bf16*)(smem + 2 * TILEB + TILEB / 2);
    const int tid = threadIdx.x, wid = tid >> 5, lane = tid & 31;
    const int rowBase = blockIdx.y * 128, colBase = blockIdx.x * 64;
    const int wm = (wid & 3) * 32, wn = (wid >> 2) * 32;
    const int lrow = lane & 15, lch = lane >> 4;

    float acc[2][2][4][4];
#pragma unroll
    for (int h = 0; h < 2; h++)
#pragma unroll
        for (int i = 0; i < 2; i++)
#pragma unroll
            for (int j = 0; j < 4; j++)
#pragma unroll
                for (int q = 0; q < 4; q++) acc[h][i][j][q] = 0.f;

    const uint32_t sbAhi = smem_u32(sAhi), sbAlo = smem_u32(sAlo);
    const uint32_t sbBhi = smem_u32(sBhi), sbBlo = smem_u32(sBlo);

#pragma unroll
    for (int h = 0; h < 2; h++) {
        const bf16* ahp = Ahi + (size_t)h * NN * 64;
        const bf16* alp = Alo + (size_t)h * NN * 64;
        const bf16* bhp = Bhi + (size_t)h * NDEC * 64;
        const bf16* blp = Blo + (size_t)h * NDEC * 64;
        __syncthreads();
        for (int idx = tid; idx < 1024; idx += 256) {
            int row = idx >> 3, ch = idx & 7;
            int off = row * APITCH + ch * 8;
            *(uint4*)(sAhi + off) = *(const uint4*)(ahp + (size_t)(rowBase + row) * 64 + ch * 8);
            *(uint4*)(sAlo + off) = *(const uint4*)(alp + (size_t)(rowBase + row) * 64 + ch * 8);
        }
        for (int idx = tid; idx < 512; idx += 256) {
            int row = idx >> 3, ch = idx & 7;
            int off = row * APITCH + ch * 8;
            *(uint4*)(sBhi + off) = *(const uint4*)(bhp + (size_t)(colBase + row) * 64 + ch * 8);
            *(uint4*)(sBlo + off) = *(const uint4*)(blp + (size_t)(colBase + row) * 64 + ch * 8);
        }
        __syncthreads();
#pragma unroll
        for (int ks = 0; ks < 4; ks++) {
            uint32_t afh[2][4], afl[2][4];
#pragma unroll
            for (int i = 0; i < 2; i++) {
                uint32_t ao = ((wm + i * 16 + lrow) * APITCH) * 2 + (ks * 2 + lch) * 16;
                ldm_x4(afh[i], sbAhi + ao);
                ldm_x4(afl[i], sbAlo + ao);
            }
            uint32_t bfh[4][2], bfl[4][2];
#pragma unroll
            for (int jj = 0; jj < 2; jj++) {
                uint32_t bo = ((wn + jj * 16 + lrow) * APITCH) * 2 + (ks * 2 + lch) * 16;
                uint32_t r[4];
                ldm_x4(r, sbBhi + bo);
                bfh[2 * jj][0] = r[0]; bfh[2 * jj][1] = r[2];
                bfh[2 * jj + 1][0] = r[1]; bfh[2 * jj + 1][1] = r[3];
                ldm_x4(r, sbBlo + bo);
                bfl[2 * jj][0] = r[0]; bfl[2 * jj][1] = r[2];
                bfl[2 * jj + 1][0] = r[1]; bfl[2 * jj + 1][1] = r[3];
            }
#pragma unroll
            for (int i = 0; i < 2; i++)
#pragma unroll
                for (int j = 0; j < 4; j++) {
                    mma_bf16(acc[h][i][j], afh[i], bfh[j][0], bfh[j][1]);
                    mma_bf16(acc[h][i][j], afh[i], bfl[j][0], bfl[j][1]);
                    mma_bf16(acc[h][i][j], afl[i], bfh[j][0], bfh[j][1]);
                }
        }
    }

    const int rr = lane >> 2, cc = (lane & 3) * 2;
#pragma unroll
    for (int i = 0; i < 2; i++) {
#pragma unroll
        for (int j = 0; j < 4; j++) {
#pragma unroll
            for (int half = 0; half < 2; half++) {
                int gr = rowBase + wm + i * 16 + rr + half * 8;
                int gn = colBase + wn + j * 8 + cc;
                if (gn < FIN) {
                    float v0 = acc[0][i][j][half * 2], v1 = acc[1][i][j][half * 2];
                    xhat[(size_t)gr * FIN + gn] =
                        0.5f * (lrelu(v0 + b3[gn], 0.01f) + lrelu(v1 + b3[FIN + gn], 0.01f));
                }
                if (gn + 1 < FIN) {
                    float v0 = acc[0][i][j][half * 2 + 1], v1 = acc[1][i][j][half * 2 + 1];
                    xhat[(size_t)gr * FIN + gn + 1] =
                        0.5f * (lrelu(v0 + b3[gn + 1], 0.01f) + lrelu(v1 + b3[FIN + gn + 1], 0.01f));
                }
            }
        }
    }
}

// ================= CSR build =================
__global__ void k_zerodeg(int* deg) {
    int i = blockIdx.x * blockDim.x + threadIdx.x;
    if (i < NN) deg[i] = 0;
}
__global__ void k_deg(const int* __restrict__ dst, int* deg, int E) {
    int e = blockIdx.x * blockDim.x + threadIdx.x;
    if (e < E) atomicAdd(&deg[dst[e]], 1);
}
__global__ void k_scan(const int* __restrict__ deg, int* rowptr, int* cursor) {
    __shared__ int partx[257];
    int t = threadIdx.x;
    int base = t * 32;
    int loc[32];
    int s = 0;
#pragma unroll
    for (int i = 0; i < 32; i++) { loc[i] = s; s += deg[base + i]; }
    __shared__ int part[256];
    part[t] = s;
    __syncthreads();
    if (t == 0) {
        int acc = 0;
        for (int i = 0; i < 256; i++) { partx[i] = acc; acc += part[i]; }
        partx[256] = acc;
    }
    __syncthreads();
    int off = partx[t];
#pragma unroll
    for (int i = 0; i < 32; i++) {
        int v = off + loc[i];
        rowptr[base + i] = v;
        cursor[base + i] = v;
    }
    if (t == 0) rowptr[NN] = partx[256];
}
__global__ void k_scatter(const int* __restrict__ src, const int* __restrict__ dst,
                          int* cursor, int* csrsrc, int E) {
    int e = blockIdx.x * blockDim.x + threadIdx.x;
    if (e >= E) return;
    int d = dst[e];
    int idx = atomicAdd(&cursor[d], 1);
    csrsrc[idx] = src[e];
}

// ================= pack kernels =================
__global__ void k_pack_w1t(const float* __restrict__ W1, bf16* __restrict__ whi,
                           bf16* __restrict__ wlo) {
    int n = blockIdx.x;  // 256
    for (int k = threadIdx.x; k < FINB; k += blockDim.x) {
        float v = (k < FIN) ? W1[(size_t)k * 256 + n] : 0.f;
        split_bf16(v, &whi[(size_t)n * FINB + k], &wlo[(size_t)n * FINB + k]);
    }
}
__global__ void k_pack_w2t(const float* __restrict__ W2, bf16* __restrict__ whi,
                           bf16* __restrict__ wlo) {
    int n = blockIdx.x;  // 128
    for (int k = threadIdx.x; k < 256; k += blockDim.x) {
        float v = W2[(size_t)k * 128 + n];
        split_bf16(v, &whi[(size_t)n * 256 + k], &wlo[(size_t)n * 256 + k]);
    }
}
__global__ void k_pack_w3t(const float* __restrict__ W3, bf16* __restrict__ whi,
                           bf16* __restrict__ wlo) {
    int f = blockIdx.x;  // NDEC
    int k = threadIdx.x; // 64
#pragma unroll
    for (int h = 0; h < 2; h++) {
        float v = (f < FIN) ? W3[(size_t)k * (2 * FIN) + h * FIN + f] : 0.f;
        split_bf16(v, &whi[((size_t)h * NDEC + f) * 64 + k], &wlo[((size_t)h * NDEC + f) * 64 + k]);
    }
}

// ================= attention projections =================
// layer-1: u1[q][f] with q = {el_h0, el_h1, er_h0, er_h1}, f<FIN
__global__ void k_uv1(const float* __restrict__ W1, const float* __restrict__ al1,
                      const float* __restrict__ ar1, float* __restrict__ u1) {
    int w = (blockIdx.x * blockDim.x + threadIdx.x) >> 5;
    int lane = threadIdx.x & 31;
    if (w >= FIN) return;
    const float* Wr = W1 + (size_t)w * 256;
    float a0 = 0.f, a1 = 0.f, r0 = 0.f, r1 = 0.f;
#pragma unroll
    for (int j = lane; j < 128; j += 32) {
        float w0 = Wr[j], w1 = Wr[128 + j];
        a0 += w0 * al1[j]; a1 += w1 * al1[128 + j];
        r0 += w0 * ar1[j]; r1 += w1 * ar1[128 + j];
    }
#pragma unroll
    for (int o = 16; o; o >>= 1) {
        a0 += __shfl_down_sync(0xffffffffu, a0, o);
        a1 += __shfl_down_sync(0xffffffffu, a1, o);
        r0 += __shfl_down_sync(0xffffffffu, r0, o);
        r1 += __shfl_down_sync(0xffffffffu, r1, o);
    }
    if (lane == 0) {
        u1[w] = a0; u1[FINB + w] = a1; u1[2 * FINB + w] = r0; u1[3 * FINB + w] = r1;
    }
}
// el1/er1 from feat directly
__global__ void k_elr1(const float* __restrict__ feat, const float* __restrict__ u1,
                       float* __restrict__ el, float* __restrict__ er) {
    int w = (blockIdx.x * blockDim.x + threadIdx.x) >> 5;
    int lane = threadIdx.x & 31;
    if (w >= NN) return;
    const float* row = feat + (size_t)w * FIN;
    float a0 = 0.f, a1 = 0.f, r0 = 0.f, r1 = 0.f;
    for (int f = lane; f < FIN; f += 32) {
        float x = row[f];
        a0 += x * u1[f]; a1 += x * u1[FINB + f];
        r0 += x * u1[2 * FINB + f]; r1 += x * u1[3 * FINB + f];
    }
#pragma unroll
    for (int o = 16; o; o >>= 1) {
        a0 += __shfl_down_sync(0xffffffffu, a0, o);
        a1 += __shfl_down_sync(0xffffffffu, a1, o);
        r0 += __shfl_down_sync(0xffffffffu, r0, o);
        r1 += __shfl_down_sync(0xffffffffu, r1, o);
    }
    if (lane == 0) { el[w * 2] = a0; el[w * 2 + 1] = a1; er[w * 2] = r0; er[w * 2 + 1] = r1; }
}
// layer-2: u2[q][t], t<256
__global__ void k_uv2(const float* __restrict__ W2, const float* __restrict__ al2,
                      const float* __restrict__ ar2, float* __restrict__ u2) {
    int w = (blockIdx.x * blockDim.x + threadIdx.x) >> 5;
    int lane = threadIdx.x & 31;
    if (w >= 256) return;
    const float* Wr = W2 + (size_t)w * 128;
    float a0 = 0.f, a1 = 0.f, r0 = 0.f, r1 = 0.f;
#pragma unroll
    for (int j = lane; j < 64; j += 32) {
        float w0 = Wr[j], w1 = Wr[64 + j];
        a0 += w0 * al2[j]; a1 += w1 * al2[64 + j];
        r0 += w0 * ar2[j]; r1 += w1 * ar2[64 + j];
    }
#pragma unroll
    for (int o = 16; o; o >>= 1) {
        a0 += __shfl_down_sync(0xffffffffu, a0, o);
        a1 += __shfl_down_sync(0xffffffffu, a1, o);
        r0 += __shfl_down_sync(0xffffffffu, r0, o);
        r1 += __shfl_down_sync(0xffffffffu, r1, o);
    }
    if (lane == 0) { u2[w] = a0; u2[256 + w] = a1; u2[512 + w] = r0; u2[768 + w] = r1; }
}
// layer-3 (existing): uv[h*64+k], uv[128+h*64+k]
__global__ void k_uv(const float* __restrict__ W3, const float* __restrict__ al3,
                     const float* __restrict__ ar3, float* uv) {
    int w = (blockIdx.x * blockDim.x + threadIdx.x) >> 5;
    int lane = threadIdx.x & 31;
    if (w >= 128) return;
    int h = w >> 6, k = w & 63;
    const float* Wr = W3 + (size_t)k * (2 * FIN) + h * FIN;
    const float* a = al3 + (size_t)h * FIN;
    const float* b = ar3 + (size_t)h * FIN;
    float su = 0.f, sv = 0.f;
    for (int f = lane; f < FIN; f += 32) { float ww = Wr[f]; su += ww * a[f]; sv += ww * b[f]; }
#pragma unroll
    for (int o = 16; o; o >>= 1) {
        su += __shfl_down_sync(0xffffffffu, su, o);
        sv += __shfl_down_sync(0xffffffffu, sv, o);
    }
    if (lane == 0) { uv[h * 64 + k] = su; uv[128 + h * 64 + k] = sv; }
}

// ================= block softmax-sum helper =================
template <int NT>
__device__ __forceinline__ float2 block_inv_sum(const int* csrsrc, int b, int en,
                                                const float* el, float2 r,
                                                float* red, float2* out_sh) {
    int t = threadIdx.x, lane = t & 31, wid = t >> 5;
    float p0 = 0.f, p1 = 0.f;
    for (int i = b + t; i < en; i += NT) {
        int s = csrsrc[i];
        float2 l = *(const float2*)&el[s * 2];
        float e0 = l.x + r.x; e0 = e0 > 0.f ? e0 : 0.2f * e0;
        float e1 = l.y + r.y; e1 = e1 > 0.f ? e1 : 0.2f * e1;
        p0 += __expf(e0); p1 += __expf(e1);
    }
#pragma unroll
    for (int o = 16; o; o >>= 1) {
        p0 += __shfl_down_sync(0xffffffffu, p0, o);
        p1 += __shfl_down_sync(0xffffffffu, p1, o);
    }
    if (lane == 0) { red[wid * 2] = p0; red[wid * 2 + 1] = p1; }
    __syncthreads();
    if (t == 0) {
        float s0 = 0.f, s1 = 0.f;
        for (int w = 0; w < NT / 32; w++) { s0 += red[w * 2]; s1 += red[w * 2 + 1]; }
        *out_sh = make_float2(1.f / s0, 1.f / s1);
    }
    __syncthreads();
    return *out_sh;
}

// ================= CSR gather aggregation =================
// layer1 + fused el2/er2 epilogue
__global__ void __launch_bounds__(256)
k_agg1(const int* __restrict__ rowptr, const int* __restrict__ csrsrc,
       const float* __restrict__ el, const float* __restrict__ er,
       const float* __restrict__ hp, const float* __restrict__ b1,
       const float* __restrict__ u2,
       bf16* __restrict__ ohi, bf16* __restrict__ olo,
       float* __restrict__ el2, float* __restrict__ er2) {
    int d = blockIdx.x;
    int t = threadIdx.x, lane = t & 31, warp = t >> 5;
    __shared__ float2 sal[128];
    __shared__ int ssrc[128];
    __shared__ float red[16];
    __shared__ float2 inv_sh;
    __shared__ float redq[8][4];
    int b = rowptr[d], en = rowptr[d + 1];
    float2 r = *(const float2*)&er[d * 2];
    float2 inv = block_inv_sum<256>(csrsrc, b, en, el, r, red, &inv_sh);
    float acc = 0.f;
    int h = t >> 7;
    for (int c = b; c < en; c += 128) {
        int cnt = min(128, en - c);
        __syncthreads();
        if (t < cnt) {
            int s = csrsrc[c + t];
            float2 l = *(const float2*)&el[s * 2];
            float e0 = l.x + r.x; e0 = e0 > 0.f ? e0 : 0.2f * e0;
            float e1 = l.y + r.y; e1 = e1 > 0.f ? e1 : 0.2f * e1;
            sal[t] = make_float2(__expf(e0) * inv.x, __expf(e1) * inv.y);
            ssrc[t] = s;
        }
        __syncthreads();
#pragma unroll 4
        for (int i = 0; i < cnt; i++) {
            float a = h ? sal[i].y : sal[i].x;
            acc = fmaf(a, hp[(size_t)ssrc[i] * 256 + t], acc);
        }
    }
    float x = lrelu(acc + b1[t], 0.01f);
    split_bf16(x, &ohi[(size_t)d * 256 + t], &olo[(size_t)d * 256 + t]);
    // fused el2/er2: dot of x with u2 columns, block reduce
    float c0 = x * u2[t], c1 = x * u2[256 + t], c2 = x * u2[512 + t], c3 = x * u2[768 + t];
#pragma unroll
    for (int o = 16; o; o >>= 1) {
        c0 += __shfl_down_sync(0xffffffffu, c0, o);
        c1 += __shfl_down_sync(0xffffffffu, c1, o);
        c2 += __shfl_down_sync(0xffffffffu, c2, o);
        c3 += __shfl_down_sync(0xffffffffu, c3, o);
    }
    if (lane == 0) { redq[warp][0] = c0; redq[warp][1] = c1; redq[warp][2] = c2; redq[warp][3] = c3; }
    __syncthreads();
    if (t == 0) {
        float s0 = 0.f, s1 = 0.f, s2 = 0.f, s3 = 0.f;
        for (int w = 0; w < 8; w++) { s0 += redq[w][0]; s1 += redq[w][1]; s2 += redq[w][2]; s3 += redq[w][3]; }
        el2[d * 2] = s0; el2[d * 2 + 1] = s1;
        er2[d * 2] = s2; er2[d * 2 + 1] = s3;
    }
}

// layer2 + fused el3/er3 epilogue
__global__ void __launch_bounds__(128)
k_agg2(const int* __restrict__ rowptr, const int* __restrict__ csrsrc,
       const float* __restrict__ el, const float* __restrict__ er,
       const float* __restrict__ hp, const float* __restrict__ b2,
       const float* __restrict__ uv,
       float* __restrict__ h2, bf16* __restrict__ h2hi, bf16* __restrict__ h2lo,
       float* __restrict__ el3, float* __restrict__ er3) {
    int d = blockIdx.x;
    int t = threadIdx.x, lane = t & 31, warp = t >> 5;
    __shared__ float2 sal[128];
    __shared__ int ssrc[128];
    __shared__ float o[128];
    __shared__ float red[8];
    __shared__ float2 inv_sh;
    __shared__ float redq[4][4];
    int b = rowptr[d], en = rowptr[d + 1];
    float2 r = *(const float2*)&er[d * 2];
    float2 inv = block_inv_sum<128>(csrsrc, b, en, el, r, red, &inv_sh);
    float acc = 0.f;
    int h = t >> 6;
    for (int c = b; c < en; c += 128) {
        int cnt = min(128, en - c);
        __syncthreads();
        if (t < cnt) {
            int s = csrsrc[c + t];
            float2 l = *(const float2*)&el[s * 2];
            float e0 = l.x + r.x; e0 = e0 > 0.f ? e0 : 0.2f * e0;
            float e1 = l.y + r.y; e1 = e1 > 0.f ? e1 : 0.2f * e1;
            sal[t] = make_float2(__expf(e0) * inv.x, __expf(e1) * inv.y);
            ssrc[t] = s;
        }
        __syncthreads();
#pragma unroll 4
        for (int i = 0; i < cnt; i++) {
            float a = h ? sal[i].y : sal[i].x;
            acc = fmaf(a, hp[(size_t)ssrc[i] * 128 + t], acc);
        }
    }
    o[t] = acc;
    __syncthreads();
    float v = 0.f;
    if (t < 64) {
        float x0 = lrelu(o[t] + b2[t], 0.01f);
        float x1 = lrelu(o[64 + t] + b2[64 + t], 0.01f);
        v = 0.5f * (x0 + x1);
        h2[(size_t)d * 64 + t] = v;
        split_bf16(v, &h2hi[(size_t)d * 64 + t], &h2lo[(size_t)d * 64 + t]);
    }
    // fused el3/er3: dot of h2 row with uv columns (threads t<64 contribute)
    float c0 = 0.f, c1 = 0.f, c2 = 0.f, c3 = 0.f;
    if (t < 64) {
        c0 = v * uv[t]; c1 = v * uv[64 + t]; c2 = v * uv[128 + t]; c3 = v * uv[192 + t];
    }
#pragma unroll
    for (int o2 = 16; o2; o2 >>= 1) {
        c0 += __shfl_down_sync(0xffffffffu, c0, o2);
        c1 += __shfl_down_sync(0xffffffffu, c1, o2);
        c2 += __shfl_down_sync(0xffffffffu, c2, o2);
        c3 += __shfl_down_sync(0xffffffffu, c3, o2);
    }
    if (lane == 0) { redq[warp][0] = c0; redq[warp][1] = c1; redq[warp][2] = c2; redq[warp][3] = c3; }
    __syncthreads();
    if (t == 0) {
        float s0 = redq[0][0] + redq[1][0];
        float s1 = redq[0][1] + redq[1][1];
        float s2 = redq[0][2] + redq[1][2];
        float s3 = redq[0][3] + redq[1][3];
        el3[d * 2] = s0; el3[d * 2 + 1] = s1;
        er3[d * 2] = s2; er3[d * 2 + 1] = s3;
    }
}

__global__ void __launch_bounds__(128)
k_agg3(const int* __restrict__ rowptr, const int* __restrict__ csrsrc,
       const float* __restrict__ el, const float* __restrict__ er,
       const float* __restrict__ h2, bf16* __restrict__ ahi, bf16* __restrict__ alo) {
    int d = blockIdx.x;
    int t = threadIdx.x;
    __shared__ float2 sal[128];
    __shared__ int ssrc[128];
    __shared__ float red[8];
    __shared__ float2 inv_sh;
    int b = rowptr[d], en = rowptr[d + 1];
    float2 r = *(const float2*)&er[d * 2];
    float2 inv = block_inv_sum<128>(csrsrc, b, en, el, r, red, &inv_sh);
    float acc = 0.f;
    int h = t >> 6, dd = t & 63;
    for (int c = b; c < en; c += 128) {
        int cnt = min(128, en - c);
        __syncthreads();
        if (t < cnt) {
            int s = csrsrc[c + t];
            float2 l = *(const float2*)&el[s * 2];
            float e0 = l.x + r.x; e0 = e0 > 0.f ? e0 : 0.2f * e0;
            float e1 = l.y + r.y; e1 = e1 > 0.f ? e1 : 0.2f * e1;
            sal[t] = make_float2(__expf(e0) * inv.x, __expf(e1) * inv.y);
            ssrc[t] = s;
        }
        __syncthreads();
#pragma unroll 4
        for (int i = 0; i < cnt; i++) {
            float a = h ? sal[i].y : sal[i].x;
            acc = fmaf(a, h2[(size_t)ssrc[i] * 64 + dd], acc);
        }
    }
    size_t idx = ((size_t)h * NN + d) * 64 + dd;
    split_bf16(acc, &ahi[idx], &alo[idx]);
}

// ================= launch =================
extern "C" void kernel_launch(void* const* d_in, const int* in_sizes, int n_in,
                              void* d_out, int out_size) {
    const float* feat = (const float*)d_in[0];
    const int* src = (const int*)d_in[1];
    const int* dst = (const int*)d_in[2];
    const float* W1 = (const float*)d_in[3];
    const float* al1 = (const float*)d_in[4];
    const float* ar1 = (const float*)d_in[5];
    const float* b1 = (const float*)d_in[6];
    const float* W2 = (const float*)d_in[7];
    const float* al2 = (const float*)d_in[8];
    const float* ar2 = (const float*)d_in[9];
    const float* b2 = (const float*)d_in[10];
    const float* W3 = (const float*)d_in[11];
    const float* al3 = (const float*)d_in[12];
    const float* ar3 = (const float*)d_in[13];
    const float* b3 = (const float*)d_in[14];

    float* a_hat = (float*)d_out;
    float* x_hat = a_hat + (size_t)NN * NN;
    const int E = in_sizes[1];

    bf16 *w1thi, *w1tlo, *w2thi, *w2tlo, *w3thi, *w3tlo;
    bf16 *agg1hi, *agg1lo, *h2hi, *h2lo, *agg3hi, *agg3lo;
    float *h1p, *h2p, *h2, *el, *er, *uv, *u1, *u2;
    int *deg, *cursor, *rowptr, *csrsrc;
    cudaGetSymbolAddress((void**)&w1thi, g_w1thi);
    cudaGetSymbolAddress((void**)&w1tlo, g_w1tlo);
    cudaGetSymbolAddress((void**)&w2thi, g_w2thi);
    cudaGetSymbolAddress((void**)&w2tlo, g_w2tlo);
    cudaGetSymbolAddress((void**)&w3thi, g_w3thi);
    cudaGetSymbolAddress((void**)&w3tlo, g_w3tlo);
    cudaGetSymbolAddress((void**)&h1p, g_h1p);
    cudaGetSymbolAddress((void**)&agg1hi, g_agg1hi);
    cudaGetSymbolAddress((void**)&agg1lo, g_agg1lo);
    cudaGetSymbolAddress((void**)&h2p, g_h2p);
    cudaGetSymbolAddress((void**)&h2, g_h2);
    cudaGetSymbolAddress((void**)&h2hi, g_h2hi);
    cudaGetSymbolAddress((void**)&h2lo, g_h2lo);
    cudaGetSymbolAddress((void**)&agg3hi, g_agg3hi);
    cudaGetSymbolAddress((void**)&agg3lo, g_agg3lo);
    cudaGetSymbolAddress((void**)&el, g_el);
    cudaGetSymbolAddress((void**)&er, g_er);
    cudaGetSymbolAddress((void**)&uv, g_uv);
    cudaGetSymbolAddress((void**)&u1, g_u1);
    cudaGetSymbolAddress((void**)&u2, g_u2);
    cudaGetSymbolAddress((void**)&deg, g_deg);
    cudaGetSymbolAddress((void**)&cursor, g_cursor);
    cudaGetSymbolAddress((void**)&rowptr, g_rowptr);
    cudaGetSymbolAddress((void**)&csrsrc, g_csrsrc);

    cudaFuncSetAttribute(ahat_hmma, cudaFuncAttributeMaxDynamicSharedMemorySize, AHAT_SMEM);
    cudaFuncSetAttribute(hmma_gemm, cudaFuncAttributeMaxDynamicSharedMemorySize, HG_SMEM);
    cudaFuncSetAttribute(hmma_gemm1, cudaFuncAttributeMaxDynamicSharedMemorySize, HG1_SMEM);
    cudaFuncSetAttribute(dec_hmma, cudaFuncAttributeMaxDynamicSharedMemorySize, DEC_SMEM);

    static cudaStream_t s1 = nullptr, s2 = nullptr;
    static cudaEvent_t evRoot, evCSR, evW1, evPre, evW, evH2, evAhat;
    if (s1 == nullptr) {
        cudaStreamCreateWithFlags(&s1, cudaStreamNonBlocking);
        cudaStreamCreateWithFlags(&s2, cudaStreamNonBlocking);
        cudaEventCreateWithFlags(&evRoot, cudaEventDisableTiming);
        cudaEventCreateWithFlags(&evCSR, cudaEventDisableTiming);
        cudaEventCreateWithFlags(&evW1, cudaEventDisableTiming);
        cudaEventCreateWithFlags(&evPre, cudaEventDisableTiming);
        cudaEventCreateWithFlags(&evW, cudaEventDisableTiming);
        cudaEventCreateWithFlags(&evH2, cudaEventDisableTiming);
        cudaEventCreateWithFlags(&evAhat, cudaEventDisableTiming);
    }

    float *el1 = el, *el2 = el + NN * 2, *el3 = el + 2 * NN * 2;
    float *er1 = er, *er2 = er + NN * 2, *er3 = er + 2 * NN * 2;

    const int eb = (E + 255) / 256;

    // fork side streams
    cudaEventRecord(evRoot, 0);
    cudaStreamWaitEvent(s1, evRoot, 0);
    cudaStreamWaitEvent(s2, evRoot, 0);

    // ---- s1: CSR build (first needed at k_agg1) ----
    k_zerodeg<<<(NN + 255) / 256, 256, 0, s1>>>(deg);
    k_deg<<<eb, 256, 0, s1>>>(dst, deg, E);
    k_scan<<<1, 256, 0, s1>>>(deg, rowptr, cursor);
    k_scatter<<<eb, 256, 0, s1>>>(src, dst, cursor, csrsrc, E);
    cudaEventRecord(evCSR, s1);

    // ---- s2: weight packs + attention projections (overlap gemm1) ----
    k_pack_w1t<<<256, 256, 0, s2>>>(W1, w1thi, w1tlo);
    cudaEventRecord(evW1, s2);
    k_uv1<<<(FIN * 32 + 255) / 256, 256, 0, s2>>>(W1, al1, ar1, u1);
    k_elr1<<<(NN * 32 + 255) / 256, 256, 0, s2>>>(feat, u1, el1, er1);
    k_uv2<<<32, 256, 0, s2>>>(W2, al2, ar2, u2);
    cudaEventRecord(evPre, s2);
    k_pack_w2t<<<128, 256, 0, s2>>>(W2, w2thi, w2tlo);
    k_pack_w3t<<<NDEC, 64, 0, s2>>>(W3, w3thi, w3tlo);
    k_uv<<<16, 256, 0, s2>>>(W3, al3, ar3, uv);
    cudaEventRecord(evW, s2);

    // ---- main stream: layer 1 (reads fp32 feat directly) ----
    cudaStreamWaitEvent(0, evW1, 0);
    {
        dim3 grid(2, 64);
        hmma_gemm1<<<grid, 256, HG1_SMEM>>>(feat, w1thi, w1tlo, h1p);
    }
    cudaStreamWaitEvent(0, evCSR, 0);
    cudaStreamWaitEvent(0, evPre, 0);
    k_agg1<<<NN, 256>>>(rowptr, csrsrc, el1, er1, h1p, b1, u2, agg1hi, agg1lo, el2, er2);

    // ---- layer 2 ----
    cudaStreamWaitEvent(0, evW, 0);
    {
        dim3 grid(1, 64);
        hmma_gemm<<<grid, 256, HG_SMEM>>>(agg1hi, agg1lo, w2thi, w2tlo, h2p, 256, 256, 256, 128);
    }
    k_agg2<<<NN, 128>>>(rowptr, csrsrc, el2, er2, h2p, b2, uv, h2, h2hi, h2lo, el3, er3);
    cudaEventRecord(evH2, 0);

    // ---- s1: structure decoder a_hat (overlaps attribute decoder) ----
    cudaStreamWaitEvent(s1, evH2, 0);
    {
        dim3 grid(NN / 128, NN / 128);
        ahat_hmma<<<grid, 256, AHAT_SMEM, s1>>>(h2hi, h2lo, a_hat);
    }
    cudaEventRecord(evAhat, s1);

    // ---- main stream: attribute decoder ----
    k_agg3<<<NN, 128>>>(rowptr, csrsrc, el3, er3, h2, agg3hi, agg3lo);
    {
        dim3 grid(NDEC / 64, NN / 128);
        dec_hmma<<<grid, 256, DEC_SMEM>>>(agg3hi, agg3lo, w3thi, w3tlo, b3, x_hat);
    }

    // join
    cudaStreamWaitEvent(0, evAhat, 0);
}

// round 10
// speedup vs baseline: 1.0738x; 1.0738x over previous
#include <cuda_runtime.h>
#include <cuda_bf16.h>
#include <cstdint>

#define NN 8192
#define FIN 1433
#define FINB 1472      // FIN padded to multiple of 64
#define NDEC 1536      // decoder N padded to multiple of 64
#define MAXE (1 << 20)

typedef unsigned long long u64t;
typedef __nv_bfloat16 bf16;

// ---------------- scratch (device globals) ----------------
__device__ bf16 g_feathi[NN * FINB];
__device__ bf16 g_featlo[NN * FINB];
__device__ bf16 g_w1thi[256 * FINB];
__device__ bf16 g_w1tlo[256 * FINB];
__device__ bf16 g_w2thi[128 * 256];
__device__ bf16 g_w2tlo[128 * 256];
__device__ bf16 g_w3thi[2 * NDEC * 64];
__device__ bf16 g_w3tlo[2 * NDEC * 64];
__device__ float g_h1p[NN * 256];
__device__ bf16 g_agg1hi[NN * 256];
__device__ bf16 g_agg1lo[NN * 256];
__device__ float g_h2p[NN * 128];
__device__ float g_h2[NN * 64];
__device__ bf16 g_h2hi[NN * 64];
__device__ bf16 g_h2lo[NN * 64];
__device__ bf16 g_agg3hi[2 * NN * 64];
__device__ bf16 g_agg3lo[2 * NN * 64];
__device__ float g_el[3 * NN * 2];
__device__ float g_er[3 * NN * 2];
__device__ float g_uv[2 * 64 * 2];     // layer-3 u/v
__device__ float g_u1[4 * FINB];       // layer-1 u/v from feat
__device__ float g_u2[4 * 256];        // layer-2 u/v over agg1 dims
__device__ int g_deg[NN];
__device__ int g_cursor[NN];
__device__ int g_rowptr[NN + 1];
__device__ int g_csrsrc[MAXE];

__device__ __forceinline__ float lrelu(float x, float a) { return x > 0.f ? x : a * x; }

__device__ __forceinline__ uint32_t smem_u32(const void* p) {
    uint32_t a;
    asm("{ .reg .u64 t; cvta.to.shared.u64 t, %1; cvt.u32.u64 %0, t; }" : "=r"(a) : "l"(p));
    return a;
}
__device__ __forceinline__ void ldm_x4(uint32_t* r, uint32_t addr) {
    asm volatile("ldmatrix.sync.aligned.m8n8.x4.shared.b16 {%0,%1,%2,%3}, [%4];"
                 : "=r"(r[0]), "=r"(r[1]), "=r"(r[2]), "=r"(r[3]) : "r"(addr));
}
__device__ __forceinline__ void mma_bf16(float* c, const uint32_t* a, uint32_t b0, uint32_t b1) {
    asm volatile(
        "mma.sync.aligned.m16n8k16.row.col.f32.bf16.bf16.f32 "
        "{%0,%1,%2,%3}, {%4,%5,%6,%7}, {%8,%9}, {%0,%1,%2,%3};"
        : "+f"(c[0]), "+f"(c[1]), "+f"(c[2]), "+f"(c[3])
        : "r"(a[0]), "r"(a[1]), "r"(a[2]), "r"(a[3]), "r"(b0), "r"(b1));
}
__device__ __forceinline__ void split_bf16(float v, bf16* hi, bf16* lo) {
    bf16 h = __float2bfloat16(v);
    *hi = h;
    *lo = __float2bfloat16(v - __bfloat162float(h));
}
__device__ __forceinline__ void cp16(uint32_t dst, const void* src) {
    asm volatile("cp.async.cg.shared.global [%0], [%1], 16;" :: "r"(dst), "l"(src));
}

#define APITCH 72    // bf16 per smem row (144B) — conflict-free ldmatrix
#define TILEB 18432  // one 128xAPITCH bf16 tile in bytes

// ================= generic bf16-split HMMA GEMM, cp.async double-buffered =================
#define HG_SMEM (8 * TILEB)  // 147456 B

__global__ void __launch_bounds__(256)
hmma_gemm(const bf16* __restrict__ Ahi, const bf16* __restrict__ Alo,
          const bf16* __restrict__ Bhi, const bf16* __restrict__ Blo,
          float* __restrict__ C, int K, int lda, int ldb, int ldc) {
    extern __shared__ char smem[];
    const uint32_t sb = smem_u32(smem);
    const int tid = threadIdx.x, wid = tid >> 5, lane = tid & 31;
    const int rowBase = blockIdx.y * 128, colBase = blockIdx.x * 128;
    const int wm = (wid & 3) * 32, wn = (wid >> 2) * 64;
    const int lrow = lane & 15, lch = lane >> 4;
    const int nk = K >> 6;

    float acc[2][8][4];
#pragma unroll
    for (int i = 0; i < 2; i++)
#pragma unroll
        for (int j = 0; j < 8; j++)
#pragma unroll
            for (int q = 0; q < 4; q++) acc[i][j][q] = 0.f;

    auto stage = [&](int buf, int kc) {
        uint32_t base = sb + buf * (4 * TILEB);
        for (int idx = tid; idx < 1024; idx += 256) {
            int row = idx >> 3, ch = idx & 7;
            uint32_t off = (uint32_t)(row * APITCH + ch * 8) * 2;
            cp16(base + off, Ahi + (size_t)(rowBase + row) * lda + kc + ch * 8);
            cp16(base + TILEB + off, Alo + (size_t)(rowBase + row) * lda + kc + ch * 8);
            cp16(base + 2 * TILEB + off, Bhi + (size_t)(colBase + row) * ldb + kc + ch * 8);
            cp16(base + 3 * TILEB + off, Blo + (size_t)(colBase + row) * ldb + kc + ch * 8);
        }
        asm volatile("cp.async.commit_group;" ::: "memory");
    };

    stage(0, 0);
    for (int t = 0; t < nk; ++t) {
        asm volatile("cp.async.wait_group 0;" ::: "memory");
        __syncthreads();
        if (t + 1 < nk) stage((t + 1) & 1, (t + 1) * 64);
        const uint32_t base = sb + (t & 1) * (4 * TILEB);
        const uint32_t bAhi = base, bAlo = base + TILEB;
        const uint32_t bBhi = base + 2 * TILEB, bBlo = base + 3 * TILEB;
#pragma unroll
        for (int ks = 0; ks < 4; ks++) {
            uint32_t afh[2][4], afl[2][4];
#pragma unroll
            for (int i = 0; i < 2; i++) {
                uint32_t ao = ((wm + i * 16 + lrow) * APITCH) * 2 + (ks * 2 + lch) * 16;
                ldm_x4(afh[i], bAhi + ao);
                ldm_x4(afl[i], bAlo + ao);
            }
            uint32_t bfh[8][2], bfl[8][2];
#pragma unroll
            for (int jj = 0; jj < 4; jj++) {
                uint32_t bo = ((wn + jj * 16 + lrow) * APITCH) * 2 + (ks * 2 + lch) * 16;
                uint32_t r[4];
                ldm_x4(r, bBhi + bo);
                bfh[2 * jj][0] = r[0]; bfh[2 * jj][1] = r[2];
                bfh[2 * jj + 1][0] = r[1]; bfh[2 * jj + 1][1] = r[3];
                ldm_x4(r, bBlo + bo);
                bfl[2 * jj][0] = r[0]; bfl[2 * jj][1] = r[2];
                bfl[2 * jj + 1][0] = r[1]; bfl[2 * jj + 1][1] = r[3];
            }
#pragma unroll
            for (int i = 0; i < 2; i++)
#pragma unroll
                for (int j = 0; j < 8; j++) {
                    mma_bf16(acc[i][j], afh[i], bfh[j][0], bfh[j][1]);
                    mma_bf16(acc[i][j], afh[i], bfl[j][0], bfl[j][1]);
                    mma_bf16(acc[i][j], afl[i], bfh[j][0], bfh[j][1]);
                }
        }
        __syncthreads();
    }

    const int rr = lane >> 2, cc = (lane & 3) * 2;
#pragma unroll
    for (int i = 0; i < 2; i++) {
        int gr = rowBase + wm + i * 16 + rr;
        float* out0 = C + (size_t)gr * ldc + colBase + wn + cc;
        float* out1 = out0 + 8 * ldc;
#pragma unroll
        for (int j = 0; j < 8; j++) {
            *(float2*)(out0 + j * 8) = make_float2(acc[i][j][0], acc[i][j][1]);
            *(float2*)(out1 + j * 8) = make_float2(acc[i][j][2], acc[i][j][3]);
        }
    }
}

// ================= a_hat HMMA (128x128, K=64) =================
#define AHAT_SMEM (4 * TILEB)

__global__ void __launch_bounds__(256)
ahat_hmma(const bf16* __restrict__ hi, const bf16* __restrict__ lo, float* __restrict__ C) {
    extern __shared__ char smem[];
    bf16* sAhi = (bf16*)(smem);
    bf16* sAlo = (bf16*)(smem + TILEB);
    bf16* sBhi = (bf16*)(smem + 2 * TILEB);
    bf16* sBlo = (bf16*)(smem + 3 * TILEB);
    const int tid = threadIdx.x, wid = tid >> 5, lane = tid & 31;
    const int rowBase = blockIdx.y * 128, colBase = blockIdx.x * 128;

    for (int idx = tid; idx < 128 * 8; idx += 256) {
        int row = idx >> 3, ch = idx & 7;
        int off = row * APITCH + ch * 8;
        *(uint4*)(sAhi + off) = *((const uint4*)(hi + (size_t)(rowBase + row) * 64) + ch);
        *(uint4*)(sAlo + off) = *((const uint4*)(lo + (size_t)(rowBase + row) * 64) + ch);
        *(uint4*)(sBhi + off) = *((const uint4*)(hi + (size_t)(colBase + row) * 64) + ch);
        *(uint4*)(sBlo + off) = *((const uint4*)(lo + (size_t)(colBase + row) * 64) + ch);
    }
    __syncthreads();

    const int wm = (wid & 3) * 32, wn = (wid >> 2) * 64;
    float acc[2][8][4];
#pragma unroll
    for (int i = 0; i < 2; i++)
#pragma unroll
        for (int j = 0; j < 8; j++)
#pragma unroll
            for (int q = 0; q < 4; q++) acc[i][j][q] = 0.f;

    const int lrow = lane & 15, lch = lane >> 4;
    const uint32_t sbAhi = smem_u32(sAhi), sbAlo = smem_u32(sAlo);
    const uint32_t sbBhi = smem_u32(sBhi), sbBlo = smem_u32(sBlo);

#pragma unroll
    for (int pass = 0; pass < 3; pass++) {
        const uint32_t aBase = (pass == 2) ? sbAlo : sbAhi;
        const uint32_t bBase = (pass == 1) ? sbBlo : sbBhi;
#pragma unroll
        for (int ks = 0; ks < 4; ks++) {
            uint32_t af[2][4];
#pragma unroll
            for (int i = 0; i < 2; i++)
                ldm_x4(af[i], aBase + ((wm + i * 16 + lrow) * APITCH) * 2 + (ks * 2 + lch) * 16);
            uint32_t bf[8][2];
#pragma unroll
            for (int jj = 0; jj < 4; jj++) {
                uint32_t r[4];
                ldm_x4(r, bBase + ((wn + jj * 16 + lrow) * APITCH) * 2 + (ks * 2 + lch) * 16);
                bf[2 * jj][0] = r[0]; bf[2 * jj][1] = r[2];
                bf[2 * jj + 1][0] = r[1]; bf[2 * jj + 1][1] = r[3];
            }
#pragma unroll
            for (int i = 0; i < 2; i++)
#pragma unroll
                for (int j = 0; j < 8; j++)
                    mma_bf16(acc[i][j], af[i], bf[j][0], bf[j][1]);
        }
    }

    const int rr = lane >> 2, cc = (lane & 3) * 2;
#pragma unroll
    for (int i = 0; i < 2; i++) {
        int gr = rowBase + wm + i * 16 + rr;
        float* out0 = C + (size_t)gr * NN + colBase + wn + cc;
        float* out1 = out0 + 8 * NN;
#pragma unroll
        for (int j = 0; j < 8; j++) {
            *(float2*)(out0 + j * 8) = make_float2(acc[i][j][0], acc[i][j][1]);
            *(float2*)(out1 + j * 8) = make_float2(acc[i][j][2], acc[i][j][3]);
        }
    }
}

// ================= fused decoder HMMA (2 heads + bias + lrelu + mean) =================
#define DEC_SMEM (2 * TILEB + TILEB)

__global__ void __launch_bounds__(256)
dec_hmma(const bf16* __restrict__ Ahi, const bf16* __restrict__ Alo,
         const bf16* __restrict__ Bhi, const bf16* __restrict__ Blo,
         const float* __restrict__ b3, float* __restrict__ xhat) {
    extern __shared__ char smem[];
    bf16* sAhi = (bf16*)smem;
    bf16* sAlo = (bf16*)(smem + TILEB);
    bf16* sBhi = (bf16*)(smem + 2 * TILEB);
    bf16* sBlo = (bf16*)(smem + 2 * TILEB + TILEB / 2);
    const int tid = threadIdx.x, wid = tid >> 5, lane = tid & 31;
    const int rowBase = blockIdx.y * 128, colBase = blockIdx.x * 64;
    const int wm = (wid & 3) * 32, wn = (wid >> 2) * 32;
    const int lrow = lane & 15, lch = lane >> 4;

    float acc[2][2][4][4];
#pragma unroll
    for (int h = 0; h < 2; h++)
#pragma unroll
        for (int i = 0; i < 2; i++)
#pragma unroll
            for (int j = 0; j < 4; j++)
#pragma unroll
                for (int q = 0; q < 4; q++) acc[h][i][j][q] = 0.f;

    const uint32_t sbAhi = smem_u32(sAhi), sbAlo = smem_u32(sAlo);
    const uint32_t sbBhi = smem_u32(sBhi), sbBlo = smem_u32(sBlo);

#pragma unroll
    for (int h = 0; h < 2; h++) {
        const bf16* ahp = Ahi + (size_t)h * NN * 64;
        const bf16* alp = Alo + (size_t)h * NN * 64;
        const bf16* bhp = Bhi + (size_t)h * NDEC * 64;
        const bf16* blp = Blo + (size_t)h * NDEC * 64;
        __syncthreads();
        for (int idx = tid; idx < 1024; idx += 256) {
            int row = idx >> 3, ch = idx & 7;
            int off = row * APITCH + ch * 8;
            *(uint4*)(sAhi + off) = *(const uint4*)(ahp + (size_t)(rowBase + row) * 64 + ch * 8);
            *(uint4*)(sAlo + off) = *(const uint4*)(alp + (size_t)(rowBase + row) * 64 + ch * 8);
        }
        for (int idx = tid; idx < 512; idx += 256) {
            int row = idx >> 3, ch = idx & 7;
            int off = row * APITCH + ch * 8;
            *(uint4*)(sBhi + off) = *(const uint4*)(bhp + (size_t)(colBase + row) * 64 + ch * 8);
            *(uint4*)(sBlo + off) = *(const uint4*)(blp + (size_t)(colBase + row) * 64 + ch * 8);
        }
        __syncthreads();
#pragma unroll
        for (int ks = 0; ks < 4; ks++) {
            uint32_t afh[2][4], afl[2][4];
#pragma unroll
            for (int i = 0; i < 2; i++) {
                uint32_t ao = ((wm + i * 16 + lrow) * APITCH) * 2 + (ks * 2 + lch) * 16;
                ldm_x4(afh[i], sbAhi + ao);
                ldm_x4(afl[i], sbAlo + ao);
            }
            uint32_t bfh[4][2], bfl[4][2];
#pragma unroll
            for (int jj = 0; jj < 2; jj++) {
                uint32_t bo = ((wn + jj * 16 + lrow) * APITCH) * 2 + (ks * 2 + lch) * 16;
                uint32_t r[4];
                ldm_x4(r, sbBhi + bo);
                bfh[2 * jj][0] = r[0]; bfh[2 * jj][1] = r[2];
                bfh[2 * jj + 1][0] = r[1]; bfh[2 * jj + 1][1] = r[3];
                ldm_x4(r, sbBlo + bo);
                bfl[2 * jj][0] = r[0]; bfl[2 * jj][1] = r[2];
                bfl[2 * jj + 1][0] = r[1]; bfl[2 * jj + 1][1] = r[3];
            }
#pragma unroll
            for (int i = 0; i < 2; i++)
#pragma unroll
                for (int j = 0; j < 4; j++) {
                    mma_bf16(acc[h][i][j], afh[i], bfh[j][0], bfh[j][1]);
                    mma_bf16(acc[h][i][j], afh[i], bfl[j][0], bfl[j][1]);
                    mma_bf16(acc[h][i][j], afl[i], bfh[j][0], bfh[j][1]);
                }
        }
    }

    const int rr = lane >> 2, cc = (lane & 3) * 2;
#pragma unroll
    for (int i = 0; i < 2; i++) {
#pragma unroll
        for (int j = 0; j < 4; j++) {
#pragma unroll
            for (int half = 0; half < 2; half++) {
                int gr = rowBase + wm + i * 16 + rr + half * 8;
                int gn = colBase + wn + j * 8 + cc;
                if (gn < FIN) {
                    float v0 = acc[0][i][j][half * 2], v1 = acc[1][i][j][half * 2];
                    xhat[(size_t)gr * FIN + gn] =
                        0.5f * (lrelu(v0 + b3[gn], 0.01f) + lrelu(v1 + b3[FIN + gn], 0.01f));
                }
                if (gn + 1 < FIN) {
                    float v0 = acc[0][i][j][half * 2 + 1], v1 = acc[1][i][j][half * 2 + 1];
                    xhat[(size_t)gr * FIN + gn + 1] =
                        0.5f * (lrelu(v0 + b3[gn + 1], 0.01f) + lrelu(v1 + b3[FIN + gn + 1], 0.01f));
                }
            }
        }
    }
}

// ================= CSR build =================
__global__ void k_zerodeg(int* deg) {
    int i = blockIdx.x * blockDim.x + threadIdx.x;
    if (i < NN) deg[i] = 0;
}
__global__ void k_deg(const int* __restrict__ dst, int* deg, int E) {
    int e = blockIdx.x * blockDim.x + threadIdx.x;
    if (e < E) atomicAdd(&deg[dst[e]], 1);
}
__global__ void k_scan(const int* __restrict__ deg, int* rowptr, int* cursor) {
    __shared__ int partx[257];
    int t = threadIdx.x;
    int base = t * 32;
    int loc[32];
    int s = 0;
#pragma unroll
    for (int i = 0; i < 32; i++) { loc[i] = s; s += deg[base + i]; }
    __shared__ int part[256];
    part[t] = s;
    __syncthreads();
    if (t == 0) {
        int acc = 0;
        for (int i = 0; i < 256; i++) { partx[i] = acc; acc += part[i]; }
        partx[256] = acc;
    }
    __syncthreads();
    int off = partx[t];
#pragma unroll
    for (int i = 0; i < 32; i++) {
        int v = off + loc[i];
        rowptr[base + i] = v;
        cursor[base + i] = v;
    }
    if (t == 0) rowptr[NN] = partx[256];
}
__global__ void k_scatter(const int* __restrict__ src, const int* __restrict__ dst,
                          int* cursor, int* csrsrc, int E) {
    int e = blockIdx.x * blockDim.x + threadIdx.x;
    if (e >= E) return;
    int d = dst[e];
    int idx = atomicAdd(&cursor[d], 1);
    csrsrc[idx] = src[e];
}

// ================= pack kernels =================
__global__ void k_pack_feat(const float* __restrict__ feat, bf16* __restrict__ fhi,
                            bf16* __restrict__ flo) {
    int n = blockIdx.x;
    for (int f = threadIdx.x; f < FINB; f += blockDim.x) {
        float v = (f < FIN) ? feat[(size_t)n * FIN + f] : 0.f;
        split_bf16(v, &fhi[(size_t)n * FINB + f], &flo[(size_t)n * FINB + f]);
    }
}
__global__ void k_pack_w1t(const float* __restrict__ W1, bf16* __restrict__ whi,
                           bf16* __restrict__ wlo) {
    int n = blockIdx.x;  // 256
    for (int k = threadIdx.x; k < FINB; k += blockDim.x) {
        float v = (k < FIN) ? W1[(size_t)k * 256 + n] : 0.f;
        split_bf16(v, &whi[(size_t)n * FINB + k], &wlo[(size_t)n * FINB + k]);
    }
}
__global__ void k_pack_w2t(const float* __restrict__ W2, bf16* __restrict__ whi,
                           bf16* __restrict__ wlo) {
    int n = blockIdx.x;  // 128
    for (int k = threadIdx.x; k < 256; k += blockDim.x) {
        float v = W2[(size_t)k * 128 + n];
        split_bf16(v, &whi[(size_t)n * 256 + k], &wlo[(size_t)n * 256 + k]);
    }
}
__global__ void k_pack_w3t(const float* __restrict__ W3, bf16* __restrict__ whi,
                           bf16* __restrict__ wlo) {
    int f = blockIdx.x;  // NDEC
    int k = threadIdx.x; // 64
#pragma unroll
    for (int h = 0; h < 2; h++) {
        float v = (f < FIN) ? W3[(size_t)k * (2 * FIN) + h * FIN + f] : 0.f;
        split_bf16(v, &whi[((size_t)h * NDEC + f) * 64 + k], &wlo[((size_t)h * NDEC + f) * 64 + k]);
    }
}

// ================= attention projections =================
__global__ void k_uv1(const float* __restrict__ W1, const float* __restrict__ al1,
                      const float* __restrict__ ar1, float* __restrict__ u1) {
    int w = (blockIdx.x * blockDim.x + threadIdx.x) >> 5;
    int lane = threadIdx.x & 31;
    if (w >= FIN) return;
    const float* Wr = W1 + (size_t)w * 256;
    float a0 = 0.f, a1 = 0.f, r0 = 0.f, r1 = 0.f;
#pragma unroll
    for (int j = lane; j < 128; j += 32) {
        float w0 = Wr[j], w1 = Wr[128 + j];
        a0 += w0 * al1[j]; a1 += w1 * al1[128 + j];
        r0 += w0 * ar1[j]; r1 += w1 * ar1[128 + j];
    }
#pragma unroll
    for (int o = 16; o; o >>= 1) {
        a0 += __shfl_down_sync(0xffffffffu, a0, o);
        a1 += __shfl_down_sync(0xffffffffu, a1, o);
        r0 += __shfl_down_sync(0xffffffffu, r0, o);
        r1 += __shfl_down_sync(0xffffffffu, r1, o);
    }
    if (lane == 0) {
        u1[w] = a0; u1[FINB + w] = a1; u1[2 * FINB + w] = r0; u1[3 * FINB + w] = r1;
    }
}
__global__ void k_elr1(const float* __restrict__ feat, const float* __restrict__ u1,
                       float* __restrict__ el, float* __restrict__ er) {
    int w = (blockIdx.x * blockDim.x + threadIdx.x) >> 5;
    int lane = threadIdx.x & 31;
    if (w >= NN) return;
    const float* row = feat + (size_t)w * FIN;
    float a0 = 0.f, a1 = 0.f, r0 = 0.f, r1 = 0.f;
    for (int f = lane; f < FIN; f += 32) {
        float x = row[f];
        a0 += x * u1[f]; a1 += x * u1[FINB + f];
        r0 += x * u1[2 * FINB + f]; r1 += x * u1[3 * FINB + f];
    }
#pragma unroll
    for (int o = 16; o; o >>= 1) {
        a0 += __shfl_down_sync(0xffffffffu, a0, o);
        a1 += __shfl_down_sync(0xffffffffu, a1, o);
        r0 += __shfl_down_sync(0xffffffffu, r0, o);
        r1 += __shfl_down_sync(0xffffffffu, r1, o);
    }
    if (lane == 0) { el[w * 2] = a0; el[w * 2 + 1] = a1; er[w * 2] = r0; er[w * 2 + 1] = r1; }
}
__global__ void k_uv2(const float* __restrict__ W2, const float* __restrict__ al2,
                      const float* __restrict__ ar2, float* __restrict__ u2) {
    int w = (blockIdx.x * blockDim.x + threadIdx.x) >> 5;
    int lane = threadIdx.x & 31;
    if (w >= 256) return;
    const float* Wr = W2 + (size_t)w * 128;
    float a0 = 0.f, a1 = 0.f, r0 = 0.f, r1 = 0.f;
#pragma unroll
    for (int j = lane; j < 64; j += 32) {
        float w0 = Wr[j], w1 = Wr[64 + j];
        a0 += w0 * al2[j]; a1 += w1 * al2[64 + j];
        r0 += w0 * ar2[j]; r1 += w1 * ar2[64 + j];
    }
#pragma unroll
    for (int o = 16; o; o >>= 1) {
        a0 += __shfl_down_sync(0xffffffffu, a0, o);
        a1 += __shfl_down_sync(0xffffffffu, a1, o);
        r0 += __shfl_down_sync(0xffffffffu, r0, o);
        r1 += __shfl_down_sync(0xffffffffu, r1, o);
    }
    if (lane == 0) { u2[w] = a0; u2[256 + w] = a1; u2[512 + w] = r0; u2[768 + w] = r1; }
}
__global__ void k_uv(const float* __restrict__ W3, const float* __restrict__ al3,
                     const float* __restrict__ ar3, float* uv) {
    int w = (blockIdx.x * blockDim.x + threadIdx.x) >> 5;
    int lane = threadIdx.x & 31;
    if (w >= 128) return;
    int h = w >> 6, k = w & 63;
    const float* Wr = W3 + (size_t)k * (2 * FIN) + h * FIN;
    const float* a = al3 + (size_t)h * FIN;
    const float* b = ar3 + (size_t)h * FIN;
    float su = 0.f, sv = 0.f;
    for (int f = lane; f < FIN; f += 32) { float ww = Wr[f]; su += ww * a[f]; sv += ww * b[f]; }
#pragma unroll
    for (int o = 16; o; o >>= 1) {
        su += __shfl_down_sync(0xffffffffu, su, o);
        sv += __shfl_down_sync(0xffffffffu, sv, o);
    }
    if (lane == 0) { uv[h * 64 + k] = su; uv[128 + h * 64 + k] = sv; }
}

// ================= block softmax-sum helper =================
template <int NT>
__device__ __forceinline__ float2 block_inv_sum(const int* csrsrc, int b, int en,
                                                const float* el, float2 r,
                                                float* red, float2* out_sh) {
    int t = threadIdx.x, lane = t & 31, wid = t >> 5;
    float p0 = 0.f, p1 = 0.f;
    for (int i = b + t; i < en; i += NT) {
        int s = csrsrc[i];
        float2 l = *(const float2*)&el[s * 2];
        float e0 = l.x + r.x; e0 = e0 > 0.f ? e0 : 0.2f * e0;
        float e1 = l.y + r.y; e1 = e1 > 0.f ? e1 : 0.2f * e1;
        p0 += __expf(e0); p1 += __expf(e1);
    }
#pragma unroll
    for (int o = 16; o; o >>= 1) {
        p0 += __shfl_down_sync(0xffffffffu, p0, o);
        p1 += __shfl_down_sync(0xffffffffu, p1, o);
    }
    if (lane == 0) { red[wid * 2] = p0; red[wid * 2 + 1] = p1; }
    __syncthreads();
    if (t == 0) {
        float s0 = 0.f, s1 = 0.f;
        for (int w = 0; w < NT / 32; w++) { s0 += red[w * 2]; s1 += red[w * 2 + 1]; }
        *out_sh = make_float2(1.f / s0, 1.f / s1);
    }
    __syncthreads();
    return *out_sh;
}

// ================= CSR gather aggregation =================
// layer1 + fused el2/er2 epilogue
__global__ void __launch_bounds__(256)
k_agg1(const int* __restrict__ rowptr, const int* __restrict__ csrsrc,
       const float* __restrict__ el, const float* __restrict__ er,
       const float* __restrict__ hp, const float* __restrict__ b1,
       const float* __restrict__ u2,
       bf16* __restrict__ ohi, bf16* __restrict__ olo,
       float* __restrict__ el2, float* __restrict__ er2) {
    int d = blockIdx.x;
    int t = threadIdx.x, lane = t & 31, warp = t >> 5;
    __shared__ float2 sal[128];
    __shared__ int ssrc[128];
    __shared__ float red[16];
    __shared__ float2 inv_sh;
    __shared__ float redq[8][4];
    int b = rowptr[d], en = rowptr[d + 1];
    float2 r = *(const float2*)&er[d * 2];
    float2 inv = block_inv_sum<256>(csrsrc, b, en, el, r, red, &inv_sh);
    float acc = 0.f;
    int h = t >> 7;
    for (int c = b; c < en; c += 128) {
        int cnt = min(128, en - c);
        __syncthreads();
        if (t < cnt) {
            int s = csrsrc[c + t];
            float2 l = *(const float2*)&el[s * 2];
            float e0 = l.x + r.x; e0 = e0 > 0.f ? e0 : 0.2f * e0;
            float e1 = l.y + r.y; e1 = e1 > 0.f ? e1 : 0.2f * e1;
            sal[t] = make_float2(__expf(e0) * inv.x, __expf(e1) * inv.y);
            ssrc[t] = s;
        }
        __syncthreads();
#pragma unroll 4
        for (int i = 0; i < cnt; i++) {
            float a = h ? sal[i].y : sal[i].x;
            acc = fmaf(a, hp[(size_t)ssrc[i] * 256 + t], acc);
        }
    }
    float x = lrelu(acc + b1[t], 0.01f);
    split_bf16(x, &ohi[(size_t)d * 256 + t], &olo[(size_t)d * 256 + t]);
    // fused el2/er2
    float c0 = x * u2[t], c1 = x * u2[256 + t], c2 = x * u2[512 + t], c3 = x * u2[768 + t];
#pragma unroll
    for (int o = 16; o; o >>= 1) {
        c0 += __shfl_down_sync(0xffffffffu, c0, o);
        c1 += __shfl_down_sync(0xffffffffu, c1, o);
        c2 += __shfl_down_sync(0xffffffffu, c2, o);
        c3 += __shfl_down_sync(0xffffffffu, c3, o);
    }
    if (lane == 0) { redq[warp][0] = c0; redq[warp][1] = c1; redq[warp][2] = c2; redq[warp][3] = c3; }
    __syncthreads();
    if (t == 0) {
        float s0 = 0.f, s1 = 0.f, s2 = 0.f, s3 = 0.f;
        for (int w = 0; w < 8; w++) { s0 += redq[w][0]; s1 += redq[w][1]; s2 += redq[w][2]; s3 += redq[w][3]; }
        el2[d * 2] = s0; el2[d * 2 + 1] = s1;
        er2[d * 2] = s2; er2[d * 2 + 1] = s3;
    }
}

// layer2 + fused el3/er3 epilogue
__global__ void __launch_bounds__(128)
k_agg2(const int* __restrict__ rowptr, const int* __restrict__ csrsrc,
       const float* __restrict__ el, const float* __restrict__ er,
       const float* __restrict__ hp, const float* __restrict__ b2,
       const float* __restrict__ uv,
       float* __restrict__ h2, bf16* __restrict__ h2hi, bf16* __restrict__ h2lo,
       float* __restrict__ el3, float* __restrict__ er3) {
    int d = blockIdx.x;
    int t = threadIdx.x, lane = t & 31, warp = t >> 5;
    __shared__ float2 sal[128];
    __shared__ int ssrc[128];
    __shared__ float o[128];
    __shared__ float red[8];
    __shared__ float2 inv_sh;
    __shared__ float redq[4][4];
    int b = rowptr[d], en = rowptr[d + 1];
    float2 r = *(const float2*)&er[d * 2];
    float2 inv = block_inv_sum<128>(csrsrc, b, en, el, r, red, &inv_sh);
    float acc = 0.f;
    int h = t >> 6;
    for (int c = b; c < en; c += 128) {
        int cnt = min(128, en - c);
        __syncthreads();
        if (t < cnt) {
            int s = csrsrc[c + t];
            float2 l = *(const float2*)&el[s * 2];
            float e0 = l.x + r.x; e0 = e0 > 0.f ? e0 : 0.2f * e0;
            float e1 = l.y + r.y; e1 = e1 > 0.f ? e1 : 0.2f * e1;
            sal[t] = make_float2(__expf(e0) * inv.x, __expf(e1) * inv.y);
            ssrc[t] = s;
        }
        __syncthreads();
#pragma unroll 4
        for (int i = 0; i < cnt; i++) {
            float a = h ? sal[i].y : sal[i].x;
            acc = fmaf(a, hp[(size_t)ssrc[i] * 128 + t], acc);
        }
    }
    o[t] = acc;
    __syncthreads();
    float v = 0.f;
    if (t < 64) {
        float x0 = lrelu(o[t] + b2[t], 0.01f);
        float x1 = lrelu(o[64 + t] + b2[64 + t], 0.01f);
        v = 0.5f * (x0 + x1);
        h2[(size_t)d * 64 + t] = v;
        split_bf16(v, &h2hi[(size_t)d * 64 + t], &h2lo[(size_t)d * 64 + t]);
    }
    // fused el3/er3
    float c0 = 0.f, c1 = 0.f, c2 = 0.f, c3 = 0.f;
    if (t < 64) {
        c0 = v * uv[t]; c1 = v * uv[64 + t]; c2 = v * uv[128 + t]; c3 = v * uv[192 + t];
    }
#pragma unroll
    for (int o2 = 16; o2; o2 >>= 1) {
        c0 += __shfl_down_sync(0xffffffffu, c0, o2);
        c1 += __shfl_down_sync(0xffffffffu, c1, o2);
        c2 += __shfl_down_sync(0xffffffffu, c2, o2);
        c3 += __shfl_down_sync(0xffffffffu, c3, o2);
    }
    if (lane == 0) { redq[warp][0] = c0; redq[warp][1] = c1; redq[warp][2] = c2; redq[warp][3] = c3; }
    __syncthreads();
    if (t == 0) {
        el3[d * 2] = redq[0][0] + redq[1][0];
        el3[d * 2 + 1] = redq[0][1] + redq[1][1];
        er3[d * 2] = redq[0][2] + redq[1][2];
        er3[d * 2 + 1] = redq[0][3] + redq[1][3];
    }
}

__global__ void __launch_bounds__(128)
k_agg3(const int* __restrict__ rowptr, const int* __restrict__ csrsrc,
       const float* __restrict__ el, const float* __restrict__ er,
       const float* __restrict__ h2, bf16* __restrict__ ahi, bf16* __restrict__ alo) {
    int d = blockIdx.x;
    int t = threadIdx.x;
    __shared__ float2 sal[128];
    __shared__ int ssrc[128];
    __shared__ float red[8];
    __shared__ float2 inv_sh;
    int b = rowptr[d], en = rowptr[d + 1];
    float2 r = *(const float2*)&er[d * 2];
    float2 inv = block_inv_sum<128>(csrsrc, b, en, el, r, red, &inv_sh);
    float acc = 0.f;
    int h = t >> 6, dd = t & 63;
    for (int c = b; c < en; c += 128) {
        int cnt = min(128, en - c);
        __syncthreads();
        if (t < cnt) {
            int s = csrsrc[c + t];
            float2 l = *(const float2*)&el[s * 2];
            float e0 = l.x + r.x; e0 = e0 > 0.f ? e0 : 0.2f * e0;
            float e1 = l.y + r.y; e1 = e1 > 0.f ? e1 : 0.2f * e1;
            sal[t] = make_float2(__expf(e0) * inv.x, __expf(e1) * inv.y);
            ssrc[t] = s;
        }
        __syncthreads();
#pragma unroll 4
        for (int i = 0; i < cnt; i++) {
            float a = h ? sal[i].y : sal[i].x;
            acc = fmaf(a, h2[(size_t)ssrc[i] * 64 + dd], acc);
        }
    }
    size_t idx = ((size_t)h * NN + d) * 64 + dd;
    split_bf16(acc, &ahi[idx], &alo[idx]);
}

// ================= launch =================
extern "C" void kernel_launch(void* const* d_in, const int* in_sizes, int n_in,
                              void* d_out, int out_size) {
    const float* feat = (const float*)d_in[0];
    const int* src = (const int*)d_in[1];
    const int* dst = (const int*)d_in[2];
    const float* W1 = (const float*)d_in[3];
    const float* al1 = (const float*)d_in[4];
    const float* ar1 = (const float*)d_in[5];
    const float* b1 = (const float*)d_in[6];
    const float* W2 = (const float*)d_in[7];
    const float* al2 = (const float*)d_in[8];
    const float* ar2 = (const float*)d_in[9];
    const float* b2 = (const float*)d_in[10];
    const float* W3 = (const float*)d_in[11];
    const float* al3 = (const float*)d_in[12];
    const float* ar3 = (const float*)d_in[13];
    const float* b3 = (const float*)d_in[14];

    float* a_hat = (float*)d_out;
    float* x_hat = a_hat + (size_t)NN * NN;
    const int E = in_sizes[1];

    bf16 *feathi, *featlo, *w1thi, *w1tlo, *w2thi, *w2tlo, *w3thi, *w3tlo;
    bf16 *agg1hi, *agg1lo, *h2hi, *h2lo, *agg3hi, *agg3lo;
    float *h1p, *h2p, *h2, *el, *er, *uv, *u1, *u2;
    int *deg, *cursor, *rowptr, *csrsrc;
    cudaGetSymbolAddress((void**)&feathi, g_feathi);
    cudaGetSymbolAddress((void**)&featlo, g_featlo);
    cudaGetSymbolAddress((void**)&w1thi, g_w1thi);
    cudaGetSymbolAddress((void**)&w1tlo, g_w1tlo);
    cudaGetSymbolAddress((void**)&w2thi, g_w2thi);
    cudaGetSymbolAddress((void**)&w2tlo, g_w2tlo);
    cudaGetSymbolAddress((void**)&w3thi, g_w3thi);
    cudaGetSymbolAddress((void**)&w3tlo, g_w3tlo);
    cudaGetSymbolAddress((void**)&h1p, g_h1p);
    cudaGetSymbolAddress((void**)&agg1hi, g_agg1hi);
    cudaGetSymbolAddress((void**)&agg1lo, g_agg1lo);
    cudaGetSymbolAddress((void**)&h2p, g_h2p);
    cudaGetSymbolAddress((void**)&h2, g_h2);
    cudaGetSymbolAddress((void**)&h2hi, g_h2hi);
    cudaGetSymbolAddress((void**)&h2lo, g_h2lo);
    cudaGetSymbolAddress((void**)&agg3hi, g_agg3hi);
    cudaGetSymbolAddress((void**)&agg3lo, g_agg3lo);
    cudaGetSymbolAddress((void**)&el, g_el);
    cudaGetSymbolAddress((void**)&er, g_er);
    cudaGetSymbolAddress((void**)&uv, g_uv);
    cudaGetSymbolAddress((void**)&u1, g_u1);
    cudaGetSymbolAddress((void**)&u2, g_u2);
    cudaGetSymbolAddress((void**)&deg, g_deg);
    cudaGetSymbolAddress((void**)&cursor, g_cursor);
    cudaGetSymbolAddress((void**)&rowptr, g_rowptr);
    cudaGetSymbolAddress((void**)&csrsrc, g_csrsrc);

    cudaFuncSetAttribute(ahat_hmma, cudaFuncAttributeMaxDynamicSharedMemorySize, AHAT_SMEM);
    cudaFuncSetAttribute(hmma_gemm, cudaFuncAttributeMaxDynamicSharedMemorySize, HG_SMEM);
    cudaFuncSetAttribute(dec_hmma, cudaFuncAttributeMaxDynamicSharedMemorySize, DEC_SMEM);

    static cudaStream_t s1 = nullptr, s2 = nullptr;
    static cudaEvent_t evRoot, evCSR, evW1, evPre, evW, evH2, evAhat;
    if (s1 == nullptr) {
        cudaStreamCreateWithFlags(&s1, cudaStreamNonBlocking);
        cudaStreamCreateWithFlags(&s2, cudaStreamNonBlocking);
        cudaEventCreateWithFlags(&evRoot, cudaEventDisableTiming);
        cudaEventCreateWithFlags(&evCSR, cudaEventDisableTiming);
        cudaEventCreateWithFlags(&evW1, cudaEventDisableTiming);
        cudaEventCreateWithFlags(&evPre, cudaEventDisableTiming);
        cudaEventCreateWithFlags(&evW, cudaEventDisableTiming);
        cudaEventCreateWithFlags(&evH2, cudaEventDisableTiming);
        cudaEventCreateWithFlags(&evAhat, cudaEventDisableTiming);
    }

    float *el1 = el, *el2 = el + NN * 2, *el3 = el + 2 * NN * 2;
    float *er1 = er, *er2 = er + NN * 2, *er3 = er + 2 * NN * 2;

    const int eb = (E + 255) / 256;

    // fork side streams
    cudaEventRecord(evRoot, 0);
    cudaStreamWaitEvent(s1, evRoot, 0);
    cudaStreamWaitEvent(s2, evRoot, 0);

    // ---- s1: CSR build (first needed at k_agg1) ----
    k_zerodeg<<<(NN + 255) / 256, 256, 0, s1>>>(deg);
    k_deg<<<eb, 256, 0, s1>>>(dst, deg, E);
    k_scan<<<1, 256, 0, s1>>>(deg, rowptr, cursor);
    k_scatter<<<eb, 256, 0, s1>>>(src, dst, cursor, csrsrc, E);
    cudaEventRecord(evCSR, s1);

    // ---- s2: weight packs + attention projections (overlap gemm1) ----
    k_pack_w1t<<<256, 256, 0, s2>>>(W1, w1thi, w1tlo);
    cudaEventRecord(evW1, s2);
    k_uv1<<<(FIN * 32 + 255) / 256, 256, 0, s2>>>(W1, al1, ar1, u1);
    k_elr1<<<(NN * 32 + 255) / 256, 256, 0, s2>>>(feat, u1, el1, er1);
    k_uv2<<<32, 256, 0, s2>>>(W2, al2, ar2, u2);
    cudaEventRecord(evPre, s2);
    k_pack_w2t<<<128, 256, 0, s2>>>(W2, w2thi, w2tlo);
    k_pack_w3t<<<NDEC, 64, 0, s2>>>(W3, w3thi, w3tlo);
    k_uv<<<16, 256, 0, s2>>>(W3, al3, ar3, uv);
    cudaEventRecord(evW, s2);

    // ---- main stream: layer 1 (packed bf16 feat, proven R8 path) ----
    k_pack_feat<<<NN, 256>>>(feat, feathi, featlo);
    cudaStreamWaitEvent(0, evW1, 0);
    {
        dim3 grid(2, 64);
        hmma_gemm<<<grid, 256, HG_SMEM>>>(feathi, featlo, w1thi, w1tlo, h1p, FINB, FINB, FINB, 256);
    }
    cudaStreamWaitEvent(0, evCSR, 0);
    cudaStreamWaitEvent(0, evPre, 0);
    k_agg1<<<NN, 256>>>(rowptr, csrsrc, el1, er1, h1p, b1, u2, agg1hi, agg1lo, el2, er2);

    // ---- layer 2 ----
    cudaStreamWaitEvent(0, evW, 0);
    {
        dim3 grid(1, 64);
        hmma_gemm<<<grid, 256, HG_SMEM>>>(agg1hi, agg1lo, w2thi, w2tlo, h2p, 256, 256, 256, 128);
    }
    k_agg2<<<NN, 128>>>(rowptr, csrsrc, el2, er2, h2p, b2, uv, h2, h2hi, h2lo, el3, er3);
    cudaEventRecord(evH2, 0);

    // ---- s1: structure decoder a_hat (overlaps attribute decoder) ----
    cudaStreamWaitEvent(s1, evH2, 0);
    {
        dim3 grid(NN / 128, NN / 128);
        ahat_hmma<<<grid, 256, AHAT_SMEM, s1>>>(h2hi, h2lo, a_hat);
    }
    cudaEventRecord(evAhat, s1);

    // ---- main stream: attribute decoder ----
    k_agg3<<<NN, 128>>>(rowptr, csrsrc, el3, er3, h2, agg3hi, agg3lo);
    {
        dim3 grid(NDEC / 64, NN / 128);
        dec_hmma<<<grid, 256, DEC_SMEM>>>(agg3hi, agg3lo, w3thi, w3tlo, b3, x_hat);
    }

    // join
    cudaStreamWaitEvent(0, evAhat, 0);
}

// round 11
// speedup vs baseline: 1.0758x; 1.0019x over previous
#include <cuda_runtime.h>
#include <cuda_bf16.h>
#include <cstdint>

#define NN 8192
#define FIN 1433
#define FINB 1472      // FIN padded to multiple of 64
#define NDEC 1536      // decoder N padded to multiple of 64
#define MAXE (1 << 20)

typedef unsigned long long u64t;
typedef __nv_bfloat16 bf16;

// ---------------- scratch (device globals) ----------------
__device__ bf16 g_feathi[NN * FINB];
__device__ bf16 g_featlo[NN * FINB];
__device__ bf16 g_w1thi[256 * FINB];
__device__ bf16 g_w1tlo[256 * FINB];
__device__ bf16 g_w2thi[128 * 256];
__device__ bf16 g_w2tlo[128 * 256];
__device__ bf16 g_w3thi[2 * NDEC * 64];
__device__ bf16 g_w3tlo[2 * NDEC * 64];
__device__ float g_h1p[NN * 256];
__device__ bf16 g_agg1hi[NN * 256];
__device__ bf16 g_agg1lo[NN * 256];
__device__ float g_h2p[NN * 128];
__device__ float g_h2[NN * 64];
__device__ bf16 g_h2hi[NN * 64];
__device__ bf16 g_h2lo[NN * 64];
__device__ bf16 g_agg3hi[2 * NN * 64];
__device__ bf16 g_agg3lo[2 * NN * 64];
__device__ float g_el[3 * NN * 2];
__device__ float g_er[3 * NN * 2];
__device__ float g_uv[2 * 64 * 2];     // layer-3 u/v
__device__ float g_u2[4 * 256];        // layer-2 u/v over agg1 dims
__device__ int g_deg[NN];
__device__ int g_cursor[NN];
__device__ int g_rowptr[NN + 1];
__device__ int g_csrsrc[MAXE];

__device__ __forceinline__ float lrelu(float x, float a) { return x > 0.f ? x : a * x; }

__device__ __forceinline__ uint32_t smem_u32(const void* p) {
    uint32_t a;
    asm("{ .reg .u64 t; cvta.to.shared.u64 t, %1; cvt.u32.u64 %0, t; }" : "=r"(a) : "l"(p));
    return a;
}
__device__ __forceinline__ void ldm_x4(uint32_t* r, uint32_t addr) {
    asm volatile("ldmatrix.sync.aligned.m8n8.x4.shared.b16 {%0,%1,%2,%3}, [%4];"
                 : "=r"(r[0]), "=r"(r[1]), "=r"(r[2]), "=r"(r[3]) : "r"(addr));
}
__device__ __forceinline__ void mma_bf16(float* c, const uint32_t* a, uint32_t b0, uint32_t b1) {
    asm volatile(
        "mma.sync.aligned.m16n8k16.row.col.f32.bf16.bf16.f32 "
        "{%0,%1,%2,%3}, {%4,%5,%6,%7}, {%8,%9}, {%0,%1,%2,%3};"
        : "+f"(c[0]), "+f"(c[1]), "+f"(c[2]), "+f"(c[3])
        : "r"(a[0]), "r"(a[1]), "r"(a[2]), "r"(a[3]), "r"(b0), "r"(b1));
}
__device__ __forceinline__ void split_bf16(float v, bf16* hi, bf16* lo) {
    bf16 h = __float2bfloat16(v);
    *hi = h;
    *lo = __float2bfloat16(v - __bfloat162float(h));
}
__device__ __forceinline__ void cp16(uint32_t dst, const void* src) {
    asm volatile("cp.async.cg.shared.global [%0], [%1], 16;" :: "r"(dst), "l"(src));
}

#define APITCH 72    // bf16 per smem row (144B) — conflict-free ldmatrix
#define TILEB 18432  // one 128xAPITCH bf16 tile in bytes

// ================= generic bf16-split HMMA GEMM, cp.async double-buffered =================
#define HG_SMEM (8 * TILEB)  // 147456 B

__global__ void __launch_bounds__(256)
hmma_gemm(const bf16* __restrict__ Ahi, const bf16* __restrict__ Alo,
          const bf16* __restrict__ Bhi, const bf16* __restrict__ Blo,
          float* __restrict__ C, int K, int lda, int ldb, int ldc) {
    extern __shared__ char smem[];
    const uint32_t sb = smem_u32(smem);
    const int tid = threadIdx.x, wid = tid >> 5, lane = tid & 31;
    const int rowBase = blockIdx.y * 128, colBase = blockIdx.x * 128;
    const int wm = (wid & 3) * 32, wn = (wid >> 2) * 64;
    const int lrow = lane & 15, lch = lane >> 4;
    const int nk = K >> 6;

    float acc[2][8][4];
#pragma unroll
    for (int i = 0; i < 2; i++)
#pragma unroll
        for (int j = 0; j < 8; j++)
#pragma unroll
            for (int q = 0; q < 4; q++) acc[i][j][q] = 0.f;

    auto stage = [&](int buf, int kc) {
        uint32_t base = sb + buf * (4 * TILEB);
        for (int idx = tid; idx < 1024; idx += 256) {
            int row = idx >> 3, ch = idx & 7;
            uint32_t off = (uint32_t)(row * APITCH + ch * 8) * 2;
            cp16(base + off, Ahi + (size_t)(rowBase + row) * lda + kc + ch * 8);
            cp16(base + TILEB + off, Alo + (size_t)(rowBase + row) * lda + kc + ch * 8);
            cp16(base + 2 * TILEB + off, Bhi + (size_t)(colBase + row) * ldb + kc + ch * 8);
            cp16(base + 3 * TILEB + off, Blo + (size_t)(colBase + row) * ldb + kc + ch * 8);
        }
        asm volatile("cp.async.commit_group;" ::: "memory");
    };

    stage(0, 0);
    for (int t = 0; t < nk; ++t) {
        asm volatile("cp.async.wait_group 0;" ::: "memory");
        __syncthreads();
        if (t + 1 < nk) stage((t + 1) & 1, (t + 1) * 64);
        const uint32_t base = sb + (t & 1) * (4 * TILEB);
        const uint32_t bAhi = base, bAlo = base + TILEB;
        const uint32_t bBhi = base + 2 * TILEB, bBlo = base + 3 * TILEB;
#pragma unroll
        for (int ks = 0; ks < 4; ks++) {
            uint32_t afh[2][4], afl[2][4];
#pragma unroll
            for (int i = 0; i < 2; i++) {
                uint32_t ao = ((wm + i * 16 + lrow) * APITCH) * 2 + (ks * 2 + lch) * 16;
                ldm_x4(afh[i], bAhi + ao);
                ldm_x4(afl[i], bAlo + ao);
            }
            uint32_t bfh[8][2], bfl[8][2];
#pragma unroll
            for (int jj = 0; jj < 4; jj++) {
                uint32_t bo = ((wn + jj * 16 + lrow) * APITCH) * 2 + (ks * 2 + lch) * 16;
                uint32_t r[4];
                ldm_x4(r, bBhi + bo);
                bfh[2 * jj][0] = r[0]; bfh[2 * jj][1] = r[2];
                bfh[2 * jj + 1][0] = r[1]; bfh[2 * jj + 1][1] = r[3];
                ldm_x4(r, bBlo + bo);
                bfl[2 * jj][0] = r[0]; bfl[2 * jj][1] = r[2];
                bfl[2 * jj + 1][0] = r[1]; bfl[2 * jj + 1][1] = r[3];
            }
#pragma unroll
            for (int i = 0; i < 2; i++)
#pragma unroll
                for (int j = 0; j < 8; j++) {
                    mma_bf16(acc[i][j], afh[i], bfh[j][0], bfh[j][1]);
                    mma_bf16(acc[i][j], afh[i], bfl[j][0], bfl[j][1]);
                    mma_bf16(acc[i][j], afl[i], bfh[j][0], bfh[j][1]);
                }
        }
        __syncthreads();
    }

    const int rr = lane >> 2, cc = (lane & 3) * 2;
#pragma unroll
    for (int i = 0; i < 2; i++) {
        int gr = rowBase + wm + i * 16 + rr;
        float* out0 = C + (size_t)gr * ldc + colBase + wn + cc;
        float* out1 = out0 + 8 * ldc;
#pragma unroll
        for (int j = 0; j < 8; j++) {
            *(float2*)(out0 + j * 8) = make_float2(acc[i][j][0], acc[i][j][1]);
            *(float2*)(out1 + j * 8) = make_float2(acc[i][j][2], acc[i][j][3]);
        }
    }
}

// ================= a_hat HMMA (128x128, K=64) =================
#define AHAT_SMEM (4 * TILEB)

__global__ void __launch_bounds__(256)
ahat_hmma(const bf16* __restrict__ hi, const bf16* __restrict__ lo, float* __restrict__ C) {
    extern __shared__ char smem[];
    bf16* sAhi = (bf16*)(smem);
    bf16* sAlo = (bf16*)(smem + TILEB);
    bf16* sBhi = (bf16*)(smem + 2 * TILEB);
    bf16* sBlo = (bf16*)(smem + 3 * TILEB);
    const int tid = threadIdx.x, wid = tid >> 5, lane = tid & 31;
    const int rowBase = blockIdx.y * 128, colBase = blockIdx.x * 128;

    for (int idx = tid; idx < 128 * 8; idx += 256) {
        int row = idx >> 3, ch = idx & 7;
        int off = row * APITCH + ch * 8;
        *(uint4*)(sAhi + off) = *((const uint4*)(hi + (size_t)(rowBase + row) * 64) + ch);
        *(uint4*)(sAlo + off) = *((const uint4*)(lo + (size_t)(rowBase + row) * 64) + ch);
        *(uint4*)(sBhi + off) = *((const uint4*)(hi + (size_t)(colBase + row) * 64) + ch);
        *(uint4*)(sBlo + off) = *((const uint4*)(lo + (size_t)(colBase + row) * 64) + ch);
    }
    __syncthreads();

    const int wm = (wid & 3) * 32, wn = (wid >> 2) * 64;
    float acc[2][8][4];
#pragma unroll
    for (int i = 0; i < 2; i++)
#pragma unroll
        for (int j = 0; j < 8; j++)
#pragma unroll
            for (int q = 0; q < 4; q++) acc[i][j][q] = 0.f;

    const int lrow = lane & 15, lch = lane >> 4;
    const uint32_t sbAhi = smem_u32(sAhi), sbAlo = smem_u32(sAlo);
    const uint32_t sbBhi = smem_u32(sBhi), sbBlo = smem_u32(sBlo);

#pragma unroll
    for (int pass = 0; pass < 3; pass++) {
        const uint32_t aBase = (pass == 2) ? sbAlo : sbAhi;
        const uint32_t bBase = (pass == 1) ? sbBlo : sbBhi;
#pragma unroll
        for (int ks = 0; ks < 4; ks++) {
            uint32_t af[2][4];
#pragma unroll
            for (int i = 0; i < 2; i++)
                ldm_x4(af[i], aBase + ((wm + i * 16 + lrow) * APITCH) * 2 + (ks * 2 + lch) * 16);
            uint32_t bf[8][2];
#pragma unroll
            for (int jj = 0; jj < 4; jj++) {
                uint32_t r[4];
                ldm_x4(r, bBase + ((wn + jj * 16 + lrow) * APITCH) * 2 + (ks * 2 + lch) * 16);
                bf[2 * jj][0] = r[0]; bf[2 * jj][1] = r[2];
                bf[2 * jj + 1][0] = r[1]; bf[2 * jj + 1][1] = r[3];
            }
#pragma unroll
            for (int i = 0; i < 2; i++)
#pragma unroll
                for (int j = 0; j < 8; j++)
                    mma_bf16(acc[i][j], af[i], bf[j][0], bf[j][1]);
        }
    }

    const int rr = lane >> 2, cc = (lane & 3) * 2;
#pragma unroll
    for (int i = 0; i < 2; i++) {
        int gr = rowBase + wm + i * 16 + rr;
        float* out0 = C + (size_t)gr * NN + colBase + wn + cc;
        float* out1 = out0 + 8 * NN;
#pragma unroll
        for (int j = 0; j < 8; j++) {
            *(float2*)(out0 + j * 8) = make_float2(acc[i][j][0], acc[i][j][1]);
            *(float2*)(out1 + j * 8) = make_float2(acc[i][j][2], acc[i][j][3]);
        }
    }
}

// ================= fused decoder HMMA (2 heads + bias + lrelu + mean) =================
#define DEC_SMEM (2 * TILEB + TILEB)

__global__ void __launch_bounds__(256)
dec_hmma(const bf16* __restrict__ Ahi, const bf16* __restrict__ Alo,
         const bf16* __restrict__ Bhi, const bf16* __restrict__ Blo,
         const float* __restrict__ b3, float* __restrict__ xhat) {
    extern __shared__ char smem[];
    bf16* sAhi = (bf16*)smem;
    bf16* sAlo = (bf16*)(smem + TILEB);
    bf16* sBhi = (bf16*)(smem + 2 * TILEB);
    bf16* sBlo = (bf16*)(smem + 2 * TILEB + TILEB / 2);
    const int tid = threadIdx.x, wid = tid >> 5, lane = tid & 31;
    const int rowBase = blockIdx.y * 128, colBase = blockIdx.x * 64;
    const int wm = (wid & 3) * 32, wn = (wid >> 2) * 32;
    const int lrow = lane & 15, lch = lane >> 4;

    float acc[2][2][4][4];
#pragma unroll
    for (int h = 0; h < 2; h++)
#pragma unroll
        for (int i = 0; i < 2; i++)
#pragma unroll
            for (int j = 0; j < 4; j++)
#pragma unroll
                for (int q = 0; q < 4; q++) acc[h][i][j][q] = 0.f;

    const uint32_t sbAhi = smem_u32(sAhi), sbAlo = smem_u32(sAlo);
    const uint32_t sbBhi = smem_u32(sBhi), sbBlo = smem_u32(sBlo);

#pragma unroll
    for (int h = 0; h < 2; h++) {
        const bf16* ahp = Ahi + (size_t)h * NN * 64;
        const bf16* alp = Alo + (size_t)h * NN * 64;
        const bf16* bhp = Bhi + (size_t)h * NDEC * 64;
        const bf16* blp = Blo + (size_t)h * NDEC * 64;
        __syncthreads();
        for (int idx = tid; idx < 1024; idx += 256) {
            int row = idx >> 3, ch = idx & 7;
            int off = row * APITCH + ch * 8;
            *(uint4*)(sAhi + off) = *(const uint4*)(ahp + (size_t)(rowBase + row) * 64 + ch * 8);
            *(uint4*)(sAlo + off) = *(const uint4*)(alp + (size_t)(rowBase + row) * 64 + ch * 8);
        }
        for (int idx = tid; idx < 512; idx += 256) {
            int row = idx >> 3, ch = idx & 7;
            int off = row * APITCH + ch * 8;
            *(uint4*)(sBhi + off) = *(const uint4*)(bhp + (size_t)(colBase + row) * 64 + ch * 8);
            *(uint4*)(sBlo + off) = *(const uint4*)(blp + (size_t)(colBase + row) * 64 + ch * 8);
        }
        __syncthreads();
#pragma unroll
        for (int ks = 0; ks < 4; ks++) {
            uint32_t afh[2][4], afl[2][4];
#pragma unroll
            for (int i = 0; i < 2; i++) {
                uint32_t ao = ((wm + i * 16 + lrow) * APITCH) * 2 + (ks * 2 + lch) * 16;
                ldm_x4(afh[i], sbAhi + ao);
                ldm_x4(afl[i], sbAlo + ao);
            }
            uint32_t bfh[4][2], bfl[4][2];
#pragma unroll
            for (int jj = 0; jj < 2; jj++) {
                uint32_t bo = ((wn + jj * 16 + lrow) * APITCH) * 2 + (ks * 2 + lch) * 16;
                uint32_t r[4];
                ldm_x4(r, sbBhi + bo);
                bfh[2 * jj][0] = r[0]; bfh[2 * jj][1] = r[2];
                bfh[2 * jj + 1][0] = r[1]; bfh[2 * jj + 1][1] = r[3];
                ldm_x4(r, sbBlo + bo);
                bfl[2 * jj][0] = r[0]; bfl[2 * jj][1] = r[2];
                bfl[2 * jj + 1][0] = r[1]; bfl[2 * jj + 1][1] = r[3];
            }
#pragma unroll
            for (int i = 0; i < 2; i++)
#pragma unroll
                for (int j = 0; j < 4; j++) {
                    mma_bf16(acc[h][i][j], afh[i], bfh[j][0], bfh[j][1]);
                    mma_bf16(acc[h][i][j], afh[i], bfl[j][0], bfl[j][1]);
                    mma_bf16(acc[h][i][j], afl[i], bfh[j][0], bfh[j][1]);
                }
        }
    }

    const int rr = lane >> 2, cc = (lane & 3) * 2;
#pragma unroll
    for (int i = 0; i < 2; i++) {
#pragma unroll
        for (int j = 0; j < 4; j++) {
#pragma unroll
            for (int half = 0; half < 2; half++) {
                int gr = rowBase + wm + i * 16 + rr + half * 8;
                int gn = colBase + wn + j * 8 + cc;
                if (gn < FIN) {
                    float v0 = acc[0][i][j][half * 2], v1 = acc[1][i][j][half * 2];
                    xhat[(size_t)gr * FIN + gn] =
                        0.5f * (lrelu(v0 + b3[gn], 0.01f) + lrelu(v1 + b3[FIN + gn], 0.01f));
                }
                if (gn + 1 < FIN) {
                    float v0 = acc[0][i][j][half * 2 + 1], v1 = acc[1][i][j][half * 2 + 1];
                    xhat[(size_t)gr * FIN + gn + 1] =
                        0.5f * (lrelu(v0 + b3[gn + 1], 0.01f) + lrelu(v1 + b3[FIN + gn + 1], 0.01f));
                }
            }
        }
    }
}

// ================= CSR build =================
__global__ void k_zerodeg(int* deg) {
    int i = blockIdx.x * blockDim.x + threadIdx.x;
    if (i < NN) deg[i] = 0;
}
__global__ void k_deg(const int* __restrict__ dst, int* deg, int E) {
    int e = blockIdx.x * blockDim.x + threadIdx.x;
    if (e < E) atomicAdd(&deg[dst[e]], 1);
}
__global__ void k_scan(const int* __restrict__ deg, int* rowptr, int* cursor) {
    __shared__ int partx[257];
    int t = threadIdx.x;
    int base = t * 32;
    int loc[32];
    int s = 0;
#pragma unroll
    for (int i = 0; i < 32; i++) { loc[i] = s; s += deg[base + i]; }
    __shared__ int part[256];
    part[t] = s;
    __syncthreads();
    if (t == 0) {
        int acc = 0;
        for (int i = 0; i < 256; i++) { partx[i] = acc; acc += part[i]; }
        partx[256] = acc;
    }
    __syncthreads();
    int off = partx[t];
#pragma unroll
    for (int i = 0; i < 32; i++) {
        int v = off + loc[i];
        rowptr[base + i] = v;
        cursor[base + i] = v;
    }
    if (t == 0) rowptr[NN] = partx[256];
}
__global__ void k_scatter(const int* __restrict__ src, const int* __restrict__ dst,
                          int* cursor, int* csrsrc, int E) {
    int e = blockIdx.x * blockDim.x + threadIdx.x;
    if (e >= E) return;
    int d = dst[e];
    int idx = atomicAdd(&cursor[d], 1);
    csrsrc[idx] = src[e];
}

// ================= pack kernels =================
__global__ void k_pack_feat(const float* __restrict__ feat, bf16* __restrict__ fhi,
                            bf16* __restrict__ flo) {
    int n = blockIdx.x;
    for (int f = threadIdx.x; f < FINB; f += blockDim.x) {
        float v = (f < FIN) ? feat[(size_t)n * FIN + f] : 0.f;
        split_bf16(v, &fhi[(size_t)n * FINB + f], &flo[(size_t)n * FINB + f]);
    }
}
__global__ void k_pack_w1t(const float* __restrict__ W1, bf16* __restrict__ whi,
                           bf16* __restrict__ wlo) {
    int n = blockIdx.x;  // 256
    for (int k = threadIdx.x; k < FINB; k += blockDim.x) {
        float v = (k < FIN) ? W1[(size_t)k * 256 + n] : 0.f;
        split_bf16(v, &whi[(size_t)n * FINB + k], &wlo[(size_t)n * FINB + k]);
    }
}
__global__ void k_pack_w2t(const float* __restrict__ W2, bf16* __restrict__ whi,
                           bf16* __restrict__ wlo) {
    int n = blockIdx.x;  // 128
    for (int k = threadIdx.x; k < 256; k += blockDim.x) {
        float v = W2[(size_t)k * 128 + n];
        split_bf16(v, &whi[(size_t)n * 256 + k], &wlo[(size_t)n * 256 + k]);
    }
}
__global__ void k_pack_w3t(const float* __restrict__ W3, bf16* __restrict__ whi,
                           bf16* __restrict__ wlo) {
    int f = blockIdx.x;  // NDEC
    int k = threadIdx.x; // 64
#pragma unroll
    for (int h = 0; h < 2; h++) {
        float v = (f < FIN) ? W3[(size_t)k * (2 * FIN) + h * FIN + f] : 0.f;
        split_bf16(v, &whi[((size_t)h * NDEC + f) * 64 + k], &wlo[((size_t)h * NDEC + f) * 64 + k]);
    }
}

// ================= attention projections =================
// layer-1 logits from h1p (R8-proven path)
__global__ void k_elr(const float* __restrict__ hp, const float* __restrict__ al,
                      const float* __restrict__ ar, float* el, float* er, int D) {
    int w = (blockIdx.x * blockDim.x + threadIdx.x) >> 5;
    int lane = threadIdx.x & 31;
    if (w >= NN * 2) return;
    int n = w >> 1, h = w & 1;
    const float* row = hp + (size_t)n * (2 * D) + h * D;
    const float* a = al + h * D;
    const float* b = ar + h * D;
    float sl = 0.f, sr = 0.f;
    for (int d = lane; d < D; d += 32) { float x = row[d]; sl += x * a[d]; sr += x * b[d]; }
#pragma unroll
    for (int o = 16; o; o >>= 1) {
        sl += __shfl_down_sync(0xffffffffu, sl, o);
        sr += __shfl_down_sync(0xffffffffu, sr, o);
    }
    if (lane == 0) { el[w] = sl; er[w] = sr; }
}
// layer-2: u2[q][t], t<256 (for fused el2 epilogue in k_agg1)
__global__ void k_uv2(const float* __restrict__ W2, const float* __restrict__ al2,
                      const float* __restrict__ ar2, float* __restrict__ u2) {
    int w = (blockIdx.x * blockDim.x + threadIdx.x) >> 5;
    int lane = threadIdx.x & 31;
    if (w >= 256) return;
    const float* Wr = W2 + (size_t)w * 128;
    float a0 = 0.f, a1 = 0.f, r0 = 0.f, r1 = 0.f;
#pragma unroll
    for (int j = lane; j < 64; j += 32) {
        float w0 = Wr[j], w1 = Wr[64 + j];
        a0 += w0 * al2[j]; a1 += w1 * al2[64 + j];
        r0 += w0 * ar2[j]; r1 += w1 * ar2[64 + j];
    }
#pragma unroll
    for (int o = 16; o; o >>= 1) {
        a0 += __shfl_down_sync(0xffffffffu, a0, o);
        a1 += __shfl_down_sync(0xffffffffu, a1, o);
        r0 += __shfl_down_sync(0xffffffffu, r0, o);
        r1 += __shfl_down_sync(0xffffffffu, r1, o);
    }
    if (lane == 0) { u2[w] = a0; u2[256 + w] = a1; u2[512 + w] = r0; u2[768 + w] = r1; }
}
// layer-3 projection (for fused el3 epilogue in k_agg2)
__global__ void k_uv(const float* __restrict__ W3, const float* __restrict__ al3,
                     const float* __restrict__ ar3, float* uv) {
    int w = (blockIdx.x * blockDim.x + threadIdx.x) >> 5;
    int lane = threadIdx.x & 31;
    if (w >= 128) return;
    int h = w >> 6, k = w & 63;
    const float* Wr = W3 + (size_t)k * (2 * FIN) + h * FIN;
    const float* a = al3 + (size_t)h * FIN;
    const float* b = ar3 + (size_t)h * FIN;
    float su = 0.f, sv = 0.f;
    for (int f = lane; f < FIN; f += 32) { float ww = Wr[f]; su += ww * a[f]; sv += ww * b[f]; }
#pragma unroll
    for (int o = 16; o; o >>= 1) {
        su += __shfl_down_sync(0xffffffffu, su, o);
        sv += __shfl_down_sync(0xffffffffu, sv, o);
    }
    if (lane == 0) { uv[h * 64 + k] = su; uv[128 + h * 64 + k] = sv; }
}

// ================= block softmax-sum helper =================
template <int NT>
__device__ __forceinline__ float2 block_inv_sum(const int* csrsrc, int b, int en,
                                                const float* el, float2 r,
                                                float* red, float2* out_sh) {
    int t = threadIdx.x, lane = t & 31, wid = t >> 5;
    float p0 = 0.f, p1 = 0.f;
    for (int i = b + t; i < en; i += NT) {
        int s = csrsrc[i];
        float2 l = *(const float2*)&el[s * 2];
        float e0 = l.x + r.x; e0 = e0 > 0.f ? e0 : 0.2f * e0;
        float e1 = l.y + r.y; e1 = e1 > 0.f ? e1 : 0.2f * e1;
        p0 += __expf(e0); p1 += __expf(e1);
    }
#pragma unroll
    for (int o = 16; o; o >>= 1) {
        p0 += __shfl_down_sync(0xffffffffu, p0, o);
        p1 += __shfl_down_sync(0xffffffffu, p1, o);
    }
    if (lane == 0) { red[wid * 2] = p0; red[wid * 2 + 1] = p1; }
    __syncthreads();
    if (t == 0) {
        float s0 = 0.f, s1 = 0.f;
        for (int w = 0; w < NT / 32; w++) { s0 += red[w * 2]; s1 += red[w * 2 + 1]; }
        *out_sh = make_float2(1.f / s0, 1.f / s1);
    }
    __syncthreads();
    return *out_sh;
}

// ================= CSR gather aggregation =================
// layer1 + fused el2/er2 epilogue
__global__ void __launch_bounds__(256)
k_agg1(const int* __restrict__ rowptr, const int* __restrict__ csrsrc,
       const float* __restrict__ el, const float* __restrict__ er,
       const float* __restrict__ hp, const float* __restrict__ b1,
       const float* __restrict__ u2,
       bf16* __restrict__ ohi, bf16* __restrict__ olo,
       float* __restrict__ el2, float* __restrict__ er2) {
    int d = blockIdx.x;
    int t = threadIdx.x, lane = t & 31, warp = t >> 5;
    __shared__ float2 sal[128];
    __shared__ int ssrc[128];
    __shared__ float red[16];
    __shared__ float2 inv_sh;
    __shared__ float redq[8][4];
    int b = rowptr[d], en = rowptr[d + 1];
    float2 r = *(const float2*)&er[d * 2];
    float2 inv = block_inv_sum<256>(csrsrc, b, en, el, r, red, &inv_sh);
    float acc = 0.f;
    int h = t >> 7;
    for (int c = b; c < en; c += 128) {
        int cnt = min(128, en - c);
        __syncthreads();
        if (t < cnt) {
            int s = csrsrc[c + t];
            float2 l = *(const float2*)&el[s * 2];
            float e0 = l.x + r.x; e0 = e0 > 0.f ? e0 : 0.2f * e0;
            float e1 = l.y + r.y; e1 = e1 > 0.f ? e1 : 0.2f * e1;
            sal[t] = make_float2(__expf(e0) * inv.x, __expf(e1) * inv.y);
            ssrc[t] = s;
        }
        __syncthreads();
#pragma unroll 4
        for (int i = 0; i < cnt; i++) {
            float a = h ? sal[i].y : sal[i].x;
            acc = fmaf(a, hp[(size_t)ssrc[i] * 256 + t], acc);
        }
    }
    float x = lrelu(acc + b1[t], 0.01f);
    split_bf16(x, &ohi[(size_t)d * 256 + t], &olo[(size_t)d * 256 + t]);
    // fused el2/er2
    float c0 = x * u2[t], c1 = x * u2[256 + t], c2 = x * u2[512 + t], c3 = x * u2[768 + t];
#pragma unroll
    for (int o = 16; o; o >>= 1) {
        c0 += __shfl_down_sync(0xffffffffu, c0, o);
        c1 += __shfl_down_sync(0xffffffffu, c1, o);
        c2 += __shfl_down_sync(0xffffffffu, c2, o);
        c3 += __shfl_down_sync(0xffffffffu, c3, o);
    }
    if (lane == 0) { redq[warp][0] = c0; redq[warp][1] = c1; redq[warp][2] = c2; redq[warp][3] = c3; }
    __syncthreads();
    if (t == 0) {
        float s0 = 0.f, s1 = 0.f, s2 = 0.f, s3 = 0.f;
        for (int w = 0; w < 8; w++) { s0 += redq[w][0]; s1 += redq[w][1]; s2 += redq[w][2]; s3 += redq[w][3]; }
        el2[d * 2] = s0; el2[d * 2 + 1] = s1;
        er2[d * 2] = s2; er2[d * 2 + 1] = s3;
    }
}

// layer2 + fused el3/er3 epilogue
__global__ void __launch_bounds__(128)
k_agg2(const int* __restrict__ rowptr, const int* __restrict__ csrsrc,
       const float* __restrict__ el, const float* __restrict__ er,
       const float* __restrict__ hp, const float* __restrict__ b2,
       const float* __restrict__ uv,
       float* __restrict__ h2, bf16* __restrict__ h2hi, bf16* __restrict__ h2lo,
       float* __restrict__ el3, float* __restrict__ er3) {
    int d = blockIdx.x;
    int t = threadIdx.x, lane = t & 31, warp = t >> 5;
    __shared__ float2 sal[128];
    __shared__ int ssrc[128];
    __shared__ float o[128];
    __shared__ float red[8];
    __shared__ float2 inv_sh;
    __shared__ float redq[4][4];
    int b = rowptr[d], en = rowptr[d + 1];
    float2 r = *(const float2*)&er[d * 2];
    float2 inv = block_inv_sum<128>(csrsrc, b, en, el, r, red, &inv_sh);
    float acc = 0.f;
    int h = t >> 6;
    for (int c = b; c < en; c += 128) {
        int cnt = min(128, en - c);
        __syncthreads();
        if (t < cnt) {
            int s = csrsrc[c + t];
            float2 l = *(const float2*)&el[s * 2];
            float e0 = l.x + r.x; e0 = e0 > 0.f ? e0 : 0.2f * e0;
            float e1 = l.y + r.y; e1 = e1 > 0.f ? e1 : 0.2f * e1;
            sal[t] = make_float2(__expf(e0) * inv.x, __expf(e1) * inv.y);
            ssrc[t] = s;
        }
        __syncthreads();
#pragma unroll 4
        for (int i = 0; i < cnt; i++) {
            float a = h ? sal[i].y : sal[i].x;
            acc = fmaf(a, hp[(size_t)ssrc[i] * 128 + t], acc);
        }
    }
    o[t] = acc;
    __syncthreads();
    float v = 0.f;
    if (t < 64) {
        float x0 = lrelu(o[t] + b2[t], 0.01f);
        float x1 = lrelu(o[64 + t] + b2[64 + t], 0.01f);
        v = 0.5f * (x0 + x1);
        h2[(size_t)d * 64 + t] = v;
        split_bf16(v, &h2hi[(size_t)d * 64 + t], &h2lo[(size_t)d * 64 + t]);
    }
    // fused el3/er3
    float c0 = 0.f, c1 = 0.f, c2 = 0.f, c3 = 0.f;
    if (t < 64) {
        c0 = v * uv[t]; c1 = v * uv[64 + t]; c2 = v * uv[128 + t]; c3 = v * uv[192 + t];
    }
#pragma unroll
    for (int o2 = 16; o2; o2 >>= 1) {
        c0 += __shfl_down_sync(0xffffffffu, c0, o2);
        c1 += __shfl_down_sync(0xffffffffu, c1, o2);
        c2 += __shfl_down_sync(0xffffffffu, c2, o2);
        c3 += __shfl_down_sync(0xffffffffu, c3, o2);
    }
    if (lane == 0) { redq[warp][0] = c0; redq[warp][1] = c1; redq[warp][2] = c2; redq[warp][3] = c3; }
    __syncthreads();
    if (t == 0) {
        el3[d * 2] = redq[0][0] + redq[1][0];
        el3[d * 2 + 1] = redq[0][1] + redq[1][1];
        er3[d * 2] = redq[0][2] + redq[1][2];
        er3[d * 2 + 1] = redq[0][3] + redq[1][3];
    }
}

__global__ void __launch_bounds__(128)
k_agg3(const int* __restrict__ rowptr, const int* __restrict__ csrsrc,
       const float* __restrict__ el, const float* __restrict__ er,
       const float* __restrict__ h2, bf16* __restrict__ ahi, bf16* __restrict__ alo) {
    int d = blockIdx.x;
    int t = threadIdx.x;
    __shared__ float2 sal[128];
    __shared__ int ssrc[128];
    __shared__ float red[8];
    __shared__ float2 inv_sh;
    int b = rowptr[d], en = rowptr[d + 1];
    float2 r = *(const float2*)&er[d * 2];
    float2 inv = block_inv_sum<128>(csrsrc, b, en, el, r, red, &inv_sh);
    float acc = 0.f;
    int h = t >> 6, dd = t & 63;
    for (int c = b; c < en; c += 128) {
        int cnt = min(128, en - c);
        __syncthreads();
        if (t < cnt) {
            int s = csrsrc[c + t];
            float2 l = *(const float2*)&el[s * 2];
            float e0 = l.x + r.x; e0 = e0 > 0.f ? e0 : 0.2f * e0;
            float e1 = l.y + r.y; e1 = e1 > 0.f ? e1 : 0.2f * e1;
            sal[t] = make_float2(__expf(e0) * inv.x, __expf(e1) * inv.y);
            ssrc[t] = s;
        }
        __syncthreads();
#pragma unroll 4
        for (int i = 0; i < cnt; i++) {
            float a = h ? sal[i].y : sal[i].x;
            acc = fmaf(a, h2[(size_t)ssrc[i] * 64 + dd], acc);
        }
    }
    size_t idx = ((size_t)h * NN + d) * 64 + dd;
    split_bf16(acc, &ahi[idx], &alo[idx]);
}

// ================= launch =================
extern "C" void kernel_launch(void* const* d_in, const int* in_sizes, int n_in,
                              void* d_out, int out_size) {
    const float* feat = (const float*)d_in[0];
    const int* src = (const int*)d_in[1];
    const int* dst = (const int*)d_in[2];
    const float* W1 = (const float*)d_in[3];
    const float* al1 = (const float*)d_in[4];
    const float* ar1 = (const float*)d_in[5];
    const float* b1 = (const float*)d_in[6];
    const float* W2 = (const float*)d_in[7];
    const float* al2 = (const float*)d_in[8];
    const float* ar2 = (const float*)d_in[9];
    const float* b2 = (const float*)d_in[10];
    const float* W3 = (const float*)d_in[11];
    const float* al3 = (const float*)d_in[12];
    const float* ar3 = (const float*)d_in[13];
    const float* b3 = (const float*)d_in[14];

    float* a_hat = (float*)d_out;
    float* x_hat = a_hat + (size_t)NN * NN;
    const int E = in_sizes[1];

    bf16 *feathi, *featlo, *w1thi, *w1tlo, *w2thi, *w2tlo, *w3thi, *w3tlo;
    bf16 *agg1hi, *agg1lo, *h2hi, *h2lo, *agg3hi, *agg3lo;
    float *h1p, *h2p, *h2, *el, *er, *uv, *u2;
    int *deg, *cursor, *rowptr, *csrsrc;
    cudaGetSymbolAddress((void**)&feathi, g_feathi);
    cudaGetSymbolAddress((void**)&featlo, g_featlo);
    cudaGetSymbolAddress((void**)&w1thi, g_w1thi);
    cudaGetSymbolAddress((void**)&w1tlo, g_w1tlo);
    cudaGetSymbolAddress((void**)&w2thi, g_w2thi);
    cudaGetSymbolAddress((void**)&w2tlo, g_w2tlo);
    cudaGetSymbolAddress((void**)&w3thi, g_w3thi);
    cudaGetSymbolAddress((void**)&w3tlo, g_w3tlo);
    cudaGetSymbolAddress((void**)&h1p, g_h1p);
    cudaGetSymbolAddress((void**)&agg1hi, g_agg1hi);
    cudaGetSymbolAddress((void**)&agg1lo, g_agg1lo);
    cudaGetSymbolAddress((void**)&h2p, g_h2p);
    cudaGetSymbolAddress((void**)&h2, g_h2);
    cudaGetSymbolAddress((void**)&h2hi, g_h2hi);
    cudaGetSymbolAddress((void**)&h2lo, g_h2lo);
    cudaGetSymbolAddress((void**)&agg3hi, g_agg3hi);
    cudaGetSymbolAddress((void**)&agg3lo, g_agg3lo);
    cudaGetSymbolAddress((void**)&el, g_el);
    cudaGetSymbolAddress((void**)&er, g_er);
    cudaGetSymbolAddress((void**)&uv, g_uv);
    cudaGetSymbolAddress((void**)&u2, g_u2);
    cudaGetSymbolAddress((void**)&deg, g_deg);
    cudaGetSymbolAddress((void**)&cursor, g_cursor);
    cudaGetSymbolAddress((void**)&rowptr, g_rowptr);
    cudaGetSymbolAddress((void**)&csrsrc, g_csrsrc);

    cudaFuncSetAttribute(ahat_hmma, cudaFuncAttributeMaxDynamicSharedMemorySize, AHAT_SMEM);
    cudaFuncSetAttribute(hmma_gemm, cudaFuncAttributeMaxDynamicSharedMemorySize, HG_SMEM);
    cudaFuncSetAttribute(dec_hmma, cudaFuncAttributeMaxDynamicSharedMemorySize, DEC_SMEM);

    static cudaStream_t s1 = nullptr, s2 = nullptr;
    static cudaEvent_t evRoot, evCSR, evW1, evPre, evW, evH2, evAhat;
    if (s1 == nullptr) {
        cudaStreamCreateWithFlags(&s1, cudaStreamNonBlocking);
        cudaStreamCreateWithFlags(&s2, cudaStreamNonBlocking);
        cudaEventCreateWithFlags(&evRoot, cudaEventDisableTiming);
        cudaEventCreateWithFlags(&evCSR, cudaEventDisableTiming);
        cudaEventCreateWithFlags(&evW1, cudaEventDisableTiming);
        cudaEventCreateWithFlags(&evPre, cudaEventDisableTiming);
        cudaEventCreateWithFlags(&evW, cudaEventDisableTiming);
        cudaEventCreateWithFlags(&evH2, cudaEventDisableTiming);
        cudaEventCreateWithFlags(&evAhat, cudaEventDisableTiming);
    }

    float *el1 = el, *el2 = el + NN * 2, *el3 = el + 2 * NN * 2;
    float *er1 = er, *er2 = er + NN * 2, *er3 = er + 2 * NN * 2;

    const int eb = (E + 255) / 256;

    // fork side streams
    cudaEventRecord(evRoot, 0);
    cudaStreamWaitEvent(s1, evRoot, 0);
    cudaStreamWaitEvent(s2, evRoot, 0);

    // ---- s1: CSR build (first needed at k_agg1) ----
    k_zerodeg<<<(NN + 255) / 256, 256, 0, s1>>>(deg);
    k_deg<<<eb, 256, 0, s1>>>(dst, deg, E);
    k_scan<<<1, 256, 0, s1>>>(deg, rowptr, cursor);
    k_scatter<<<eb, 256, 0, s1>>>(src, dst, cursor, csrsrc, E);
    cudaEventRecord(evCSR, s1);

    // ---- s2: weight packs + attention projections (small, weight-only reads) ----
    k_pack_w1t<<<256, 256, 0, s2>>>(W1, w1thi, w1tlo);
    cudaEventRecord(evW1, s2);
    k_uv2<<<32, 256, 0, s2>>>(W2, al2, ar2, u2);
    cudaEventRecord(evPre, s2);
    k_pack_w2t<<<128, 256, 0, s2>>>(W2, w2thi, w2tlo);
    k_pack_w3t<<<NDEC, 64, 0, s2>>>(W3, w3thi, w3tlo);
    k_uv<<<16, 256, 0, s2>>>(W3, al3, ar3, uv);
    cudaEventRecord(evW, s2);

    // ---- main stream: layer 1 (R8-proven path) ----
    k_pack_feat<<<NN, 256>>>(feat, feathi, featlo);
    cudaStreamWaitEvent(0, evW1, 0);
    {
        dim3 grid(2, 64);
        hmma_gemm<<<grid, 256, HG_SMEM>>>(feathi, featlo, w1thi, w1tlo, h1p, FINB, FINB, FINB, 256);
    }
    k_elr<<<(NN * 2 * 32 + 255) / 256, 256>>>(h1p, al1, ar1, el1, er1, 128);
    cudaStreamWaitEvent(0, evCSR, 0);
    cudaStreamWaitEvent(0, evPre, 0);
    k_agg1<<<NN, 256>>>(rowptr, csrsrc, el1, er1, h1p, b1, u2, agg1hi, agg1lo, el2, er2);

    // ---- layer 2 ----
    cudaStreamWaitEvent(0, evW, 0);
    {
        dim3 grid(1, 64);
        hmma_gemm<<<grid, 256, HG_SMEM>>>(agg1hi, agg1lo, w2thi, w2tlo, h2p, 256, 256, 256, 128);
    }
    k_agg2<<<NN, 128>>>(rowptr, csrsrc, el2, er2, h2p, b2, uv, h2, h2hi, h2lo, el3, er3);
    cudaEventRecord(evH2, 0);

    // ---- s1: structure decoder a_hat (overlaps attribute decoder) ----
    cudaStreamWaitEvent(s1, evH2, 0);
    {
        dim3 grid(NN / 128, NN / 128);
        ahat_hmma<<<grid, 256, AHAT_SMEM, s1>>>(h2hi, h2lo, a_hat);
    }
    cudaEventRecord(evAhat, s1);

    // ---- main stream: attribute decoder ----
    k_agg3<<<NN, 128>>>(rowptr, csrsrc, el3, er3, h2, agg3hi, agg3lo);
    {
        dim3 grid(NDEC / 64, NN / 128);
        dec_hmma<<<grid, 256, DEC_SMEM>>>(agg3hi, agg3lo, w3thi, w3tlo, b3, x_hat);
    }

    // join
    cudaStreamWaitEvent(0, evAhat, 0);
}

// round 12
// speedup vs baseline: 1.1094x; 1.0312x over previous
#include <cuda_runtime.h>
#include <cuda_bf16.h>
#include <cstdint>

#define NN 8192
#define FIN 1433
#define FINB 1472      // FIN padded to multiple of 64
#define NDEC 1536      // decoder N padded to multiple of 64
#define MAXE (1 << 20)

typedef unsigned long long u64t;
typedef __nv_bfloat16 bf16;

// ---------------- scratch (device globals) ----------------
__device__ bf16 g_feathi[NN * FINB];
__device__ bf16 g_featlo[NN * FINB];
__device__ bf16 g_w1thi[256 * FINB];
__device__ bf16 g_w1tlo[256 * FINB];
__device__ bf16 g_w2thi[128 * 256];
__device__ bf16 g_w2tlo[128 * 256];
__device__ bf16 g_w3thi[2 * NDEC * 64];
__device__ bf16 g_w3tlo[2 * NDEC * 64];
__device__ float g_h1p[NN * 256];
__device__ bf16 g_agg1hi[NN * 256];
__device__ bf16 g_agg1lo[NN * 256];
__device__ float g_h2p[NN * 128];
__device__ float g_h2[NN * 64];
__device__ bf16 g_h2hi[NN * 64];
__device__ bf16 g_h2lo[NN * 64];
__device__ bf16 g_agg3hi[2 * NN * 64];
__device__ bf16 g_agg3lo[2 * NN * 64];
__device__ float g_el[3 * NN * 2];
__device__ float g_er[3 * NN * 2];
__device__ float g_uv[2 * 64 * 2];
__device__ float g_u2[4 * 256];
__device__ int g_deg[NN];
__device__ int g_cursor[NN];
__device__ int g_rowptr[NN + 1];
__device__ int g_csrsrc[MAXE];

__device__ __forceinline__ float lrelu(float x, float a) { return x > 0.f ? x : a * x; }

__device__ __forceinline__ uint32_t smem_u32(const void* p) {
    uint32_t a;
    asm("{ .reg .u64 t; cvta.to.shared.u64 t, %1; cvt.u32.u64 %0, t; }" : "=r"(a) : "l"(p));
    return a;
}
__device__ __forceinline__ void ldm_x4(uint32_t* r, uint32_t addr) {
    asm volatile("ldmatrix.sync.aligned.m8n8.x4.shared.b16 {%0,%1,%2,%3}, [%4];"
                 : "=r"(r[0]), "=r"(r[1]), "=r"(r[2]), "=r"(r[3]) : "r"(addr));
}
__device__ __forceinline__ void mma_bf16(float* c, const uint32_t* a, uint32_t b0, uint32_t b1) {
    asm volatile(
        "mma.sync.aligned.m16n8k16.row.col.f32.bf16.bf16.f32 "
        "{%0,%1,%2,%3}, {%4,%5,%6,%7}, {%8,%9}, {%0,%1,%2,%3};"
        : "+f"(c[0]), "+f"(c[1]), "+f"(c[2]), "+f"(c[3])
        : "r"(a[0]), "r"(a[1]), "r"(a[2]), "r"(a[3]), "r"(b0), "r"(b1));
}
__device__ __forceinline__ void split_bf16(float v, bf16* hi, bf16* lo) {
    bf16 h = __float2bfloat16(v);
    *hi = h;
    *lo = __float2bfloat16(v - __bfloat162float(h));
}
__device__ __forceinline__ void cp16(uint32_t dst, const void* src) {
    asm volatile("cp.async.cg.shared.global [%0], [%1], 16;" :: "r"(dst), "l"(src));
}
__device__ __forceinline__ void st_cs_f2(float* p, float a, float b) {
    asm volatile("st.global.cs.v2.f32 [%0], {%1, %2};" :: "l"(p), "f"(a), "f"(b) : "memory");
}

#define APITCH 72    // bf16 per smem row (144B) — conflict-free ldmatrix
#define TILEB 18432  // one 128xAPITCH bf16 tile in bytes

// ================= generic bf16-split HMMA GEMM, cp.async double-buffered =================
#define HG_SMEM (8 * TILEB)  // 147456 B

__global__ void __launch_bounds__(256)
hmma_gemm(const bf16* __restrict__ Ahi, const bf16* __restrict__ Alo,
          const bf16* __restrict__ Bhi, const bf16* __restrict__ Blo,
          float* __restrict__ C, int K, int lda, int ldb, int ldc) {
    extern __shared__ char smem[];
    const uint32_t sb = smem_u32(smem);
    const int tid = threadIdx.x, wid = tid >> 5, lane = tid & 31;
    const int rowBase = blockIdx.y * 128, colBase = blockIdx.x * 128;
    const int wm = (wid & 3) * 32, wn = (wid >> 2) * 64;
    const int lrow = lane & 15, lch = lane >> 4;
    const int nk = K >> 6;

    float acc[2][8][4];
#pragma unroll
    for (int i = 0; i < 2; i++)
#pragma unroll
        for (int j = 0; j < 8; j++)
#pragma unroll
            for (int q = 0; q < 4; q++) acc[i][j][q] = 0.f;

    auto stage = [&](int buf, int kc) {
        uint32_t base = sb + buf * (4 * TILEB);
        for (int idx = tid; idx < 1024; idx += 256) {
            int row = idx >> 3, ch = idx & 7;
            uint32_t off = (uint32_t)(row * APITCH + ch * 8) * 2;
            cp16(base + off, Ahi + (size_t)(rowBase + row) * lda + kc + ch * 8);
            cp16(base + TILEB + off, Alo + (size_t)(rowBase + row) * lda + kc + ch * 8);
            cp16(base + 2 * TILEB + off, Bhi + (size_t)(colBase + row) * ldb + kc + ch * 8);
            cp16(base + 3 * TILEB + off, Blo + (size_t)(colBase + row) * ldb + kc + ch * 8);
        }
        asm volatile("cp.async.commit_group;" ::: "memory");
    };

    stage(0, 0);
    for (int t = 0; t < nk; ++t) {
        asm volatile("cp.async.wait_group 0;" ::: "memory");
        __syncthreads();
        if (t + 1 < nk) stage((t + 1) & 1, (t + 1) * 64);
        const uint32_t base = sb + (t & 1) * (4 * TILEB);
        const uint32_t bAhi = base, bAlo = base + TILEB;
        const uint32_t bBhi = base + 2 * TILEB, bBlo = base + 3 * TILEB;
#pragma unroll
        for (int ks = 0; ks < 4; ks++) {
            uint32_t afh[2][4], afl[2][4];
#pragma unroll
            for (int i = 0; i < 2; i++) {
                uint32_t ao = ((wm + i * 16 + lrow) * APITCH) * 2 + (ks * 2 + lch) * 16;
                ldm_x4(afh[i], bAhi + ao);
                ldm_x4(afl[i], bAlo + ao);
            }
            uint32_t bfh[8][2], bfl[8][2];
#pragma unroll
            for (int jj = 0; jj < 4; jj++) {
                uint32_t bo = ((wn + jj * 16 + lrow) * APITCH) * 2 + (ks * 2 + lch) * 16;
                uint32_t r[4];
                ldm_x4(r, bBhi + bo);
                bfh[2 * jj][0] = r[0]; bfh[2 * jj][1] = r[2];
                bfh[2 * jj + 1][0] = r[1]; bfh[2 * jj + 1][1] = r[3];
                ldm_x4(r, bBlo + bo);
                bfl[2 * jj][0] = r[0]; bfl[2 * jj][1] = r[2];
                bfl[2 * jj + 1][0] = r[1]; bfl[2 * jj + 1][1] = r[3];
            }
#pragma unroll
            for (int i = 0; i < 2; i++)
#pragma unroll
                for (int j = 0; j < 8; j++) {
                    mma_bf16(acc[i][j], afh[i], bfh[j][0], bfh[j][1]);
                    mma_bf16(acc[i][j], afh[i], bfl[j][0], bfl[j][1]);
                    mma_bf16(acc[i][j], afl[i], bfh[j][0], bfh[j][1]);
                }
        }
        __syncthreads();
    }

    const int rr = lane >> 2, cc = (lane & 3) * 2;
#pragma unroll
    for (int i = 0; i < 2; i++) {
        int gr = rowBase + wm + i * 16 + rr;
        float* out0 = C + (size_t)gr * ldc + colBase + wn + cc;
        float* out1 = out0 + 8 * ldc;
#pragma unroll
        for (int j = 0; j < 8; j++) {
            *(float2*)(out0 + j * 8) = make_float2(acc[i][j][0], acc[i][j][1]);
            *(float2*)(out1 + j * 8) = make_float2(acc[i][j][2], acc[i][j][3]);
        }
    }
}

// ================= a_hat HMMA (128x128, K=64), streaming stores =================
#define AHAT_SMEM (4 * TILEB)

__global__ void __launch_bounds__(256)
ahat_hmma(const bf16* __restrict__ hi, const bf16* __restrict__ lo, float* __restrict__ C) {
    extern __shared__ char smem[];
    bf16* sAhi = (bf16*)(smem);
    bf16* sAlo = (bf16*)(smem + TILEB);
    bf16* sBhi = (bf16*)(smem + 2 * TILEB);
    bf16* sBlo = (bf16*)(smem + 3 * TILEB);
    const int tid = threadIdx.x, wid = tid >> 5, lane = tid & 31;
    const int rowBase = blockIdx.y * 128, colBase = blockIdx.x * 128;

    for (int idx = tid; idx < 128 * 8; idx += 256) {
        int row = idx >> 3, ch = idx & 7;
        int off = row * APITCH + ch * 8;
        *(uint4*)(sAhi + off) = *((const uint4*)(hi + (size_t)(rowBase + row) * 64) + ch);
        *(uint4*)(sAlo + off) = *((const uint4*)(lo + (size_t)(rowBase + row) * 64) + ch);
        *(uint4*)(sBhi + off) = *((const uint4*)(hi + (size_t)(colBase + row) * 64) + ch);
        *(uint4*)(sBlo + off) = *((const uint4*)(lo + (size_t)(colBase + row) * 64) + ch);
    }
    __syncthreads();

    const int wm = (wid & 3) * 32, wn = (wid >> 2) * 64;
    float acc[2][8][4];
#pragma unroll
    for (int i = 0; i < 2; i++)
#pragma unroll
        for (int j = 0; j < 8; j++)
#pragma unroll
            for (int q = 0; q < 4; q++) acc[i][j][q] = 0.f;

    const int lrow = lane & 15, lch = lane >> 4;
    const uint32_t sbAhi = smem_u32(sAhi), sbAlo = smem_u32(sAlo);
    const uint32_t sbBhi = smem_u32(sBhi), sbBlo = smem_u32(sBlo);

#pragma unroll
    for (int pass = 0; pass < 3; pass++) {
        const uint32_t aBase = (pass == 2) ? sbAlo : sbAhi;
        const uint32_t bBase = (pass == 1) ? sbBlo : sbBhi;
#pragma unroll
        for (int ks = 0; ks < 4; ks++) {
            uint32_t af[2][4];
#pragma unroll
            for (int i = 0; i < 2; i++)
                ldm_x4(af[i], aBase + ((wm + i * 16 + lrow) * APITCH) * 2 + (ks * 2 + lch) * 16);
            uint32_t bf[8][2];
#pragma unroll
            for (int jj = 0; jj < 4; jj++) {
                uint32_t r[4];
                ldm_x4(r, bBase + ((wn + jj * 16 + lrow) * APITCH) * 2 + (ks * 2 + lch) * 16);
                bf[2 * jj][0] = r[0]; bf[2 * jj][1] = r[2];
                bf[2 * jj + 1][0] = r[1]; bf[2 * jj + 1][1] = r[3];
            }
#pragma unroll
            for (int i = 0; i < 2; i++)
#pragma unroll
                for (int j = 0; j < 8; j++)
                    mma_bf16(acc[i][j], af[i], bf[j][0], bf[j][1]);
        }
    }

    const int rr = lane >> 2, cc = (lane & 3) * 2;
#pragma unroll
    for (int i = 0; i < 2; i++) {
        int gr = rowBase + wm + i * 16 + rr;
        float* out0 = C + (size_t)gr * NN + colBase + wn + cc;
        float* out1 = out0 + 8 * NN;
#pragma unroll
        for (int j = 0; j < 8; j++) {
            st_cs_f2(out0 + j * 8, acc[i][j][0], acc[i][j][1]);
            st_cs_f2(out1 + j * 8, acc[i][j][2], acc[i][j][3]);
        }
    }
}

// ================= fused decoder HMMA (2 heads + bias + lrelu + mean) =================
#define DEC_SMEM (2 * TILEB + TILEB)

__global__ void __launch_bounds__(256)
dec_hmma(const bf16* __restrict__ Ahi, const bf16* __restrict__ Alo,
         const bf16* __restrict__ Bhi, const bf16* __restrict__ Blo,
         const float* __restrict__ b3, float* __restrict__ xhat) {
    extern __shared__ char smem[];
    bf16* sAhi = (bf16*)smem;
    bf16* sAlo = (bf16*)(smem + TILEB);
    bf16* sBhi = (bf16*)(smem + 2 * TILEB);
    bf16* sBlo = (bf16*)(smem + 2 * TILEB + TILEB / 2);
    const int tid = threadIdx.x, wid = tid >> 5, lane = tid & 31;
    const int rowBase = blockIdx.y * 128, colBase = blockIdx.x * 64;
    const int wm = (wid & 3) * 32, wn = (wid >> 2) * 32;
    const int lrow = lane & 15, lch = lane >> 4;

    float acc[2][2][4][4];
#pragma unroll
    for (int h = 0; h < 2; h++)
#pragma unroll
        for (int i = 0; i < 2; i++)
#pragma unroll
            for (int j = 0; j < 4; j++)
#pragma unroll
                for (int q = 0; q < 4; q++) acc[h][i][j][q] = 0.f;

    const uint32_t sbAhi = smem_u32(sAhi), sbAlo = smem_u32(sAlo);
    const uint32_t sbBhi = smem_u32(sBhi), sbBlo = smem_u32(sBlo);

#pragma unroll
    for (int h = 0; h < 2; h++) {
        const bf16* ahp = Ahi + (size_t)h * NN * 64;
        const bf16* alp = Alo + (size_t)h * NN * 64;
        const bf16* bhp = Bhi + (size_t)h * NDEC * 64;
        const bf16* blp = Blo + (size_t)h * NDEC * 64;
        __syncthreads();
        for (int idx = tid; idx < 1024; idx += 256) {
            int row = idx >> 3, ch = idx & 7;
            int off = row * APITCH + ch * 8;
            *(uint4*)(sAhi + off) = *(const uint4*)(ahp + (size_t)(rowBase + row) * 64 + ch * 8);
            *(uint4*)(sAlo + off) = *(const uint4*)(alp + (size_t)(rowBase + row) * 64 + ch * 8);
        }
        for (int idx = tid; idx < 512; idx += 256) {
            int row = idx >> 3, ch = idx & 7;
            int off = row * APITCH + ch * 8;
            *(uint4*)(sBhi + off) = *(const uint4*)(bhp + (size_t)(colBase + row) * 64 + ch * 8);
            *(uint4*)(sBlo + off) = *(const uint4*)(blp + (size_t)(colBase + row) * 64 + ch * 8);
        }
        __syncthreads();
#pragma unroll
        for (int ks = 0; ks < 4; ks++) {
            uint32_t afh[2][4], afl[2][4];
#pragma unroll
            for (int i = 0; i < 2; i++) {
                uint32_t ao = ((wm + i * 16 + lrow) * APITCH) * 2 + (ks * 2 + lch) * 16;
                ldm_x4(afh[i], sbAhi + ao);
                ldm_x4(afl[i], sbAlo + ao);
            }
            uint32_t bfh[4][2], bfl[4][2];
#pragma unroll
            for (int jj = 0; jj < 2; jj++) {
                uint32_t bo = ((wn + jj * 16 + lrow) * APITCH) * 2 + (ks * 2 + lch) * 16;
                uint32_t r[4];
                ldm_x4(r, sbBhi + bo);
                bfh[2 * jj][0] = r[0]; bfh[2 * jj][1] = r[2];
                bfh[2 * jj + 1][0] = r[1]; bfh[2 * jj + 1][1] = r[3];
                ldm_x4(r, sbBlo + bo);
                bfl[2 * jj][0] = r[0]; bfl[2 * jj][1] = r[2];
                bfl[2 * jj + 1][0] = r[1]; bfl[2 * jj + 1][1] = r[3];
            }
#pragma unroll
            for (int i = 0; i < 2; i++)
#pragma unroll
                for (int j = 0; j < 4; j++) {
                    mma_bf16(acc[h][i][j], afh[i], bfh[j][0], bfh[j][1]);
                    mma_bf16(acc[h][i][j], afh[i], bfl[j][0], bfl[j][1]);
                    mma_bf16(acc[h][i][j], afl[i], bfh[j][0], bfh[j][1]);
                }
        }
    }

    const int rr = lane >> 2, cc = (lane & 3) * 2;
#pragma unroll
    for (int i = 0; i < 2; i++) {
#pragma unroll
        for (int j = 0; j < 4; j++) {
#pragma unroll
            for (int half = 0; half < 2; half++) {
                int gr = rowBase + wm + i * 16 + rr + half * 8;
                int gn = colBase + wn + j * 8 + cc;
                if (gn < FIN) {
                    float v0 = acc[0][i][j][half * 2], v1 = acc[1][i][j][half * 2];
                    xhat[(size_t)gr * FIN + gn] =
                        0.5f * (lrelu(v0 + b3[gn], 0.01f) + lrelu(v1 + b3[FIN + gn], 0.01f));
                }
                if (gn + 1 < FIN) {
                    float v0 = acc[0][i][j][half * 2 + 1], v1 = acc[1][i][j][half * 2 + 1];
                    xhat[(size_t)gr * FIN + gn + 1] =
                        0.5f * (lrelu(v0 + b3[gn + 1], 0.01f) + lrelu(v1 + b3[FIN + gn + 1], 0.01f));
                }
            }
        }
    }
}

// ================= CSR build =================
__global__ void k_zerodeg(int* deg) {
    int i = blockIdx.x * blockDim.x + threadIdx.x;
    if (i < NN) deg[i] = 0;
}
__global__ void k_deg(const int* __restrict__ dst, int* deg, int E) {
    int e = blockIdx.x * blockDim.x + threadIdx.x;
    if (e < E) atomicAdd(&deg[dst[e]], 1);
}
__global__ void k_scan(const int* __restrict__ deg, int* rowptr, int* cursor) {
    __shared__ int partx[257];
    int t = threadIdx.x;
    int base = t * 32;
    int loc[32];
    int s = 0;
#pragma unroll
    for (int i = 0; i < 32; i++) { loc[i] = s; s += deg[base + i]; }
    __shared__ int part[256];
    part[t] = s;
    __syncthreads();
    if (t == 0) {
        int acc = 0;
        for (int i = 0; i < 256; i++) { partx[i] = acc; acc += part[i]; }
        partx[256] = acc;
    }
    __syncthreads();
    int off = partx[t];
#pragma unroll
    for (int i = 0; i < 32; i++) {
        int v = off + loc[i];
        rowptr[base + i] = v;
        cursor[base + i] = v;
    }
    if (t == 0) rowptr[NN] = partx[256];
}
__global__ void k_scatter(const int* __restrict__ src, const int* __restrict__ dst,
                          int* cursor, int* csrsrc, int E) {
    int e = blockIdx.x * blockDim.x + threadIdx.x;
    if (e >= E) return;
    int d = dst[e];
    int idx = atomicAdd(&cursor[d], 1);
    csrsrc[idx] = src[e];
}

// ================= pack kernels =================
__global__ void k_pack_feat(const float* __restrict__ feat, bf16* __restrict__ fhi,
                            bf16* __restrict__ flo) {
    int n = blockIdx.x;
    for (int f = threadIdx.x; f < FINB; f += blockDim.x) {
        float v = (f < FIN) ? feat[(size_t)n * FIN + f] : 0.f;
        split_bf16(v, &fhi[(size_t)n * FINB + f], &flo[(size_t)n * FINB + f]);
    }
}
__global__ void k_pack_w1t(const float* __restrict__ W1, bf16* __restrict__ whi,
                           bf16* __restrict__ wlo) {
    int n = blockIdx.x;  // 256
    for (int k = threadIdx.x; k < FINB; k += blockDim.x) {
        float v = (k < FIN) ? W1[(size_t)k * 256 + n] : 0.f;
        split_bf16(v, &whi[(size_t)n * FINB + k], &wlo[(size_t)n * FINB + k]);
    }
}
__global__ void k_pack_w2t(const float* __restrict__ W2, bf16* __restrict__ whi,
                           bf16* __restrict__ wlo) {
    int n = blockIdx.x;  // 128
    for (int k = threadIdx.x; k < 256; k += blockDim.x) {
        float v = W2[(size_t)k * 128 + n];
        split_bf16(v, &whi[(size_t)n * 256 + k], &wlo[(size_t)n * 256 + k]);
    }
}
__global__ void k_pack_w3t(const float* __restrict__ W3, bf16* __restrict__ whi,
                           bf16* __restrict__ wlo) {
    int f = blockIdx.x;  // NDEC
    int k = threadIdx.x; // 64
#pragma unroll
    for (int h = 0; h < 2; h++) {
        float v = (f < FIN) ? W3[(size_t)k * (2 * FIN) + h * FIN + f] : 0.f;
        split_bf16(v, &whi[((size_t)h * NDEC + f) * 64 + k], &wlo[((size_t)h * NDEC + f) * 64 + k]);
    }
}

// ================= attention logits =================
__global__ void k_elr(const float* __restrict__ hp, const float* __restrict__ al,
                      const float* __restrict__ ar, float* el, float* er, int D) {
    int w = (blockIdx.x * blockDim.x + threadIdx.x) >> 5;
    int lane = threadIdx.x & 31;
    if (w >= NN * 2) return;
    int n = w >> 1, h = w & 1;
    const float* row = hp + (size_t)n * (2 * D) + h * D;
    const float* a = al + h * D;
    const float* b = ar + h * D;
    float sl = 0.f, sr = 0.f;
    for (int d = lane; d < D; d += 32) { float x = row[d]; sl += x * a[d]; sr += x * b[d]; }
#pragma unroll
    for (int o = 16; o; o >>= 1) {
        sl += __shfl_down_sync(0xffffffffu, sl, o);
        sr += __shfl_down_sync(0xffffffffu, sr, o);
    }
    if (lane == 0) { el[w] = sl; er[w] = sr; }
}

__global__ void k_uv(const float* __restrict__ W3, const float* __restrict__ al3,
                     const float* __restrict__ ar3, float* uv) {
    int w = (blockIdx.x * blockDim.x + threadIdx.x) >> 5;
    int lane = threadIdx.x & 31;
    if (w >= 128) return;
    int h = w >> 6, k = w & 63;
    const float* Wr = W3 + (size_t)k * (2 * FIN) + h * FIN;
    const float* a = al3 + (size_t)h * FIN;
    const float* b = ar3 + (size_t)h * FIN;
    float su = 0.f, sv = 0.f;
    for (int f = lane; f < FIN; f += 32) { float ww = Wr[f]; su += ww * a[f]; sv += ww * b[f]; }
#pragma unroll
    for (int o = 16; o; o >>= 1) {
        su += __shfl_down_sync(0xffffffffu, su, o);
        sv += __shfl_down_sync(0xffffffffu, sv, o);
    }
    if (lane == 0) { uv[h * 64 + k] = su; uv[128 + h * 64 + k] = sv; }
}

__global__ void k_elr3(const float* __restrict__ h2, const float* __restrict__ uv,
                       float* el, float* er) {
    int w = (blockIdx.x * blockDim.x + threadIdx.x) >> 5;
    int lane = threadIdx.x & 31;
    if (w >= NN * 2) return;
    int n = w >> 1, h = w & 1;
    const float* row = h2 + (size_t)n * 64;
    const float* u = uv + h * 64;
    const float* v = uv + 128 + h * 64;
    float sl = 0.f, sr = 0.f;
    for (int d = lane; d < 64; d += 32) { float x = row[d]; sl += x * u[d]; sr += x * v[d]; }
#pragma unroll
    for (int o = 16; o; o >>= 1) {
        sl += __shfl_down_sync(0xffffffffu, sl, o);
        sr += __shfl_down_sync(0xffffffffu, sr, o);
    }
    if (lane == 0) { el[w] = sl; er[w] = sr; }
}

// ================= block softmax-sum helper =================
template <int NT>
__device__ __forceinline__ float2 block_inv_sum(const int* csrsrc, int b, int en,
                                                const float* el, float2 r,
                                                float* red, float2* out_sh) {
    int t = threadIdx.x, lane = t & 31, wid = t >> 5;
    float p0 = 0.f, p1 = 0.f;
    for (int i = b + t; i < en; i += NT) {
        int s = csrsrc[i];
        float2 l = *(const float2*)&el[s * 2];
        float e0 = l.x + r.x; e0 = e0 > 0.f ? e0 : 0.2f * e0;
        float e1 = l.y + r.y; e1 = e1 > 0.f ? e1 : 0.2f * e1;
        p0 += __expf(e0); p1 += __expf(e1);
    }
#pragma unroll
    for (int o = 16; o; o >>= 1) {
        p0 += __shfl_down_sync(0xffffffffu, p0, o);
        p1 += __shfl_down_sync(0xffffffffu, p1, o);
    }
    if (lane == 0) { red[wid * 2] = p0; red[wid * 2 + 1] = p1; }
    __syncthreads();
    if (t == 0) {
        float s0 = 0.f, s1 = 0.f;
        for (int w = 0; w < NT / 32; w++) { s0 += red[w * 2]; s1 += red[w * 2 + 1]; }
        *out_sh = make_float2(1.f / s0, 1.f / s1);
    }
    __syncthreads();
    return *out_sh;
}

// ================= CSR gather aggregation (R8-lean versions) =================
__global__ void __launch_bounds__(256)
k_agg1(const int* __restrict__ rowptr, const int* __restrict__ csrsrc,
       const float* __restrict__ el, const float* __restrict__ er,
       const float* __restrict__ hp, const float* __restrict__ b1,
       bf16* __restrict__ ohi, bf16* __restrict__ olo) {
    int d = blockIdx.x;
    int t = threadIdx.x;
    __shared__ float2 sal[128];
    __shared__ int ssrc[128];
    __shared__ float red[16];
    __shared__ float2 inv_sh;
    int b = rowptr[d], en = rowptr[d + 1];
    float2 r = *(const float2*)&er[d * 2];
    float2 inv = block_inv_sum<256>(csrsrc, b, en, el, r, red, &inv_sh);
    float acc = 0.f;
    int h = t >> 7;
    for (int c = b; c < en; c += 128) {
        int cnt = min(128, en - c);
        __syncthreads();
        if (t < cnt) {
            int s = csrsrc[c + t];
            float2 l = *(const float2*)&el[s * 2];
            float e0 = l.x + r.x; e0 = e0 > 0.f ? e0 : 0.2f * e0;
            float e1 = l.y + r.y; e1 = e1 > 0.f ? e1 : 0.2f * e1;
            sal[t] = make_float2(__expf(e0) * inv.x, __expf(e1) * inv.y);
            ssrc[t] = s;
        }
        __syncthreads();
#pragma unroll 4
        for (int i = 0; i < cnt; i++) {
            float a = h ? sal[i].y : sal[i].x;
            acc = fmaf(a, hp[(size_t)ssrc[i] * 256 + t], acc);
        }
    }
    float x = lrelu(acc + b1[t], 0.01f);
    split_bf16(x, &ohi[(size_t)d * 256 + t], &olo[(size_t)d * 256 + t]);
}

__global__ void __launch_bounds__(128)
k_agg2(const int* __restrict__ rowptr, const int* __restrict__ csrsrc,
       const float* __restrict__ el, const float* __restrict__ er,
       const float* __restrict__ hp, const float* __restrict__ b2,
       float* __restrict__ h2, bf16* __restrict__ h2hi, bf16* __restrict__ h2lo) {
    int d = blockIdx.x;
    int t = threadIdx.x;
    __shared__ float2 sal[128];
    __shared__ int ssrc[128];
    __shared__ float o[128];
    __shared__ float red[8];
    __shared__ float2 inv_sh;
    int b = rowptr[d], en = rowptr[d + 1];
    float2 r = *(const float2*)&er[d * 2];
    float2 inv = block_inv_sum<128>(csrsrc, b, en, el, r, red, &inv_sh);
    float acc = 0.f;
    int h = t >> 6;
    for (int c = b; c < en; c += 128) {
        int cnt = min(128, en - c);
        __syncthreads();
        if (t < cnt) {
            int s = csrsrc[c + t];
            float2 l = *(const float2*)&el[s * 2];
            float e0 = l.x + r.x; e0 = e0 > 0.f ? e0 : 0.2f * e0;
            float e1 = l.y + r.y; e1 = e1 > 0.f ? e1 : 0.2f * e1;
            sal[t] = make_float2(__expf(e0) * inv.x, __expf(e1) * inv.y);
            ssrc[t] = s;
        }
        __syncthreads();
#pragma unroll 4
        for (int i = 0; i < cnt; i++) {
            float a = h ? sal[i].y : sal[i].x;
            acc = fmaf(a, hp[(size_t)ssrc[i] * 128 + t], acc);
        }
    }
    o[t] = acc;
    __syncthreads();
    if (t < 64) {
        float x0 = lrelu(o[t] + b2[t], 0.01f);
        float x1 = lrelu(o[64 + t] + b2[64 + t], 0.01f);
        float v = 0.5f * (x0 + x1);
        h2[(size_t)d * 64 + t] = v;
        split_bf16(v, &h2hi[(size_t)d * 64 + t], &h2lo[(size_t)d * 64 + t]);
    }
}

__global__ void __launch_bounds__(128)
k_agg3(const int* __restrict__ rowptr, const int* __restrict__ csrsrc,
       const float* __restrict__ el, const float* __restrict__ er,
       const float* __restrict__ h2, bf16* __restrict__ ahi, bf16* __restrict__ alo) {
    int d = blockIdx.x;
    int t = threadIdx.x;
    __shared__ float2 sal[128];
    __shared__ int ssrc[128];
    __shared__ float red[8];
    __shared__ float2 inv_sh;
    int b = rowptr[d], en = rowptr[d + 1];
    float2 r = *(const float2*)&er[d * 2];
    float2 inv = block_inv_sum<128>(csrsrc, b, en, el, r, red, &inv_sh);
    float acc = 0.f;
    int h = t >> 6, dd = t & 63;
    for (int c = b; c < en; c += 128) {
        int cnt = min(128, en - c);
        __syncthreads();
        if (t < cnt) {
            int s = csrsrc[c + t];
            float2 l = *(const float2*)&el[s * 2];
            float e0 = l.x + r.x; e0 = e0 > 0.f ? e0 : 0.2f * e0;
            float e1 = l.y + r.y; e1 = e1 > 0.f ? e1 : 0.2f * e1;
            sal[t] = make_float2(__expf(e0) * inv.x, __expf(e1) * inv.y);
            ssrc[t] = s;
        }
        __syncthreads();
#pragma unroll 4
        for (int i = 0; i < cnt; i++) {
            float a = h ? sal[i].y : sal[i].x;
            acc = fmaf(a, h2[(size_t)ssrc[i] * 64 + dd], acc);
        }
    }
    size_t idx = ((size_t)h * NN + d) * 64 + dd;
    split_bf16(acc, &ahi[idx], &alo[idx]);
}

// ================= launch =================
extern "C" void kernel_launch(void* const* d_in, const int* in_sizes, int n_in,
                              void* d_out, int out_size) {
    const float* feat = (const float*)d_in[0];
    const int* src = (const int*)d_in[1];
    const int* dst = (const int*)d_in[2];
    const float* W1 = (const float*)d_in[3];
    const float* al1 = (const float*)d_in[4];
    const float* ar1 = (const float*)d_in[5];
    const float* b1 = (const float*)d_in[6];
    const float* W2 = (const float*)d_in[7];
    const float* al2 = (const float*)d_in[8];
    const float* ar2 = (const float*)d_in[9];
    const float* b2 = (const float*)d_in[10];
    const float* W3 = (const float*)d_in[11];
    const float* al3 = (const float*)d_in[12];
    const float* ar3 = (const float*)d_in[13];
    const float* b3 = (const float*)d_in[14];

    float* a_hat = (float*)d_out;
    float* x_hat = a_hat + (size_t)NN * NN;
    const int E = in_sizes[1];

    bf16 *feathi, *featlo, *w1thi, *w1tlo, *w2thi, *w2tlo, *w3thi, *w3tlo;
    bf16 *agg1hi, *agg1lo, *h2hi, *h2lo, *agg3hi, *agg3lo;
    float *h1p, *h2p, *h2, *el, *er, *uv;
    int *deg, *cursor, *rowptr, *csrsrc;
    cudaGetSymbolAddress((void**)&feathi, g_feathi);
    cudaGetSymbolAddress((void**)&featlo, g_featlo);
    cudaGetSymbolAddress((void**)&w1thi, g_w1thi);
    cudaGetSymbolAddress((void**)&w1tlo, g_w1tlo);
    cudaGetSymbolAddress((void**)&w2thi, g_w2thi);
    cudaGetSymbolAddress((void**)&w2tlo, g_w2tlo);
    cudaGetSymbolAddress((void**)&w3thi, g_w3thi);
    cudaGetSymbolAddress((void**)&w3tlo, g_w3tlo);
    cudaGetSymbolAddress((void**)&h1p, g_h1p);
    cudaGetSymbolAddress((void**)&agg1hi, g_agg1hi);
    cudaGetSymbolAddress((void**)&agg1lo, g_agg1lo);
    cudaGetSymbolAddress((void**)&h2p, g_h2p);
    cudaGetSymbolAddress((void**)&h2, g_h2);
    cudaGetSymbolAddress((void**)&h2hi, g_h2hi);
    cudaGetSymbolAddress((void**)&h2lo, g_h2lo);
    cudaGetSymbolAddress((void**)&agg3hi, g_agg3hi);
    cudaGetSymbolAddress((void**)&agg3lo, g_agg3lo);
    cudaGetSymbolAddress((void**)&el, g_el);
    cudaGetSymbolAddress((void**)&er, g_er);
    cudaGetSymbolAddress((void**)&uv, g_uv);
    cudaGetSymbolAddress((void**)&deg, g_deg);
    cudaGetSymbolAddress((void**)&cursor, g_cursor);
    cudaGetSymbolAddress((void**)&rowptr, g_rowptr);
    cudaGetSymbolAddress((void**)&csrsrc, g_csrsrc);

    cudaFuncSetAttribute(ahat_hmma, cudaFuncAttributeMaxDynamicSharedMemorySize, AHAT_SMEM);
    cudaFuncSetAttribute(hmma_gemm, cudaFuncAttributeMaxDynamicSharedMemorySize, HG_SMEM);
    cudaFuncSetAttribute(dec_hmma, cudaFuncAttributeMaxDynamicSharedMemorySize, DEC_SMEM);

    static cudaStream_t s1 = nullptr, s2 = nullptr;
    static cudaEvent_t evRoot, evCSR, evW1, evW, evH2, evAhat;
    if (s1 == nullptr) {
        cudaStreamCreateWithFlags(&s1, cudaStreamNonBlocking);
        cudaStreamCreateWithFlags(&s2, cudaStreamNonBlocking);
        cudaEventCreateWithFlags(&evRoot, cudaEventDisableTiming);
        cudaEventCreateWithFlags(&evCSR, cudaEventDisableTiming);
        cudaEventCreateWithFlags(&evW1, cudaEventDisableTiming);
        cudaEventCreateWithFlags(&evW, cudaEventDisableTiming);
        cudaEventCreateWithFlags(&evH2, cudaEventDisableTiming);
        cudaEventCreateWithFlags(&evAhat, cudaEventDisableTiming);
    }

    float *el1 = el, *el2 = el + NN * 2, *el3 = el + 2 * NN * 2;
    float *er1 = er, *er2 = er + NN * 2, *er3 = er + 2 * NN * 2;

    const int eb = (E + 255) / 256;

    // fork side streams
    cudaEventRecord(evRoot, 0);
    cudaStreamWaitEvent(s1, evRoot, 0);
    cudaStreamWaitEvent(s2, evRoot, 0);

    // ---- s1: CSR build ----
    k_zerodeg<<<(NN + 255) / 256, 256, 0, s1>>>(deg);
    k_deg<<<eb, 256, 0, s1>>>(dst, deg, E);
    k_scan<<<1, 256, 0, s1>>>(deg, rowptr, cursor);
    k_scatter<<<eb, 256, 0, s1>>>(src, dst, cursor, csrsrc, E);
    cudaEventRecord(evCSR, s1);

    // ---- s2: weight packs + decoder attention projection ----
    k_pack_w1t<<<256, 256, 0, s2>>>(W1, w1thi, w1tlo);
    cudaEventRecord(evW1, s2);
    k_pack_w2t<<<128, 256, 0, s2>>>(W2, w2thi, w2tlo);
    k_pack_w3t<<<NDEC, 64, 0, s2>>>(W3, w3thi, w3tlo);
    k_uv<<<16, 256, 0, s2>>>(W3, al3, ar3, uv);
    cudaEventRecord(evW, s2);

    // ---- main stream: layer 1 ----
    k_pack_feat<<<NN, 256>>>(feat, feathi, featlo);
    cudaStreamWaitEvent(0, evW1, 0);
    {
        dim3 grid(2, 64);
        hmma_gemm<<<grid, 256, HG_SMEM>>>(feathi, featlo, w1thi, w1tlo, h1p, FINB, FINB, FINB, 256);
    }
    k_elr<<<(NN * 2 * 32 + 255) / 256, 256>>>(h1p, al1, ar1, el1, er1, 128);
    cudaStreamWaitEvent(0, evCSR, 0);
    k_agg1<<<NN, 256>>>(rowptr, csrsrc, el1, er1, h1p, b1, agg1hi, agg1lo);

    // ---- layer 2 ----
    cudaStreamWaitEvent(0, evW, 0);
    {
        dim3 grid(1, 64);
        hmma_gemm<<<grid, 256, HG_SMEM>>>(agg1hi, agg1lo, w2thi, w2tlo, h2p, 256, 256, 256, 128);
    }
    k_elr<<<(NN * 2 * 32 + 255) / 256, 256>>>(h2p, al2, ar2, el2, er2, 64);
    k_agg2<<<NN, 128>>>(rowptr, csrsrc, el2, er2, h2p, b2, h2, h2hi, h2lo);
    cudaEventRecord(evH2, 0);

    // ---- s1: structure decoder a_hat (overlaps attribute decoder) ----
    cudaStreamWaitEvent(s1, evH2, 0);
    {
        dim3 grid(NN / 128, NN / 128);
        ahat_hmma<<<grid, 256, AHAT_SMEM, s1>>>(h2hi, h2lo, a_hat);
    }
    cudaEventRecord(evAhat, s1);

    // ---- main stream: attribute decoder ----
    k_elr3<<<(NN * 2 * 32 + 255) / 256, 256>>>(h2, uv, el3, er3);
    k_agg3<<<NN, 128>>>(rowptr, csrsrc, el3, er3, h2, agg3hi, agg3lo);
    {
        dim3 grid(NDEC / 64, NN / 128);
        dec_hmma<<<grid, 256, DEC_SMEM>>>(agg3hi, agg3lo, w3thi, w3tlo, b3, x_hat);
    }

    // join
    cudaStreamWaitEvent(0, evAhat, 0);
}

// round 13
// speedup vs baseline: 1.1225x; 1.0117x over previous
#include <cuda_runtime.h>
#include <cuda_bf16.h>
#include <cstdint>

#define NN 8192
#define FIN 1433
#define FINB 1472      // FIN padded to multiple of 64
#define NDEC 1536      // decoder N padded to multiple of 64
#define MAXE (1 << 20)

typedef unsigned long long u64t;
typedef __nv_bfloat16 bf16;

// ---------------- scratch (device globals) ----------------
__device__ bf16 g_feathi[NN * FINB];
__device__ bf16 g_featlo[NN * FINB];
__device__ bf16 g_w1thi[256 * FINB];
__device__ bf16 g_w1tlo[256 * FINB];
__device__ bf16 g_w2thi[128 * 256];
__device__ bf16 g_w2tlo[128 * 256];
__device__ bf16 g_w3thi[2 * NDEC * 64];
__device__ bf16 g_w3tlo[2 * NDEC * 64];
__device__ float g_h1p[NN * 256];
__device__ bf16 g_agg1hi[NN * 256];
__device__ bf16 g_agg1lo[NN * 256];
__device__ float g_h2p[NN * 128];
__device__ float g_h2[NN * 64];
__device__ bf16 g_h2hi[NN * 64];
__device__ bf16 g_h2lo[NN * 64];
__device__ bf16 g_agg3hi[2 * NN * 64];
__device__ bf16 g_agg3lo[2 * NN * 64];
__device__ float g_el[3 * NN * 2];
__device__ float g_er[3 * NN * 2];
__device__ float g_uv[2 * 64 * 2];
__device__ int g_deg[NN];
__device__ int g_cursor[NN];
__device__ int g_rowptr[NN + 1];
__device__ int g_csrsrc[MAXE];

__device__ __forceinline__ float lrelu(float x, float a) { return x > 0.f ? x : a * x; }

__device__ __forceinline__ uint32_t smem_u32(const void* p) {
    uint32_t a;
    asm("{ .reg .u64 t; cvta.to.shared.u64 t, %1; cvt.u32.u64 %0, t; }" : "=r"(a) : "l"(p));
    return a;
}
__device__ __forceinline__ void ldm_x4(uint32_t* r, uint32_t addr) {
    asm volatile("ldmatrix.sync.aligned.m8n8.x4.shared.b16 {%0,%1,%2,%3}, [%4];"
                 : "=r"(r[0]), "=r"(r[1]), "=r"(r[2]), "=r"(r[3]) : "r"(addr));
}
__device__ __forceinline__ void mma_bf16(float* c, const uint32_t* a, uint32_t b0, uint32_t b1) {
    asm volatile(
        "mma.sync.aligned.m16n8k16.row.col.f32.bf16.bf16.f32 "
        "{%0,%1,%2,%3}, {%4,%5,%6,%7}, {%8,%9}, {%0,%1,%2,%3};"
        : "+f"(c[0]), "+f"(c[1]), "+f"(c[2]), "+f"(c[3])
        : "r"(a[0]), "r"(a[1]), "r"(a[2]), "r"(a[3]), "r"(b0), "r"(b1));
}
__device__ __forceinline__ void split_bf16(float v, bf16* hi, bf16* lo) {
    bf16 h = __float2bfloat16(v);
    *hi = h;
    *lo = __float2bfloat16(v - __bfloat162float(h));
}
__device__ __forceinline__ void cp16(uint32_t dst, const void* src) {
    asm volatile("cp.async.cg.shared.global [%0], [%1], 16;" :: "r"(dst), "l"(src));
}
__device__ __forceinline__ void st_cs_f2(float* p, float a, float b) {
    asm volatile("st.global.cs.v2.f32 [%0], {%1, %2};" :: "l"(p), "f"(a), "f"(b) : "memory");
}

#define APITCH 72    // bf16 per smem row (144B) — conflict-free ldmatrix
#define TILEB 18432  // one 128xAPITCH bf16 tile in bytes

// ================= bf16-split HMMA GEMM + fused el/er epilogue =================
// ELMODE 1: one head per col-block (gemm1, N=256, grid.x=2)  -> smem combine
// ELMODE 2: head = warp col-half (gemm2, N=128, grid.x=1)    -> direct store
#define HG_SMEM (8 * TILEB)  // 147456 B

template <int ELMODE>
__global__ void __launch_bounds__(256)
hmma_gemm_el(const bf16* __restrict__ Ahi, const bf16* __restrict__ Alo,
             const bf16* __restrict__ Bhi, const bf16* __restrict__ Blo,
             float* __restrict__ C, int K, int lda, int ldb, int ldc,
             const float* __restrict__ al, const float* __restrict__ ar,
             float* __restrict__ el, float* __restrict__ er) {
    extern __shared__ char smem[];
    const uint32_t sb = smem_u32(smem);
    const int tid = threadIdx.x, wid = tid >> 5, lane = tid & 31;
    const int rowBase = blockIdx.y * 128, colBase = blockIdx.x * 128;
    const int wm = (wid & 3) * 32, wn = (wid >> 2) * 64;
    const int lrow = lane & 15, lch = lane >> 4;
    const int nk = K >> 6;

    float acc[2][8][4];
#pragma unroll
    for (int i = 0; i < 2; i++)
#pragma unroll
        for (int j = 0; j < 8; j++)
#pragma unroll
            for (int q = 0; q < 4; q++) acc[i][j][q] = 0.f;

    auto stage = [&](int buf, int kc) {
        uint32_t base = sb + buf * (4 * TILEB);
        for (int idx = tid; idx < 1024; idx += 256) {
            int row = idx >> 3, ch = idx & 7;
            uint32_t off = (uint32_t)(row * APITCH + ch * 8) * 2;
            cp16(base + off, Ahi + (size_t)(rowBase + row) * lda + kc + ch * 8);
            cp16(base + TILEB + off, Alo + (size_t)(rowBase + row) * lda + kc + ch * 8);
            cp16(base + 2 * TILEB + off, Bhi + (size_t)(colBase + row) * ldb + kc + ch * 8);
            cp16(base + 3 * TILEB + off, Blo + (size_t)(colBase + row) * ldb + kc + ch * 8);
        }
        asm volatile("cp.async.commit_group;" ::: "memory");
    };

    stage(0, 0);
    for (int t = 0; t < nk; ++t) {
        asm volatile("cp.async.wait_group 0;" ::: "memory");
        __syncthreads();
        if (t + 1 < nk) stage((t + 1) & 1, (t + 1) * 64);
        const uint32_t base = sb + (t & 1) * (4 * TILEB);
        const uint32_t bAhi = base, bAlo = base + TILEB;
        const uint32_t bBhi = base + 2 * TILEB, bBlo = base + 3 * TILEB;
#pragma unroll
        for (int ks = 0; ks < 4; ks++) {
            uint32_t afh[2][4], afl[2][4];
#pragma unroll
            for (int i = 0; i < 2; i++) {
                uint32_t ao = ((wm + i * 16 + lrow) * APITCH) * 2 + (ks * 2 + lch) * 16;
                ldm_x4(afh[i], bAhi + ao);
                ldm_x4(afl[i], bAlo + ao);
            }
            uint32_t bfh[8][2], bfl[8][2];
#pragma unroll
            for (int jj = 0; jj < 4; jj++) {
                uint32_t bo = ((wn + jj * 16 + lrow) * APITCH) * 2 + (ks * 2 + lch) * 16;
                uint32_t r[4];
                ldm_x4(r, bBhi + bo);
                bfh[2 * jj][0] = r[0]; bfh[2 * jj][1] = r[2];
                bfh[2 * jj + 1][0] = r[1]; bfh[2 * jj + 1][1] = r[3];
                ldm_x4(r, bBlo + bo);
                bfl[2 * jj][0] = r[0]; bfl[2 * jj][1] = r[2];
                bfl[2 * jj + 1][0] = r[1]; bfl[2 * jj + 1][1] = r[3];
            }
#pragma unroll
            for (int i = 0; i < 2; i++)
#pragma unroll
                for (int j = 0; j < 8; j++) {
                    mma_bf16(acc[i][j], afh[i], bfh[j][0], bfh[j][1]);
                    mma_bf16(acc[i][j], afh[i], bfl[j][0], bfl[j][1]);
                    mma_bf16(acc[i][j], afl[i], bfh[j][0], bfh[j][1]);
                }
        }
        __syncthreads();
    }

    const int rr = lane >> 2, cc = (lane & 3) * 2;

    // ---- store C ----
#pragma unroll
    for (int i = 0; i < 2; i++) {
        int gr = rowBase + wm + i * 16 + rr;
        float* out0 = C + (size_t)gr * ldc + colBase + wn + cc;
        float* out1 = out0 + 8 * ldc;
#pragma unroll
        for (int j = 0; j < 8; j++) {
            *(float2*)(out0 + j * 8) = make_float2(acc[i][j][0], acc[i][j][1]);
            *(float2*)(out1 + j * 8) = make_float2(acc[i][j][2], acc[i][j][3]);
        }
    }

    // ---- fused el/er epilogue ----
    float2 alv[8], arv[8];
#pragma unroll
    for (int j = 0; j < 8; j++) {
        int c = colBase + wn + j * 8 + cc;
        alv[j] = make_float2(__ldg(al + c), __ldg(al + c + 1));
        arv[j] = make_float2(__ldg(ar + c), __ldg(ar + c + 1));
    }
    float pel[2][2], prr[2][2];
#pragma unroll
    for (int i = 0; i < 2; i++)
#pragma unroll
        for (int half = 0; half < 2; half++) {
            float se = 0.f, sr = 0.f;
#pragma unroll
            for (int j = 0; j < 8; j++) {
                se = fmaf(acc[i][j][half * 2], alv[j].x, se);
                se = fmaf(acc[i][j][half * 2 + 1], alv[j].y, se);
                sr = fmaf(acc[i][j][half * 2], arv[j].x, sr);
                sr = fmaf(acc[i][j][half * 2 + 1], arv[j].y, sr);
            }
            pel[i][half] = se;
            prr[i][half] = sr;
        }
#pragma unroll
    for (int o = 1; o <= 2; o <<= 1) {
#pragma unroll
        for (int i = 0; i < 2; i++)
#pragma unroll
            for (int half = 0; half < 2; half++) {
                pel[i][half] += __shfl_xor_sync(0xffffffffu, pel[i][half], o);
                prr[i][half] += __shfl_xor_sync(0xffffffffu, prr[i][half], o);
            }
    }
    if (ELMODE == 2) {
        if ((lane & 3) == 0) {
            int head = wn >> 6;
#pragma unroll
            for (int i = 0; i < 2; i++)
#pragma unroll
                for (int half = 0; half < 2; half++) {
                    int gr = rowBase + wm + i * 16 + rr + half * 8;
                    el[(size_t)gr * 2 + head] = pel[i][half];
                    er[(size_t)gr * 2 + head] = prr[i][half];
                }
        }
    } else {
        float* sel = (float*)smem;        // 256 floats
        float* ser = sel + 256;           // 256 floats
        if ((lane & 3) == 0) {
#pragma unroll
            for (int i = 0; i < 2; i++)
#pragma unroll
                for (int half = 0; half < 2; half++) {
                    int r = wm + i * 16 + rr + half * 8;
                    sel[r * 2 + (wid >> 2)] = pel[i][half];
                    ser[r * 2 + (wid >> 2)] = prr[i][half];
                }
        }
        __syncthreads();
        if (tid < 128) {
            int head = colBase >> 7;
            el[(size_t)(rowBase + tid) * 2 + head] = sel[tid * 2] + sel[tid * 2 + 1];
            er[(size_t)(rowBase + tid) * 2 + head] = ser[tid * 2] + ser[tid * 2 + 1];
        }
    }
}

// ================= a_hat HMMA (128x128, K=64), streaming stores =================
#define AHAT_SMEM (4 * TILEB)

__global__ void __launch_bounds__(256)
ahat_hmma(const bf16* __restrict__ hi, const bf16* __restrict__ lo, float* __restrict__ C) {
    extern __shared__ char smem[];
    bf16* sAhi = (bf16*)(smem);
    bf16* sAlo = (bf16*)(smem + TILEB);
    bf16* sBhi = (bf16*)(smem + 2 * TILEB);
    bf16* sBlo = (bf16*)(smem + 3 * TILEB);
    const int tid = threadIdx.x, wid = tid >> 5, lane = tid & 31;
    const int rowBase = blockIdx.y * 128, colBase = blockIdx.x * 128;

    for (int idx = tid; idx < 128 * 8; idx += 256) {
        int row = idx >> 3, ch = idx & 7;
        int off = row * APITCH + ch * 8;
        *(uint4*)(sAhi + off) = *((const uint4*)(hi + (size_t)(rowBase + row) * 64) + ch);
        *(uint4*)(sAlo + off) = *((const uint4*)(lo + (size_t)(rowBase + row) * 64) + ch);
        *(uint4*)(sBhi + off) = *((const uint4*)(hi + (size_t)(colBase + row) * 64) + ch);
        *(uint4*)(sBlo + off) = *((const uint4*)(lo + (size_t)(colBase + row) * 64) + ch);
    }
    __syncthreads();

    const int wm = (wid & 3) * 32, wn = (wid >> 2) * 64;
    float acc[2][8][4];
#pragma unroll
    for (int i = 0; i < 2; i++)
#pragma unroll
        for (int j = 0; j < 8; j++)
#pragma unroll
            for (int q = 0; q < 4; q++) acc[i][j][q] = 0.f;

    const int lrow = lane & 15, lch = lane >> 4;
    const uint32_t sbAhi = smem_u32(sAhi), sbAlo = smem_u32(sAlo);
    const uint32_t sbBhi = smem_u32(sBhi), sbBlo = smem_u32(sBlo);

#pragma unroll
    for (int pass = 0; pass < 3; pass++) {
        const uint32_t aBase = (pass == 2) ? sbAlo : sbAhi;
        const uint32_t bBase = (pass == 1) ? sbBlo : sbBhi;
#pragma unroll
        for (int ks = 0; ks < 4; ks++) {
            uint32_t af[2][4];
#pragma unroll
            for (int i = 0; i < 2; i++)
                ldm_x4(af[i], aBase + ((wm + i * 16 + lrow) * APITCH) * 2 + (ks * 2 + lch) * 16);
            uint32_t bf[8][2];
#pragma unroll
            for (int jj = 0; jj < 4; jj++) {
                uint32_t r[4];
                ldm_x4(r, bBase + ((wn + jj * 16 + lrow) * APITCH) * 2 + (ks * 2 + lch) * 16);
                bf[2 * jj][0] = r[0]; bf[2 * jj][1] = r[2];
                bf[2 * jj + 1][0] = r[1]; bf[2 * jj + 1][1] = r[3];
            }
#pragma unroll
            for (int i = 0; i < 2; i++)
#pragma unroll
                for (int j = 0; j < 8; j++)
                    mma_bf16(acc[i][j], af[i], bf[j][0], bf[j][1]);
        }
    }

    const int rr = lane >> 2, cc = (lane & 3) * 2;
#pragma unroll
    for (int i = 0; i < 2; i++) {
        int gr = rowBase + wm + i * 16 + rr;
        float* out0 = C + (size_t)gr * NN + colBase + wn + cc;
        float* out1 = out0 + 8 * NN;
#pragma unroll
        for (int j = 0; j < 8; j++) {
            st_cs_f2(out0 + j * 8, acc[i][j][0], acc[i][j][1]);
            st_cs_f2(out1 + j * 8, acc[i][j][2], acc[i][j][3]);
        }
    }
}

// ================= fused decoder HMMA (2 heads + bias + lrelu + mean) =================
#define DEC_SMEM (2 * TILEB + TILEB)

__global__ void __launch_bounds__(256)
dec_hmma(const bf16* __restrict__ Ahi, const bf16* __restrict__ Alo,
         const bf16* __restrict__ Bhi, const bf16* __restrict__ Blo,
         const float* __restrict__ b3, float* __restrict__ xhat) {
    extern __shared__ char smem[];
    bf16* sAhi = (bf16*)smem;
    bf16* sAlo = (bf16*)(smem + TILEB);
    bf16* sBhi = (bf16*)(smem + 2 * TILEB);
    bf16* sBlo = (bf16*)(smem + 2 * TILEB + TILEB / 2);
    const int tid = threadIdx.x, wid = tid >> 5, lane = tid & 31;
    const int rowBase = blockIdx.y * 128, colBase = blockIdx.x * 64;
    const int wm = (wid & 3) * 32, wn = (wid >> 2) * 32;
    const int lrow = lane & 15, lch = lane >> 4;

    float acc[2][2][4][4];
#pragma unroll
    for (int h = 0; h < 2; h++)
#pragma unroll
        for (int i = 0; i < 2; i++)
#pragma unroll
            for (int j = 0; j < 4; j++)
#pragma unroll
                for (int q = 0; q < 4; q++) acc[h][i][j][q] = 0.f;

    const uint32_t sbAhi = smem_u32(sAhi), sbAlo = smem_u32(sAlo);
    const uint32_t sbBhi = smem_u32(sBhi), sbBlo = smem_u32(sBlo);

#pragma unroll
    for (int h = 0; h < 2; h++) {
        const bf16* ahp = Ahi + (size_t)h * NN * 64;
        const bf16* alp = Alo + (size_t)h * NN * 64;
        const bf16* bhp = Bhi + (size_t)h * NDEC * 64;
        const bf16* blp = Blo + (size_t)h * NDEC * 64;
        __syncthreads();
        for (int idx = tid; idx < 1024; idx += 256) {
            int row = idx >> 3, ch = idx & 7;
            int off = row * APITCH + ch * 8;
            *(uint4*)(sAhi + off) = *(const uint4*)(ahp + (size_t)(rowBase + row) * 64 + ch * 8);
            *(uint4*)(sAlo + off) = *(const uint4*)(alp + (size_t)(rowBase + row) * 64 + ch * 8);
        }
        for (int idx = tid; idx < 512; idx += 256) {
            int row = idx >> 3, ch = idx & 7;
            int off = row * APITCH + ch * 8;
            *(uint4*)(sBhi + off) = *(const uint4*)(bhp + (size_t)(colBase + row) * 64 + ch * 8);
            *(uint4*)(sBlo + off) = *(const uint4*)(blp + (size_t)(colBase + row) * 64 + ch * 8);
        }
        __syncthreads();
#pragma unroll
        for (int ks = 0; ks < 4; ks++) {
            uint32_t afh[2][4], afl[2][4];
#pragma unroll
            for (int i = 0; i < 2; i++) {
                uint32_t ao = ((wm + i * 16 + lrow) * APITCH) * 2 + (ks * 2 + lch) * 16;
                ldm_x4(afh[i], sbAhi + ao);
                ldm_x4(afl[i], sbAlo + ao);
            }
            uint32_t bfh[4][2], bfl[4][2];
#pragma unroll
            for (int jj = 0; jj < 2; jj++) {
                uint32_t bo = ((wn + jj * 16 + lrow) * APITCH) * 2 + (ks * 2 + lch) * 16;
                uint32_t r[4];
                ldm_x4(r, sbBhi + bo);
                bfh[2 * jj][0] = r[0]; bfh[2 * jj][1] = r[2];
                bfh[2 * jj + 1][0] = r[1]; bfh[2 * jj + 1][1] = r[3];
                ldm_x4(r, sbBlo + bo);
                bfl[2 * jj][0] = r[0]; bfl[2 * jj][1] = r[2];
                bfl[2 * jj + 1][0] = r[1]; bfl[2 * jj + 1][1] = r[3];
            }
#pragma unroll
            for (int i = 0; i < 2; i++)
#pragma unroll
                for (int j = 0; j < 4; j++) {
                    mma_bf16(acc[h][i][j], afh[i], bfh[j][0], bfh[j][1]);
                    mma_bf16(acc[h][i][j], afh[i], bfl[j][0], bfl[j][1]);
                    mma_bf16(acc[h][i][j], afl[i], bfh[j][0], bfh[j][1]);
                }
        }
    }

    const int rr = lane >> 2, cc = (lane & 3) * 2;
#pragma unroll
    for (int i = 0; i < 2; i++) {
#pragma unroll
        for (int j = 0; j < 4; j++) {
#pragma unroll
            for (int half = 0; half < 2; half++) {
                int gr = rowBase + wm + i * 16 + rr + half * 8;
                int gn = colBase + wn + j * 8 + cc;
                if (gn < FIN) {
                    float v0 = acc[0][i][j][half * 2], v1 = acc[1][i][j][half * 2];
                    xhat[(size_t)gr * FIN + gn] =
                        0.5f * (lrelu(v0 + b3[gn], 0.01f) + lrelu(v1 + b3[FIN + gn], 0.01f));
                }
                if (gn + 1 < FIN) {
                    float v0 = acc[0][i][j][half * 2 + 1], v1 = acc[1][i][j][half * 2 + 1];
                    xhat[(size_t)gr * FIN + gn + 1] =
                        0.5f * (lrelu(v0 + b3[gn + 1], 0.01f) + lrelu(v1 + b3[FIN + gn + 1], 0.01f));
                }
            }
        }
    }
}

// ================= CSR build =================
__global__ void k_zerodeg(int* deg) {
    int i = blockIdx.x * blockDim.x + threadIdx.x;
    if (i < NN) deg[i] = 0;
}
__global__ void k_deg(const int* __restrict__ dst, int* deg, int E) {
    int e = blockIdx.x * blockDim.x + threadIdx.x;
    if (e < E) atomicAdd(&deg[dst[e]], 1);
}
__global__ void k_scan(const int* __restrict__ deg, int* rowptr, int* cursor) {
    __shared__ int partx[257];
    int t = threadIdx.x;
    int base = t * 32;
    int loc[32];
    int s = 0;
#pragma unroll
    for (int i = 0; i < 32; i++) { loc[i] = s; s += deg[base + i]; }
    __shared__ int part[256];
    part[t] = s;
    __syncthreads();
    if (t == 0) {
        int acc = 0;
        for (int i = 0; i < 256; i++) { partx[i] = acc; acc += part[i]; }
        partx[256] = acc;
    }
    __syncthreads();
    int off = partx[t];
#pragma unroll
    for (int i = 0; i < 32; i++) {
        int v = off + loc[i];
        rowptr[base + i] = v;
        cursor[base + i] = v;
    }
    if (t == 0) rowptr[NN] = partx[256];
}
__global__ void k_scatter(const int* __restrict__ src, const int* __restrict__ dst,
                          int* cursor, int* csrsrc, int E) {
    int e = blockIdx.x * blockDim.x + threadIdx.x;
    if (e >= E) return;
    int d = dst[e];
    int idx = atomicAdd(&cursor[d], 1);
    csrsrc[idx] = src[e];
}

// ================= pack kernels =================
__global__ void k_pack_feat(const float* __restrict__ feat, bf16* __restrict__ fhi,
                            bf16* __restrict__ flo) {
    int n = blockIdx.x;
    for (int f = threadIdx.x; f < FINB; f += blockDim.x) {
        float v = (f < FIN) ? feat[(size_t)n * FIN + f] : 0.f;
        split_bf16(v, &fhi[(size_t)n * FINB + f], &flo[(size_t)n * FINB + f]);
    }
}
__global__ void k_pack_w1t(const float* __restrict__ W1, bf16* __restrict__ whi,
                           bf16* __restrict__ wlo) {
    int n = blockIdx.x;  // 256
    for (int k = threadIdx.x; k < FINB; k += blockDim.x) {
        float v = (k < FIN) ? W1[(size_t)k * 256 + n] : 0.f;
        split_bf16(v, &whi[(size_t)n * FINB + k], &wlo[(size_t)n * FINB + k]);
    }
}
__global__ void k_pack_w2t(const float* __restrict__ W2, bf16* __restrict__ whi,
                           bf16* __restrict__ wlo) {
    int n = blockIdx.x;  // 128
    for (int k = threadIdx.x; k < 256; k += blockDim.x) {
        float v = W2[(size_t)k * 128 + n];
        split_bf16(v, &whi[(size_t)n * 256 + k], &wlo[(size_t)n * 256 + k]);
    }
}
__global__ void k_pack_w3t(const float* __restrict__ W3, bf16* __restrict__ whi,
                           bf16* __restrict__ wlo) {
    int f = blockIdx.x;  // NDEC
    int k = threadIdx.x; // 64
#pragma unroll
    for (int h = 0; h < 2; h++) {
        float v = (f < FIN) ? W3[(size_t)k * (2 * FIN) + h * FIN + f] : 0.f;
        split_bf16(v, &whi[((size_t)h * NDEC + f) * 64 + k], &wlo[((size_t)h * NDEC + f) * 64 + k]);
    }
}

// ================= attention logits (layer 3 only) =================
__global__ void k_uv(const float* __restrict__ W3, const float* __restrict__ al3,
                     const float* __restrict__ ar3, float* uv) {
    int w = (blockIdx.x * blockDim.x + threadIdx.x) >> 5;
    int lane = threadIdx.x & 31;
    if (w >= 128) return;
    int h = w >> 6, k = w & 63;
    const float* Wr = W3 + (size_t)k * (2 * FIN) + h * FIN;
    const float* a = al3 + (size_t)h * FIN;
    const float* b = ar3 + (size_t)h * FIN;
    float su = 0.f, sv = 0.f;
    for (int f = lane; f < FIN; f += 32) { float ww = Wr[f]; su += ww * a[f]; sv += ww * b[f]; }
#pragma unroll
    for (int o = 16; o; o >>= 1) {
        su += __shfl_down_sync(0xffffffffu, su, o);
        sv += __shfl_down_sync(0xffffffffu, sv, o);
    }
    if (lane == 0) { uv[h * 64 + k] = su; uv[128 + h * 64 + k] = sv; }
}

__global__ void k_elr3(const float* __restrict__ h2, const float* __restrict__ uv,
                       float* el, float* er) {
    int w = (blockIdx.x * blockDim.x + threadIdx.x) >> 5;
    int lane = threadIdx.x & 31;
    if (w >= NN * 2) return;
    int n = w >> 1, h = w & 1;
    const float* row = h2 + (size_t)n * 64;
    const float* u = uv + h * 64;
    const float* v = uv + 128 + h * 64;
    float sl = 0.f, sr = 0.f;
    for (int d = lane; d < 64; d += 32) { float x = row[d]; sl += x * u[d]; sr += x * v[d]; }
#pragma unroll
    for (int o = 16; o; o >>= 1) {
        sl += __shfl_down_sync(0xffffffffu, sl, o);
        sr += __shfl_down_sync(0xffffffffu, sr, o);
    }
    if (lane == 0) { el[w] = sl; er[w] = sr; }
}

// ================= block softmax-sum helper =================
template <int NT>
__device__ __forceinline__ float2 block_inv_sum(const int* csrsrc, int b, int en,
                                                const float* el, float2 r,
                                                float* red, float2* out_sh) {
    int t = threadIdx.x, lane = t & 31, wid = t >> 5;
    float p0 = 0.f, p1 = 0.f;
    for (int i = b + t; i < en; i += NT) {
        int s = csrsrc[i];
        float2 l = *(const float2*)&el[s * 2];
        float e0 = l.x + r.x; e0 = e0 > 0.f ? e0 : 0.2f * e0;
        float e1 = l.y + r.y; e1 = e1 > 0.f ? e1 : 0.2f * e1;
        p0 += __expf(e0); p1 += __expf(e1);
    }
#pragma unroll
    for (int o = 16; o; o >>= 1) {
        p0 += __shfl_down_sync(0xffffffffu, p0, o);
        p1 += __shfl_down_sync(0xffffffffu, p1, o);
    }
    if (lane == 0) { red[wid * 2] = p0; red[wid * 2 + 1] = p1; }
    __syncthreads();
    if (t == 0) {
        float s0 = 0.f, s1 = 0.f;
        for (int w = 0; w < NT / 32; w++) { s0 += red[w * 2]; s1 += red[w * 2 + 1]; }
        *out_sh = make_float2(1.f / s0, 1.f / s1);
    }
    __syncthreads();
    return *out_sh;
}

// ================= CSR gather aggregation (lean) =================
__global__ void __launch_bounds__(256)
k_agg1(const int* __restrict__ rowptr, const int* __restrict__ csrsrc,
       const float* __restrict__ el, const float* __restrict__ er,
       const float* __restrict__ hp, const float* __restrict__ b1,
       bf16* __restrict__ ohi, bf16* __restrict__ olo) {
    int d = blockIdx.x;
    int t = threadIdx.x;
    __shared__ float2 sal[128];
    __shared__ int ssrc[128];
    __shared__ float red[16];
    __shared__ float2 inv_sh;
    int b = rowptr[d], en = rowptr[d + 1];
    float2 r = *(const float2*)&er[d * 2];
    float2 inv = block_inv_sum<256>(csrsrc, b, en, el, r, red, &inv_sh);
    float acc = 0.f;
    int h = t >> 7;
    for (int c = b; c < en; c += 128) {
        int cnt = min(128, en - c);
        __syncthreads();
        if (t < cnt) {
            int s = csrsrc[c + t];
            float2 l = *(const float2*)&el[s * 2];
            float e0 = l.x + r.x; e0 = e0 > 0.f ? e0 : 0.2f * e0;
            float e1 = l.y + r.y; e1 = e1 > 0.f ? e1 : 0.2f * e1;
            sal[t] = make_float2(__expf(e0) * inv.x, __expf(e1) * inv.y);
            ssrc[t] = s;
        }
        __syncthreads();
#pragma unroll 4
        for (int i = 0; i < cnt; i++) {
            float a = h ? sal[i].y : sal[i].x;
            acc = fmaf(a, hp[(size_t)ssrc[i] * 256 + t], acc);
        }
    }
    float x = lrelu(acc + b1[t], 0.01f);
    split_bf16(x, &ohi[(size_t)d * 256 + t], &olo[(size_t)d * 256 + t]);
}

__global__ void __launch_bounds__(128)
k_agg2(const int* __restrict__ rowptr, const int* __restrict__ csrsrc,
       const float* __restrict__ el, const float* __restrict__ er,
       const float* __restrict__ hp, const float* __restrict__ b2,
       float* __restrict__ h2, bf16* __restrict__ h2hi, bf16* __restrict__ h2lo) {
    int d = blockIdx.x;
    int t = threadIdx.x;
    __shared__ float2 sal[128];
    __shared__ int ssrc[128];
    __shared__ float o[128];
    __shared__ float red[8];
    __shared__ float2 inv_sh;
    int b = rowptr[d], en = rowptr[d + 1];
    float2 r = *(const float2*)&er[d * 2];
    float2 inv = block_inv_sum<128>(csrsrc, b, en, el, r, red, &inv_sh);
    float acc = 0.f;
    int h = t >> 6;
    for (int c = b; c < en; c += 128) {
        int cnt = min(128, en - c);
        __syncthreads();
        if (t < cnt) {
            int s = csrsrc[c + t];
            float2 l = *(const float2*)&el[s * 2];
            float e0 = l.x + r.x; e0 = e0 > 0.f ? e0 : 0.2f * e0;
            float e1 = l.y + r.y; e1 = e1 > 0.f ? e1 : 0.2f * e1;
            sal[t] = make_float2(__expf(e0) * inv.x, __expf(e1) * inv.y);
            ssrc[t] = s;
        }
        __syncthreads();
#pragma unroll 4
        for (int i = 0; i < cnt; i++) {
            float a = h ? sal[i].y : sal[i].x;
            acc = fmaf(a, hp[(size_t)ssrc[i] * 128 + t], acc);
        }
    }
    o[t] = acc;
    __syncthreads();
    if (t < 64) {
        float x0 = lrelu(o[t] + b2[t], 0.01f);
        float x1 = lrelu(o[64 + t] + b2[64 + t], 0.01f);
        float v = 0.5f * (x0 + x1);
        h2[(size_t)d * 64 + t] = v;
        split_bf16(v, &h2hi[(size_t)d * 64 + t], &h2lo[(size_t)d * 64 + t]);
    }
}

__global__ void __launch_bounds__(128)
k_agg3(const int* __restrict__ rowptr, const int* __restrict__ csrsrc,
       const float* __restrict__ el, const float* __restrict__ er,
       const float* __restrict__ h2, bf16* __restrict__ ahi, bf16* __restrict__ alo) {
    int d = blockIdx.x;
    int t = threadIdx.x;
    __shared__ float2 sal[128];
    __shared__ int ssrc[128];
    __shared__ float red[8];
    __shared__ float2 inv_sh;
    int b = rowptr[d], en = rowptr[d + 1];
    float2 r = *(const float2*)&er[d * 2];
    float2 inv = block_inv_sum<128>(csrsrc, b, en, el, r, red, &inv_sh);
    float acc = 0.f;
    int h = t >> 6, dd = t & 63;
    for (int c = b; c < en; c += 128) {
        int cnt = min(128, en - c);
        __syncthreads();
        if (t < cnt) {
            int s = csrsrc[c + t];
            float2 l = *(const float2*)&el[s * 2];
            float e0 = l.x + r.x; e0 = e0 > 0.f ? e0 : 0.2f * e0;
            float e1 = l.y + r.y; e1 = e1 > 0.f ? e1 : 0.2f * e1;
            sal[t] = make_float2(__expf(e0) * inv.x, __expf(e1) * inv.y);
            ssrc[t] = s;
        }
        __syncthreads();
#pragma unroll 4
        for (int i = 0; i < cnt; i++) {
            float a = h ? sal[i].y : sal[i].x;
            acc = fmaf(a, h2[(size_t)ssrc[i] * 64 + dd], acc);
        }
    }
    size_t idx = ((size_t)h * NN + d) * 64 + dd;
    split_bf16(acc, &ahi[idx], &alo[idx]);
}

// ================= launch =================
extern "C" void kernel_launch(void* const* d_in, const int* in_sizes, int n_in,
                              void* d_out, int out_size) {
    const float* feat = (const float*)d_in[0];
    const int* src = (const int*)d_in[1];
    const int* dst = (const int*)d_in[2];
    const float* W1 = (const float*)d_in[3];
    const float* al1 = (const float*)d_in[4];
    const float* ar1 = (const float*)d_in[5];
    const float* b1 = (const float*)d_in[6];
    const float* W2 = (const float*)d_in[7];
    const float* al2 = (const float*)d_in[8];
    const float* ar2 = (const float*)d_in[9];
    const float* b2 = (const float*)d_in[10];
    const float* W3 = (const float*)d_in[11];
    const float* al3 = (const float*)d_in[12];
    const float* ar3 = (const float*)d_in[13];
    const float* b3 = (const float*)d_in[14];

    float* a_hat = (float*)d_out;
    float* x_hat = a_hat + (size_t)NN * NN;
    const int E = in_sizes[1];

    bf16 *feathi, *featlo, *w1thi, *w1tlo, *w2thi, *w2tlo, *w3thi, *w3tlo;
    bf16 *agg1hi, *agg1lo, *h2hi, *h2lo, *agg3hi, *agg3lo;
    float *h1p, *h2p, *h2, *el, *er, *uv;
    int *deg, *cursor, *rowptr, *csrsrc;
    cudaGetSymbolAddress((void**)&feathi, g_feathi);
    cudaGetSymbolAddress((void**)&featlo, g_featlo);
    cudaGetSymbolAddress((void**)&w1thi, g_w1thi);
    cudaGetSymbolAddress((void**)&w1tlo, g_w1tlo);
    cudaGetSymbolAddress((void**)&w2thi, g_w2thi);
    cudaGetSymbolAddress((void**)&w2tlo, g_w2tlo);
    cudaGetSymbolAddress((void**)&w3thi, g_w3thi);
    cudaGetSymbolAddress((void**)&w3tlo, g_w3tlo);
    cudaGetSymbolAddress((void**)&h1p, g_h1p);
    cudaGetSymbolAddress((void**)&agg1hi, g_agg1hi);
    cudaGetSymbolAddress((void**)&agg1lo, g_agg1lo);
    cudaGetSymbolAddress((void**)&h2p, g_h2p);
    cudaGetSymbolAddress((void**)&h2, g_h2);
    cudaGetSymbolAddress((void**)&h2hi, g_h2hi);
    cudaGetSymbolAddress((void**)&h2lo, g_h2lo);
    cudaGetSymbolAddress((void**)&agg3hi, g_agg3hi);
    cudaGetSymbolAddress((void**)&agg3lo, g_agg3lo);
    cudaGetSymbolAddress((void**)&el, g_el);
    cudaGetSymbolAddress((void**)&er, g_er);
    cudaGetSymbolAddress((void**)&uv, g_uv);
    cudaGetSymbolAddress((void**)&deg, g_deg);
    cudaGetSymbolAddress((void**)&cursor, g_cursor);
    cudaGetSymbolAddress((void**)&rowptr, g_rowptr);
    cudaGetSymbolAddress((void**)&csrsrc, g_csrsrc);

    cudaFuncSetAttribute(ahat_hmma, cudaFuncAttributeMaxDynamicSharedMemorySize, AHAT_SMEM);
    cudaFuncSetAttribute(hmma_gemm_el<1>, cudaFuncAttributeMaxDynamicSharedMemorySize, HG_SMEM);
    cudaFuncSetAttribute(hmma_gemm_el<2>, cudaFuncAttributeMaxDynamicSharedMemorySize, HG_SMEM);
    cudaFuncSetAttribute(dec_hmma, cudaFuncAttributeMaxDynamicSharedMemorySize, DEC_SMEM);

    static cudaStream_t s1 = nullptr, s2 = nullptr;
    static cudaEvent_t evRoot, evCSR, evW1, evW, evH2, evAhat;
    if (s1 == nullptr) {
        cudaStreamCreateWithFlags(&s1, cudaStreamNonBlocking);
        cudaStreamCreateWithFlags(&s2, cudaStreamNonBlocking);
        cudaEventCreateWithFlags(&evRoot, cudaEventDisableTiming);
        cudaEventCreateWithFlags(&evCSR, cudaEventDisableTiming);
        cudaEventCreateWithFlags(&evW1, cudaEventDisableTiming);
        cudaEventCreateWithFlags(&evW, cudaEventDisableTiming);
        cudaEventCreateWithFlags(&evH2, cudaEventDisableTiming);
        cudaEventCreateWithFlags(&evAhat, cudaEventDisableTiming);
    }

    float *el1 = el, *el2 = el + NN * 2, *el3 = el + 2 * NN * 2;
    float *er1 = er, *er2 = er + NN * 2, *er3 = er + 2 * NN * 2;

    const int eb = (E + 255) / 256;

    // fork side streams
    cudaEventRecord(evRoot, 0);
    cudaStreamWaitEvent(s1, evRoot, 0);
    cudaStreamWaitEvent(s2, evRoot, 0);

    // ---- s1: CSR build ----
    k_zerodeg<<<(NN + 255) / 256, 256, 0, s1>>>(deg);
    k_deg<<<eb, 256, 0, s1>>>(dst, deg, E);
    k_scan<<<1, 256, 0, s1>>>(deg, rowptr, cursor);
    k_scatter<<<eb, 256, 0, s1>>>(src, dst, cursor, csrsrc, E);
    cudaEventRecord(evCSR, s1);

    // ---- s2: weight packs + decoder attention projection ----
    k_pack_w1t<<<256, 256, 0, s2>>>(W1, w1thi, w1tlo);
    cudaEventRecord(evW1, s2);
    k_pack_w2t<<<128, 256, 0, s2>>>(W2, w2thi, w2tlo);
    k_pack_w3t<<<NDEC, 64, 0, s2>>>(W3, w3thi, w3tlo);
    k_uv<<<16, 256, 0, s2>>>(W3, al3, ar3, uv);
    cudaEventRecord(evW, s2);

    // ---- main stream: layer 1 (el1/er1 fused into GEMM epilogue) ----
    k_pack_feat<<<NN, 256>>>(feat, feathi, featlo);
    cudaStreamWaitEvent(0, evW1, 0);
    {
        dim3 grid(2, 64);
        hmma_gemm_el<1><<<grid, 256, HG_SMEM>>>(feathi, featlo, w1thi, w1tlo, h1p,
                                                FINB, FINB, FINB, 256, al1, ar1, el1, er1);
    }
    cudaStreamWaitEvent(0, evCSR, 0);
    k_agg1<<<NN, 256>>>(rowptr, csrsrc, el1, er1, h1p, b1, agg1hi, agg1lo);

    // ---- layer 2 (el2/er2 fused into GEMM epilogue) ----
    cudaStreamWaitEvent(0, evW, 0);
    {
        dim3 grid(1, 64);
        hmma_gemm_el<2><<<grid, 256, HG_SMEM>>>(agg1hi, agg1lo, w2thi, w2tlo, h2p,
                                                256, 256, 256, 128, al2, ar2, el2, er2);
    }
    k_agg2<<<NN, 128>>>(rowptr, csrsrc, el2, er2, h2p, b2, h2, h2hi, h2lo);
    cudaEventRecord(evH2, 0);

    // ---- s1: structure decoder a_hat (overlaps attribute decoder) ----
    cudaStreamWaitEvent(s1, evH2, 0);
    {
        dim3 grid(NN / 128, NN / 128);
        ahat_hmma<<<grid, 256, AHAT_SMEM, s1>>>(h2hi, h2lo, a_hat);
    }
    cudaEventRecord(evAhat, s1);

    // ---- main stream: attribute decoder ----
    k_elr3<<<(NN * 2 * 32 + 255) / 256, 256>>>(h2, uv, el3, er3);
    k_agg3<<<NN, 128>>>(rowptr, csrsrc, el3, er3, h2, agg3hi, agg3lo);
    {
        dim3 grid(NDEC / 64, NN / 128);
        dec_hmma<<<grid, 256, DEC_SMEM>>>(agg3hi, agg3lo, w3thi, w3tlo, b3, x_hat);
    }

    // join
    cudaStreamWaitEvent(0, evAhat, 0);
}

// round 14
// speedup vs baseline: 1.1274x; 1.0044x over previous
#include <cuda_runtime.h>
#include <cuda_bf16.h>
#include <cstdint>

#define NN 8192
#define FIN 1433
#define FINB 1472      // FIN padded to multiple of 64
#define NDEC 1536      // decoder N padded to multiple of 64
#define MAXE (1 << 20)

typedef unsigned long long u64t;
typedef __nv_bfloat16 bf16;

// ---------------- scratch (device globals) ----------------
__device__ bf16 g_feathi[NN * FINB];
__device__ bf16 g_featlo[NN * FINB];
__device__ bf16 g_w1thi[256 * FINB];
__device__ bf16 g_w1tlo[256 * FINB];
__device__ bf16 g_w2thi[128 * 256];
__device__ bf16 g_w2tlo[128 * 256];
__device__ bf16 g_w3thi[2 * NDEC * 64];
__device__ bf16 g_w3tlo[2 * NDEC * 64];
__device__ float g_h1p[NN * 256];
__device__ bf16 g_agg1hi[NN * 256];
__device__ bf16 g_agg1lo[NN * 256];
__device__ float g_h2p[NN * 128];
__device__ float g_h2[NN * 64];
__device__ bf16 g_h2hi[NN * 64];
__device__ bf16 g_h2lo[NN * 64];
__device__ bf16 g_agg3hi[2 * NN * 64];
__device__ bf16 g_agg3lo[2 * NN * 64];
__device__ float g_el[3 * NN * 2];
__device__ float g_er[3 * NN * 2];
__device__ float g_uv[2 * 64 * 2];
__device__ int g_deg[NN];
__device__ int g_cursor[NN];
__device__ int g_rowptr[NN + 1];
__device__ int g_csrsrc[MAXE];

__device__ __forceinline__ float lrelu(float x, float a) { return x > 0.f ? x : a * x; }

__device__ __forceinline__ uint32_t smem_u32(const void* p) {
    uint32_t a;
    asm("{ .reg .u64 t; cvta.to.shared.u64 t, %1; cvt.u32.u64 %0, t; }" : "=r"(a) : "l"(p));
    return a;
}
__device__ __forceinline__ void ldm_x4(uint32_t* r, uint32_t addr) {
    asm volatile("ldmatrix.sync.aligned.m8n8.x4.shared.b16 {%0,%1,%2,%3}, [%4];"
                 : "=r"(r[0]), "=r"(r[1]), "=r"(r[2]), "=r"(r[3]) : "r"(addr));
}
__device__ __forceinline__ void mma_bf16(float* c, const uint32_t* a, uint32_t b0, uint32_t b1) {
    asm volatile(
        "mma.sync.aligned.m16n8k16.row.col.f32.bf16.bf16.f32 "
        "{%0,%1,%2,%3}, {%4,%5,%6,%7}, {%8,%9}, {%0,%1,%2,%3};"
        : "+f"(c[0]), "+f"(c[1]), "+f"(c[2]), "+f"(c[3])
        : "r"(a[0]), "r"(a[1]), "r"(a[2]), "r"(a[3]), "r"(b0), "r"(b1));
}
__device__ __forceinline__ void split_bf16(float v, bf16* hi, bf16* lo) {
    bf16 h = __float2bfloat16(v);
    *hi = h;
    *lo = __float2bfloat16(v - __bfloat162float(h));
}
__device__ __forceinline__ void cp16(uint32_t dst, const void* src) {
    asm volatile("cp.async.cg.shared.global [%0], [%1], 16;" :: "r"(dst), "l"(src));
}
__device__ __forceinline__ void st_cs_f2(float* p, float a, float b) {
    asm volatile("st.global.cs.v2.f32 [%0], {%1, %2};" :: "l"(p), "f"(a), "f"(b) : "memory");
}

#define APITCH 72    // bf16 per smem row (144B) — conflict-free ldmatrix
#define TILEB 18432  // one 128xAPITCH bf16 tile in bytes

// ================= bf16-split HMMA GEMM + fused el/er epilogue =================
#define HG_SMEM (8 * TILEB)  // 147456 B

template <int ELMODE>
__global__ void __launch_bounds__(256)
hmma_gemm_el(const bf16* __restrict__ Ahi, const bf16* __restrict__ Alo,
             const bf16* __restrict__ Bhi, const bf16* __restrict__ Blo,
             float* __restrict__ C, int K, int lda, int ldb, int ldc,
             const float* __restrict__ al, const float* __restrict__ ar,
             float* __restrict__ el, float* __restrict__ er) {
    extern __shared__ char smem[];
    const uint32_t sb = smem_u32(smem);
    const int tid = threadIdx.x, wid = tid >> 5, lane = tid & 31;
    const int rowBase = blockIdx.y * 128, colBase = blockIdx.x * 128;
    const int wm = (wid & 3) * 32, wn = (wid >> 2) * 64;
    const int lrow = lane & 15, lch = lane >> 4;
    const int nk = K >> 6;

    float acc[2][8][4];
#pragma unroll
    for (int i = 0; i < 2; i++)
#pragma unroll
        for (int j = 0; j < 8; j++)
#pragma unroll
            for (int q = 0; q < 4; q++) acc[i][j][q] = 0.f;

    auto stage = [&](int buf, int kc) {
        uint32_t base = sb + buf * (4 * TILEB);
        for (int idx = tid; idx < 1024; idx += 256) {
            int row = idx >> 3, ch = idx & 7;
            uint32_t off = (uint32_t)(row * APITCH + ch * 8) * 2;
            cp16(base + off, Ahi + (size_t)(rowBase + row) * lda + kc + ch * 8);
            cp16(base + TILEB + off, Alo + (size_t)(rowBase + row) * lda + kc + ch * 8);
            cp16(base + 2 * TILEB + off, Bhi + (size_t)(colBase + row) * ldb + kc + ch * 8);
            cp16(base + 3 * TILEB + off, Blo + (size_t)(colBase + row) * ldb + kc + ch * 8);
        }
        asm volatile("cp.async.commit_group;" ::: "memory");
    };

    stage(0, 0);
    for (int t = 0; t < nk; ++t) {
        asm volatile("cp.async.wait_group 0;" ::: "memory");
        __syncthreads();
        if (t + 1 < nk) stage((t + 1) & 1, (t + 1) * 64);
        const uint32_t base = sb + (t & 1) * (4 * TILEB);
        const uint32_t bAhi = base, bAlo = base + TILEB;
        const uint32_t bBhi = base + 2 * TILEB, bBlo = base + 3 * TILEB;
#pragma unroll
        for (int ks = 0; ks < 4; ks++) {
            uint32_t afh[2][4], afl[2][4];
#pragma unroll
            for (int i = 0; i < 2; i++) {
                uint32_t ao = ((wm + i * 16 + lrow) * APITCH) * 2 + (ks * 2 + lch) * 16;
                ldm_x4(afh[i], bAhi + ao);
                ldm_x4(afl[i], bAlo + ao);
            }
            uint32_t bfh[8][2], bfl[8][2];
#pragma unroll
            for (int jj = 0; jj < 4; jj++) {
                uint32_t bo = ((wn + jj * 16 + lrow) * APITCH) * 2 + (ks * 2 + lch) * 16;
                uint32_t r[4];
                ldm_x4(r, bBhi + bo);
                bfh[2 * jj][0] = r[0]; bfh[2 * jj][1] = r[2];
                bfh[2 * jj + 1][0] = r[1]; bfh[2 * jj + 1][1] = r[3];
                ldm_x4(r, bBlo + bo);
                bfl[2 * jj][0] = r[0]; bfl[2 * jj][1] = r[2];
                bfl[2 * jj + 1][0] = r[1]; bfl[2 * jj + 1][1] = r[3];
            }
#pragma unroll
            for (int i = 0; i < 2; i++)
#pragma unroll
                for (int j = 0; j < 8; j++) {
                    mma_bf16(acc[i][j], afh[i], bfh[j][0], bfh[j][1]);
                    mma_bf16(acc[i][j], afh[i], bfl[j][0], bfl[j][1]);
                    mma_bf16(acc[i][j], afl[i], bfh[j][0], bfh[j][1]);
                }
        }
        __syncthreads();
    }

    const int rr = lane >> 2, cc = (lane & 3) * 2;

#pragma unroll
    for (int i = 0; i < 2; i++) {
        int gr = rowBase + wm + i * 16 + rr;
        float* out0 = C + (size_t)gr * ldc + colBase + wn + cc;
        float* out1 = out0 + 8 * ldc;
#pragma unroll
        for (int j = 0; j < 8; j++) {
            *(float2*)(out0 + j * 8) = make_float2(acc[i][j][0], acc[i][j][1]);
            *(float2*)(out1 + j * 8) = make_float2(acc[i][j][2], acc[i][j][3]);
        }
    }

    // ---- fused el/er epilogue ----
    float2 alv[8], arv[8];
#pragma unroll
    for (int j = 0; j < 8; j++) {
        int c = colBase + wn + j * 8 + cc;
        alv[j] = make_float2(__ldg(al + c), __ldg(al + c + 1));
        arv[j] = make_float2(__ldg(ar + c), __ldg(ar + c + 1));
    }
    float pel[2][2], prr[2][2];
#pragma unroll
    for (int i = 0; i < 2; i++)
#pragma unroll
        for (int half = 0; half < 2; half++) {
            float se = 0.f, sr = 0.f;
#pragma unroll
            for (int j = 0; j < 8; j++) {
                se = fmaf(acc[i][j][half * 2], alv[j].x, se);
                se = fmaf(acc[i][j][half * 2 + 1], alv[j].y, se);
                sr = fmaf(acc[i][j][half * 2], arv[j].x, sr);
                sr = fmaf(acc[i][j][half * 2 + 1], arv[j].y, sr);
            }
            pel[i][half] = se;
            prr[i][half] = sr;
        }
#pragma unroll
    for (int o = 1; o <= 2; o <<= 1) {
#pragma unroll
        for (int i = 0; i < 2; i++)
#pragma unroll
            for (int half = 0; half < 2; half++) {
                pel[i][half] += __shfl_xor_sync(0xffffffffu, pel[i][half], o);
                prr[i][half] += __shfl_xor_sync(0xffffffffu, prr[i][half], o);
            }
    }
    if (ELMODE == 2) {
        if ((lane & 3) == 0) {
            int head = wn >> 6;
#pragma unroll
            for (int i = 0; i < 2; i++)
#pragma unroll
                for (int half = 0; half < 2; half++) {
                    int gr = rowBase + wm + i * 16 + rr + half * 8;
                    el[(size_t)gr * 2 + head] = pel[i][half];
                    er[(size_t)gr * 2 + head] = prr[i][half];
                }
        }
    } else {
        float* sel = (float*)smem;
        float* ser = sel + 256;
        if ((lane & 3) == 0) {
#pragma unroll
            for (int i = 0; i < 2; i++)
#pragma unroll
                for (int half = 0; half < 2; half++) {
                    int r = wm + i * 16 + rr + half * 8;
                    sel[r * 2 + (wid >> 2)] = pel[i][half];
                    ser[r * 2 + (wid >> 2)] = prr[i][half];
                }
        }
        __syncthreads();
        if (tid < 128) {
            int head = colBase >> 7;
            el[(size_t)(rowBase + tid) * 2 + head] = sel[tid * 2] + sel[tid * 2 + 1];
            er[(size_t)(rowBase + tid) * 2 + head] = ser[tid * 2] + ser[tid * 2 + 1];
        }
    }
}

// ================= a_hat HMMA (128x128, K=64), streaming stores =================
#define AHAT_SMEM (4 * TILEB)

__global__ void __launch_bounds__(256)
ahat_hmma(const bf16* __restrict__ hi, const bf16* __restrict__ lo, float* __restrict__ C) {
    extern __shared__ char smem[];
    bf16* sAhi = (bf16*)(smem);
    bf16* sAlo = (bf16*)(smem + TILEB);
    bf16* sBhi = (bf16*)(smem + 2 * TILEB);
    bf16* sBlo = (bf16*)(smem + 3 * TILEB);
    const int tid = threadIdx.x, wid = tid >> 5, lane = tid & 31;
    const int rowBase = blockIdx.y * 128, colBase = blockIdx.x * 128;

    for (int idx = tid; idx < 128 * 8; idx += 256) {
        int row = idx >> 3, ch = idx & 7;
        int off = row * APITCH + ch * 8;
        *(uint4*)(sAhi + off) = *((const uint4*)(hi + (size_t)(rowBase + row) * 64) + ch);
        *(uint4*)(sAlo + off) = *((const uint4*)(lo + (size_t)(rowBase + row) * 64) + ch);
        *(uint4*)(sBhi + off) = *((const uint4*)(hi + (size_t)(colBase + row) * 64) + ch);
        *(uint4*)(sBlo + off) = *((const uint4*)(lo + (size_t)(colBase + row) * 64) + ch);
    }
    __syncthreads();

    const int wm = (wid & 3) * 32, wn = (wid >> 2) * 64;
    float acc[2][8][4];
#pragma unroll
    for (int i = 0; i < 2; i++)
#pragma unroll
        for (int j = 0; j < 8; j++)
#pragma unroll
            for (int q = 0; q < 4; q++) acc[i][j][q] = 0.f;

    const int lrow = lane & 15, lch = lane >> 4;
    const uint32_t sbAhi = smem_u32(sAhi), sbAlo = smem_u32(sAlo);
    const uint32_t sbBhi = smem_u32(sBhi), sbBlo = smem_u32(sBlo);

#pragma unroll
    for (int pass = 0; pass < 3; pass++) {
        const uint32_t aBase = (pass == 2) ? sbAlo : sbAhi;
        const uint32_t bBase = (pass == 1) ? sbBlo : sbBhi;
#pragma unroll
        for (int ks = 0; ks < 4; ks++) {
            uint32_t af[2][4];
#pragma unroll
            for (int i = 0; i < 2; i++)
                ldm_x4(af[i], aBase + ((wm + i * 16 + lrow) * APITCH) * 2 + (ks * 2 + lch) * 16);
            uint32_t bf[8][2];
#pragma unroll
            for (int jj = 0; jj < 4; jj++) {
                uint32_t r[4];
                ldm_x4(r, bBase + ((wn + jj * 16 + lrow) * APITCH) * 2 + (ks * 2 + lch) * 16);
                bf[2 * jj][0] = r[0]; bf[2 * jj][1] = r[2];
                bf[2 * jj + 1][0] = r[1]; bf[2 * jj + 1][1] = r[3];
            }
#pragma unroll
            for (int i = 0; i < 2; i++)
#pragma unroll
                for (int j = 0; j < 8; j++)
                    mma_bf16(acc[i][j], af[i], bf[j][0], bf[j][1]);
        }
    }

    const int rr = lane >> 2, cc = (lane & 3) * 2;
#pragma unroll
    for (int i = 0; i < 2; i++) {
        int gr = rowBase + wm + i * 16 + rr;
        float* out0 = C + (size_t)gr * NN + colBase + wn + cc;
        float* out1 = out0 + 8 * NN;
#pragma unroll
        for (int j = 0; j < 8; j++) {
            st_cs_f2(out0 + j * 8, acc[i][j][0], acc[i][j][1]);
            st_cs_f2(out1 + j * 8, acc[i][j][2], acc[i][j][3]);
        }
    }
}

// ================= fused decoder HMMA (2 heads + bias + lrelu + mean) =================
#define DEC_SMEM (2 * TILEB + TILEB)

__global__ void __launch_bounds__(256)
dec_hmma(const bf16* __restrict__ Ahi, const bf16* __restrict__ Alo,
         const bf16* __restrict__ Bhi, const bf16* __restrict__ Blo,
         const float* __restrict__ b3, float* __restrict__ xhat) {
    extern __shared__ char smem[];
    bf16* sAhi = (bf16*)smem;
    bf16* sAlo = (bf16*)(smem + TILEB);
    bf16* sBhi = (bf16*)(smem + 2 * TILEB);
    bf16* sBlo = (bf16*)(smem + 2 * TILEB + TILEB / 2);
    const int tid = threadIdx.x, wid = tid >> 5, lane = tid & 31;
    const int rowBase = blockIdx.y * 128, colBase = blockIdx.x * 64;
    const int wm = (wid & 3) * 32, wn = (wid >> 2) * 32;
    const int lrow = lane & 15, lch = lane >> 4;

    float acc[2][2][4][4];
#pragma unroll
    for (int h = 0; h < 2; h++)
#pragma unroll
        for (int i = 0; i < 2; i++)
#pragma unroll
            for (int j = 0; j < 4; j++)
#pragma unroll
                for (int q = 0; q < 4; q++) acc[h][i][j][q] = 0.f;

    const uint32_t sbAhi = smem_u32(sAhi), sbAlo = smem_u32(sAlo);
    const uint32_t sbBhi = smem_u32(sBhi), sbBlo = smem_u32(sBlo);

#pragma unroll
    for (int h = 0; h < 2; h++) {
        const bf16* ahp = Ahi + (size_t)h * NN * 64;
        const bf16* alp = Alo + (size_t)h * NN * 64;
        const bf16* bhp = Bhi + (size_t)h * NDEC * 64;
        const bf16* blp = Blo + (size_t)h * NDEC * 64;
        __syncthreads();
        for (int idx = tid; idx < 1024; idx += 256) {
            int row = idx >> 3, ch = idx & 7;
            int off = row * APITCH + ch * 8;
            *(uint4*)(sAhi + off) = *(const uint4*)(ahp + (size_t)(rowBase + row) * 64 + ch * 8);
            *(uint4*)(sAlo + off) = *(const uint4*)(alp + (size_t)(rowBase + row) * 64 + ch * 8);
        }
        for (int idx = tid; idx < 512; idx += 256) {
            int row = idx >> 3, ch = idx & 7;
            int off = row * APITCH + ch * 8;
            *(uint4*)(sBhi + off) = *(const uint4*)(bhp + (size_t)(colBase + row) * 64 + ch * 8);
            *(uint4*)(sBlo + off) = *(const uint4*)(blp + (size_t)(colBase + row) * 64 + ch * 8);
        }
        __syncthreads();
#pragma unroll
        for (int ks = 0; ks < 4; ks++) {
            uint32_t afh[2][4], afl[2][4];
#pragma unroll
            for (int i = 0; i < 2; i++) {
                uint32_t ao = ((wm + i * 16 + lrow) * APITCH) * 2 + (ks * 2 + lch) * 16;
                ldm_x4(afh[i], sbAhi + ao);
                ldm_x4(afl[i], sbAlo + ao);
            }
            uint32_t bfh[4][2], bfl[4][2];
#pragma unroll
            for (int jj = 0; jj < 2; jj++) {
                uint32_t bo = ((wn + jj * 16 + lrow) * APITCH) * 2 + (ks * 2 + lch) * 16;
                uint32_t r[4];
                ldm_x4(r, sbBhi + bo);
                bfh[2 * jj][0] = r[0]; bfh[2 * jj][1] = r[2];
                bfh[2 * jj + 1][0] = r[1]; bfh[2 * jj + 1][1] = r[3];
                ldm_x4(r, sbBlo + bo);
                bfl[2 * jj][0] = r[0]; bfl[2 * jj][1] = r[2];
                bfl[2 * jj + 1][0] = r[1]; bfl[2 * jj + 1][1] = r[3];
            }
#pragma unroll
            for (int i = 0; i < 2; i++)
#pragma unroll
                for (int j = 0; j < 4; j++) {
                    mma_bf16(acc[h][i][j], afh[i], bfh[j][0], bfh[j][1]);
                    mma_bf16(acc[h][i][j], afh[i], bfl[j][0], bfl[j][1]);
                    mma_bf16(acc[h][i][j], afl[i], bfh[j][0], bfh[j][1]);
                }
        }
    }

    const int rr = lane >> 2, cc = (lane & 3) * 2;
#pragma unroll
    for (int i = 0; i < 2; i++) {
#pragma unroll
        for (int j = 0; j < 4; j++) {
#pragma unroll
            for (int half = 0; half < 2; half++) {
                int gr = rowBase + wm + i * 16 + rr + half * 8;
                int gn = colBase + wn + j * 8 + cc;
                if (gn < FIN) {
                    float v0 = acc[0][i][j][half * 2], v1 = acc[1][i][j][half * 2];
                    xhat[(size_t)gr * FIN + gn] =
                        0.5f * (lrelu(v0 + b3[gn], 0.01f) + lrelu(v1 + b3[FIN + gn], 0.01f));
                }
                if (gn + 1 < FIN) {
                    float v0 = acc[0][i][j][half * 2 + 1], v1 = acc[1][i][j][half * 2 + 1];
                    xhat[(size_t)gr * FIN + gn + 1] =
                        0.5f * (lrelu(v0 + b3[gn + 1], 0.01f) + lrelu(v1 + b3[FIN + gn + 1], 0.01f));
                }
            }
        }
    }
}

// ================= CSR build =================
__global__ void k_zerodeg(int* deg) {
    int i = blockIdx.x * blockDim.x + threadIdx.x;
    if (i < NN) deg[i] = 0;
}
__global__ void k_deg(const int* __restrict__ dst, int* deg, int E) {
    int e = blockIdx.x * blockDim.x + threadIdx.x;
    if (e < E) atomicAdd(&deg[dst[e]], 1);
}
__global__ void k_scan(const int* __restrict__ deg, int* rowptr, int* cursor) {
    __shared__ int partx[257];
    int t = threadIdx.x;
    int base = t * 32;
    int loc[32];
    int s = 0;
#pragma unroll
    for (int i = 0; i < 32; i++) { loc[i] = s; s += deg[base + i]; }
    __shared__ int part[256];
    part[t] = s;
    __syncthreads();
    if (t == 0) {
        int acc = 0;
        for (int i = 0; i < 256; i++) { partx[i] = acc; acc += part[i]; }
        partx[256] = acc;
    }
    __syncthreads();
    int off = partx[t];
#pragma unroll
    for (int i = 0; i < 32; i++) {
        int v = off + loc[i];
        rowptr[base + i] = v;
        cursor[base + i] = v;
    }
    if (t == 0) rowptr[NN] = partx[256];
}
__global__ void k_scatter(const int* __restrict__ src, const int* __restrict__ dst,
                          int* cursor, int* csrsrc, int E) {
    int e = blockIdx.x * blockDim.x + threadIdx.x;
    if (e >= E) return;
    int d = dst[e];
    int idx = atomicAdd(&cursor[d], 1);
    csrsrc[idx] = src[e];
}

// ================= pack kernels (coalesced smem-tiled transposes) =================
__global__ void k_pack_feat(const float* __restrict__ feat, bf16* __restrict__ fhi,
                            bf16* __restrict__ flo) {
    int n = blockIdx.x;
    for (int f = threadIdx.x; f < FINB; f += blockDim.x) {
        float v = (f < FIN) ? feat[(size_t)n * FIN + f] : 0.f;
        split_bf16(v, &fhi[(size_t)n * FINB + f], &flo[(size_t)n * FINB + f]);
    }
}
// W1 [FIN,256] -> w1t [256,FINB]; 32x32 tile transpose
__global__ void __launch_bounds__(256)
k_pack_w1t(const float* __restrict__ W1, bf16* __restrict__ whi, bf16* __restrict__ wlo) {
    __shared__ float tile[32][33];
    int kbase = blockIdx.x * 32, nbase = blockIdx.y * 32;
    int tx = threadIdx.x & 31, ty = threadIdx.x >> 5;  // 32x8
#pragma unroll
    for (int r = ty; r < 32; r += 8) {
        int k = kbase + r;
        tile[r][tx] = (k < FIN) ? W1[(size_t)k * 256 + nbase + tx] : 0.f;
    }
    __syncthreads();
#pragma unroll
    for (int r = ty; r < 32; r += 8) {
        int n = nbase + r, k = kbase + tx;
        split_bf16(tile[tx][r], &whi[(size_t)n * FINB + k], &wlo[(size_t)n * FINB + k]);
    }
}
// W2 [256,128] -> w2t [128,256]
__global__ void __launch_bounds__(256)
k_pack_w2t(const float* __restrict__ W2, bf16* __restrict__ whi, bf16* __restrict__ wlo) {
    __shared__ float tile[32][33];
    int kbase = blockIdx.x * 32, nbase = blockIdx.y * 32;
    int tx = threadIdx.x & 31, ty = threadIdx.x >> 5;
#pragma unroll
    for (int r = ty; r < 32; r += 8)
        tile[r][tx] = W2[(size_t)(kbase + r) * 128 + nbase + tx];
    __syncthreads();
#pragma unroll
    for (int r = ty; r < 32; r += 8) {
        int n = nbase + r, k = kbase + tx;
        split_bf16(tile[tx][r], &whi[(size_t)n * 256 + k], &wlo[(size_t)n * 256 + k]);
    }
}
// W3 [64, 2*FIN] -> w3t [h][NDEC][64]
__global__ void __launch_bounds__(256)
k_pack_w3t(const float* __restrict__ W3, bf16* __restrict__ whi, bf16* __restrict__ wlo) {
    __shared__ float tile[32][33];
    int h = blockIdx.z;
    int fbase = blockIdx.x * 32, kbase = blockIdx.y * 32;
    int tx = threadIdx.x & 31, ty = threadIdx.x >> 5;
#pragma unroll
    for (int r = ty; r < 32; r += 8) {
        int k = kbase + r, f = fbase + tx;
        tile[r][tx] = (f < FIN) ? W3[(size_t)k * (2 * FIN) + h * FIN + f] : 0.f;
    }
    __syncthreads();
#pragma unroll
    for (int r = ty; r < 32; r += 8) {
        int f = fbase + r, k = kbase + tx;
        split_bf16(tile[tx][r], &whi[((size_t)h * NDEC + f) * 64 + k],
                   &wlo[((size_t)h * NDEC + f) * 64 + k]);
    }
}

// ================= attention logits (layer 3 only) =================
__global__ void k_uv(const float* __restrict__ W3, const float* __restrict__ al3,
                     const float* __restrict__ ar3, float* uv) {
    int w = (blockIdx.x * blockDim.x + threadIdx.x) >> 5;
    int lane = threadIdx.x & 31;
    if (w >= 128) return;
    int h = w >> 6, k = w & 63;
    const float* Wr = W3 + (size_t)k * (2 * FIN) + h * FIN;
    const float* a = al3 + (size_t)h * FIN;
    const float* b = ar3 + (size_t)h * FIN;
    float su = 0.f, sv = 0.f;
    for (int f = lane; f < FIN; f += 32) { float ww = Wr[f]; su += ww * a[f]; sv += ww * b[f]; }
#pragma unroll
    for (int o = 16; o; o >>= 1) {
        su += __shfl_down_sync(0xffffffffu, su, o);
        sv += __shfl_down_sync(0xffffffffu, sv, o);
    }
    if (lane == 0) { uv[h * 64 + k] = su; uv[128 + h * 64 + k] = sv; }
}

__global__ void k_elr3(const float* __restrict__ h2, const float* __restrict__ uv,
                       float* el, float* er) {
    int w = (blockIdx.x * blockDim.x + threadIdx.x) >> 5;
    int lane = threadIdx.x & 31;
    if (w >= NN * 2) return;
    int n = w >> 1, h = w & 1;
    const float* row = h2 + (size_t)n * 64;
    const float* u = uv + h * 64;
    const float* v = uv + 128 + h * 64;
    float sl = 0.f, sr = 0.f;
    for (int d = lane; d < 64; d += 32) { float x = row[d]; sl += x * u[d]; sr += x * v[d]; }
#pragma unroll
    for (int o = 16; o; o >>= 1) {
        sl += __shfl_down_sync(0xffffffffu, sl, o);
        sr += __shfl_down_sync(0xffffffffu, sr, o);
    }
    if (lane == 0) { el[w] = sl; er[w] = sr; }
}

// ================= block softmax-sum helper =================
template <int NT>
__device__ __forceinline__ float2 block_inv_sum(const int* csrsrc, int b, int en,
                                                const float* el, float2 r,
                                                float* red, float2* out_sh) {
    int t = threadIdx.x, lane = t & 31, wid = t >> 5;
    float p0 = 0.f, p1 = 0.f;
    for (int i = b + t; i < en; i += NT) {
        int s = csrsrc[i];
        float2 l = *(const float2*)&el[s * 2];
        float e0 = l.x + r.x; e0 = e0 > 0.f ? e0 : 0.2f * e0;
        float e1 = l.y + r.y; e1 = e1 > 0.f ? e1 : 0.2f * e1;
        p0 += __expf(e0); p1 += __expf(e1);
    }
#pragma unroll
    for (int o = 16; o; o >>= 1) {
        p0 += __shfl_down_sync(0xffffffffu, p0, o);
        p1 += __shfl_down_sync(0xffffffffu, p1, o);
    }
    if (lane == 0) { red[wid * 2] = p0; red[wid * 2 + 1] = p1; }
    __syncthreads();
    if (t == 0) {
        float s0 = 0.f, s1 = 0.f;
        for (int w = 0; w < NT / 32; w++) { s0 += red[w * 2]; s1 += red[w * 2 + 1]; }
        *out_sh = make_float2(1.f / s0, 1.f / s1);
    }
    __syncthreads();
    return *out_sh;
}

// ================= CSR gather aggregation (lean) =================
__global__ void __launch_bounds__(256)
k_agg1(const int* __restrict__ rowptr, const int* __restrict__ csrsrc,
       const float* __restrict__ el, const float* __restrict__ er,
       const float* __restrict__ hp, const float* __restrict__ b1,
       bf16* __restrict__ ohi, bf16* __restrict__ olo) {
    int d = blockIdx.x;
    int t = threadIdx.x;
    __shared__ float2 sal[128];
    __shared__ int ssrc[128];
    __shared__ float red[16];
    __shared__ float2 inv_sh;
    int b = rowptr[d], en = rowptr[d + 1];
    float2 r = *(const float2*)&er[d * 2];
    float2 inv = block_inv_sum<256>(csrsrc, b, en, el, r, red, &inv_sh);
    float acc = 0.f;
    int h = t >> 7;
    for (int c = b; c < en; c += 128) {
        int cnt = min(128, en - c);
        __syncthreads();
        if (t < cnt) {
            int s = csrsrc[c + t];
            float2 l = *(const float2*)&el[s * 2];
            float e0 = l.x + r.x; e0 = e0 > 0.f ? e0 : 0.2f * e0;
            float e1 = l.y + r.y; e1 = e1 > 0.f ? e1 : 0.2f * e1;
            sal[t] = make_float2(__expf(e0) * inv.x, __expf(e1) * inv.y);
            ssrc[t] = s;
        }
        __syncthreads();
#pragma unroll 4
        for (int i = 0; i < cnt; i++) {
            float a = h ? sal[i].y : sal[i].x;
            acc = fmaf(a, hp[(size_t)ssrc[i] * 256 + t], acc);
        }
    }
    float x = lrelu(acc + b1[t], 0.01f);
    split_bf16(x, &ohi[(size_t)d * 256 + t], &olo[(size_t)d * 256 + t]);
}

__global__ void __launch_bounds__(128)
k_agg2(const int* __restrict__ rowptr, const int* __restrict__ csrsrc,
       const float* __restrict__ el, const float* __restrict__ er,
       const float* __restrict__ hp, const float* __restrict__ b2,
       float* __restrict__ h2, bf16* __restrict__ h2hi, bf16* __restrict__ h2lo) {
    int d = blockIdx.x;
    int t = threadIdx.x;
    __shared__ float2 sal[128];
    __shared__ int ssrc[128];
    __shared__ float o[128];
    __shared__ float red[8];
    __shared__ float2 inv_sh;
    int b = rowptr[d], en = rowptr[d + 1];
    float2 r = *(const float2*)&er[d * 2];
    float2 inv = block_inv_sum<128>(csrsrc, b, en, el, r, red, &inv_sh);
    float acc = 0.f;
    int h = t >> 6;
    for (int c = b; c < en; c += 128) {
        int cnt = min(128, en - c);
        __syncthreads();
        if (t < cnt) {
            int s = csrsrc[c + t];
            float2 l = *(const float2*)&el[s * 2];
            float e0 = l.x + r.x; e0 = e0 > 0.f ? e0 : 0.2f * e0;
            float e1 = l.y + r.y; e1 = e1 > 0.f ? e1 : 0.2f * e1;
            sal[t] = make_float2(__expf(e0) * inv.x, __expf(e1) * inv.y);
            ssrc[t] = s;
        }
        __syncthreads();
#pragma unroll 4
        for (int i = 0; i < cnt; i++) {
            float a = h ? sal[i].y : sal[i].x;
            acc = fmaf(a, hp[(size_t)ssrc[i] * 128 + t], acc);
        }
    }
    o[t] = acc;
    __syncthreads();
    if (t < 64) {
        float x0 = lrelu(o[t] + b2[t], 0.01f);
        float x1 = lrelu(o[64 + t] + b2[64 + t], 0.01f);
        float v = 0.5f * (x0 + x1);
        h2[(size_t)d * 64 + t] = v;
        split_bf16(v, &h2hi[(size_t)d * 64 + t], &h2lo[(size_t)d * 64 + t]);
    }
}

__global__ void __launch_bounds__(128)
k_agg3(const int* __restrict__ rowptr, const int* __restrict__ csrsrc,
       const float* __restrict__ el, const float* __restrict__ er,
       const float* __restrict__ h2, bf16* __restrict__ ahi, bf16* __restrict__ alo) {
    int d = blockIdx.x;
    int t = threadIdx.x;
    __shared__ float2 sal[128];
    __shared__ int ssrc[128];
    __shared__ float red[8];
    __shared__ float2 inv_sh;
    int b = rowptr[d], en = rowptr[d + 1];
    float2 r = *(const float2*)&er[d * 2];
    float2 inv = block_inv_sum<128>(csrsrc, b, en, el, r, red, &inv_sh);
    float acc = 0.f;
    int h = t >> 6, dd = t & 63;
    for (int c = b; c < en; c += 128) {
        int cnt = min(128, en - c);
        __syncthreads();
        if (t < cnt) {
            int s = csrsrc[c + t];
            float2 l = *(const float2*)&el[s * 2];
            float e0 = l.x + r.x; e0 = e0 > 0.f ? e0 : 0.2f * e0;
            float e1 = l.y + r.y; e1 = e1 > 0.f ? e1 : 0.2f * e1;
            sal[t] = make_float2(__expf(e0) * inv.x, __expf(e1) * inv.y);
            ssrc[t] = s;
        }
        __syncthreads();
#pragma unroll 4
        for (int i = 0; i < cnt; i++) {
            float a = h ? sal[i].y : sal[i].x;
            acc = fmaf(a, h2[(size_t)ssrc[i] * 64 + dd], acc);
        }
    }
    size_t idx = ((size_t)h * NN + d) * 64 + dd;
    split_bf16(acc, &ahi[idx], &alo[idx]);
}

// ================= launch =================
extern "C" void kernel_launch(void* const* d_in, const int* in_sizes, int n_in,
                              void* d_out, int out_size) {
    const float* feat = (const float*)d_in[0];
    const int* src = (const int*)d_in[1];
    const int* dst = (const int*)d_in[2];
    const float* W1 = (const float*)d_in[3];
    const float* al1 = (const float*)d_in[4];
    const float* ar1 = (const float*)d_in[5];
    const float* b1 = (const float*)d_in[6];
    const float* W2 = (const float*)d_in[7];
    const float* al2 = (const float*)d_in[8];
    const float* ar2 = (const float*)d_in[9];
    const float* b2 = (const float*)d_in[10];
    const float* W3 = (const float*)d_in[11];
    const float* al3 = (const float*)d_in[12];
    const float* ar3 = (const float*)d_in[13];
    const float* b3 = (const float*)d_in[14];

    float* a_hat = (float*)d_out;
    float* x_hat = a_hat + (size_t)NN * NN;
    const int E = in_sizes[1];

    bf16 *feathi, *featlo, *w1thi, *w1tlo, *w2thi, *w2tlo, *w3thi, *w3tlo;
    bf16 *agg1hi, *agg1lo, *h2hi, *h2lo, *agg3hi, *agg3lo;
    float *h1p, *h2p, *h2, *el, *er, *uv;
    int *deg, *cursor, *rowptr, *csrsrc;
    cudaGetSymbolAddress((void**)&feathi, g_feathi);
    cudaGetSymbolAddress((void**)&featlo, g_featlo);
    cudaGetSymbolAddress((void**)&w1thi, g_w1thi);
    cudaGetSymbolAddress((void**)&w1tlo, g_w1tlo);
    cudaGetSymbolAddress((void**)&w2thi, g_w2thi);
    cudaGetSymbolAddress((void**)&w2tlo, g_w2tlo);
    cudaGetSymbolAddress((void**)&w3thi, g_w3thi);
    cudaGetSymbolAddress((void**)&w3tlo, g_w3tlo);
    cudaGetSymbolAddress((void**)&h1p, g_h1p);
    cudaGetSymbolAddress((void**)&agg1hi, g_agg1hi);
    cudaGetSymbolAddress((void**)&agg1lo, g_agg1lo);
    cudaGetSymbolAddress((void**)&h2p, g_h2p);
    cudaGetSymbolAddress((void**)&h2, g_h2);
    cudaGetSymbolAddress((void**)&h2hi, g_h2hi);
    cudaGetSymbolAddress((void**)&h2lo, g_h2lo);
    cudaGetSymbolAddress((void**)&agg3hi, g_agg3hi);
    cudaGetSymbolAddress((void**)&agg3lo, g_agg3lo);
    cudaGetSymbolAddress((void**)&el, g_el);
    cudaGetSymbolAddress((void**)&er, g_er);
    cudaGetSymbolAddress((void**)&uv, g_uv);
    cudaGetSymbolAddress((void**)&deg, g_deg);
    cudaGetSymbolAddress((void**)&cursor, g_cursor);
    cudaGetSymbolAddress((void**)&rowptr, g_rowptr);
    cudaGetSymbolAddress((void**)&csrsrc, g_csrsrc);

    cudaFuncSetAttribute(ahat_hmma, cudaFuncAttributeMaxDynamicSharedMemorySize, AHAT_SMEM);
    cudaFuncSetAttribute(hmma_gemm_el<1>, cudaFuncAttributeMaxDynamicSharedMemorySize, HG_SMEM);
    cudaFuncSetAttribute(hmma_gemm_el<2>, cudaFuncAttributeMaxDynamicSharedMemorySize, HG_SMEM);
    cudaFuncSetAttribute(dec_hmma, cudaFuncAttributeMaxDynamicSharedMemorySize, DEC_SMEM);

    static cudaStream_t s1 = nullptr, s2 = nullptr;
    static cudaEvent_t evRoot, evCSR, evW1, evW, evH2, evAhat;
    if (s1 == nullptr) {
        cudaStreamCreateWithFlags(&s1, cudaStreamNonBlocking);
        cudaStreamCreateWithFlags(&s2, cudaStreamNonBlocking);
        cudaEventCreateWithFlags(&evRoot, cudaEventDisableTiming);
        cudaEventCreateWithFlags(&evCSR, cudaEventDisableTiming);
        cudaEventCreateWithFlags(&evW1, cudaEventDisableTiming);
        cudaEventCreateWithFlags(&evW, cudaEventDisableTiming);
        cudaEventCreateWithFlags(&evH2, cudaEventDisableTiming);
        cudaEventCreateWithFlags(&evAhat, cudaEventDisableTiming);
    }

    float *el1 = el, *el2 = el + NN * 2, *el3 = el + 2 * NN * 2;
    float *er1 = er, *er2 = er + NN * 2, *er3 = er + 2 * NN * 2;

    const int eb = (E + 255) / 256;

    // fork side streams
    cudaEventRecord(evRoot, 0);
    cudaStreamWaitEvent(s1, evRoot, 0);
    cudaStreamWaitEvent(s2, evRoot, 0);

    // ---- s1: CSR build ----
    k_zerodeg<<<(NN + 255) / 256, 256, 0, s1>>>(deg);
    k_deg<<<eb, 256, 0, s1>>>(dst, deg, E);
    k_scan<<<1, 256, 0, s1>>>(deg, rowptr, cursor);
    k_scatter<<<eb, 256, 0, s1>>>(src, dst, cursor, csrsrc, E);
    cudaEventRecord(evCSR, s1);

    // ---- s2: weight packs (coalesced transposes) + decoder attention projection ----
    {
        dim3 g(FINB / 32, 8);
        k_pack_w1t<<<g, 256, 0, s2>>>(W1, w1thi, w1tlo);
    }
    cudaEventRecord(evW1, s2);
    {
        dim3 g(8, 4);
        k_pack_w2t<<<g, 256, 0, s2>>>(W2, w2thi, w2tlo);
    }
    {
        dim3 g(NDEC / 32, 2, 2);
        k_pack_w3t<<<g, 256, 0, s2>>>(W3, w3thi, w3tlo);
    }
    k_uv<<<16, 256, 0, s2>>>(W3, al3, ar3, uv);
    cudaEventRecord(evW, s2);

    // ---- main stream: layer 1 (el1/er1 fused into GEMM epilogue) ----
    k_pack_feat<<<NN, 256>>>(feat, feathi, featlo);
    cudaStreamWaitEvent(0, evW1, 0);
    {
        dim3 grid(2, 64);
        hmma_gemm_el<1><<<grid, 256, HG_SMEM>>>(feathi, featlo, w1thi, w1tlo, h1p,
                                                FINB, FINB, FINB, 256, al1, ar1, el1, er1);
    }
    cudaStreamWaitEvent(0, evCSR, 0);
    k_agg1<<<NN, 256>>>(rowptr, csrsrc, el1, er1, h1p, b1, agg1hi, agg1lo);

    // ---- layer 2 (el2/er2 fused into GEMM epilogue) ----
    cudaStreamWaitEvent(0, evW, 0);
    {
        dim3 grid(1, 64);
        hmma_gemm_el<2><<<grid, 256, HG_SMEM>>>(agg1hi, agg1lo, w2thi, w2tlo, h2p,
                                                256, 256, 256, 128, al2, ar2, el2, er2);
    }
    k_agg2<<<NN, 128>>>(rowptr, csrsrc, el2, er2, h2p, b2, h2, h2hi, h2lo);
    cudaEventRecord(evH2, 0);

    // ---- s1: structure decoder a_hat (overlaps attribute decoder) ----
    cudaStreamWaitEvent(s1, evH2, 0);
    {
        dim3 grid(NN / 128, NN / 128);
        ahat_hmma<<<grid, 256, AHAT_SMEM, s1>>>(h2hi, h2lo, a_hat);
    }
    cudaEventRecord(evAhat, s1);

    // ---- main stream: attribute decoder ----
    k_elr3<<<(NN * 2 * 32 + 255) / 256, 256>>>(h2, uv, el3, er3);
    k_agg3<<<NN, 128>>>(rowptr, csrsrc, el3, er3, h2, agg3hi, agg3lo);
    {
        dim3 grid(NDEC / 64, NN / 128);
        dec_hmma<<<grid, 256, DEC_SMEM>>>(agg3hi, agg3lo, w3thi, w3tlo, b3, x_hat);
    }

    // join
    cudaStreamWaitEvent(0, evAhat, 0);
}